// round 9
// baseline (speedup 1.0000x reference)
#include <cuda_runtime.h>
#include <cuda_fp16.h>
#include <math.h>
#include <stdint.h>

#define D_MODEL 1024
#define D_INNER 2048
#define D_STATE 16
#define DT_RANK 64
#define CONV_K  4
#define BSZ     2
#define SEQ     2048
#define BL      (BSZ*SEQ)             // 4096
#define XDBL_C  (DT_RANK + 2*D_STATE) // 96
#define XPROJ_SPLITK 4
#define CROSS_SCALE 2048.0f
#define CROSS_INV   (1.0f/2048.0f)

// ---------------- scratch (static device globals) ---------------------------
__device__ __align__(16) __half   g_xn_hi[BL * D_MODEL];
__device__ __align__(16) uint8_t  g_xn8h [BL * D_MODEL];
__device__ __align__(16) uint8_t  g_xn8l [BL * D_MODEL];
__device__ __align__(16) float    g_xz   [BL * 2 * D_INNER];
__device__ __align__(16) __half   g_u_hi [BL * D_INNER];
__device__ __align__(16) __half   g_u_lo [BL * D_INNER];
__device__ __align__(16) float    g_xdbl [BL * XDBL_C];
__device__ __align__(16) __half   g_xd_hi[BL * XDBL_C];
__device__ __align__(16) __half   g_xd_lo[BL * XDBL_C];
__device__ __align__(16) float    g_part [XPROJ_SPLITK * BL * XDBL_C];
__device__ __align__(16) float    g_dl   [BL * D_INNER];
__device__ __align__(16) __half   g_y_hi [BL * D_INNER];
__device__ __align__(16) uint8_t  g_y8h  [BL * D_INNER];
__device__ __align__(16) uint8_t  g_y8l  [BL * D_INNER];
__device__ __align__(16) __half   g_wi_hi[2 * D_INNER * D_MODEL];
__device__ __align__(16) uint8_t  g_wi8h [2 * D_INNER * D_MODEL];
__device__ __align__(16) uint8_t  g_wi8l [2 * D_INNER * D_MODEL];
__device__ __align__(16) __half   g_xp_hi[XDBL_C * D_INNER];
__device__ __align__(16) __half   g_xp_lo[XDBL_C * D_INNER];
__device__ __align__(16) __half   g_dw_hi[D_INNER * DT_RANK];
__device__ __align__(16) __half   g_dw_lo[D_INNER * DT_RANK];
__device__ __align__(16) __half   g_wo_hi[D_MODEL * D_INNER];
__device__ __align__(16) uint8_t  g_wo8h [D_MODEL * D_INNER];
__device__ __align__(16) uint8_t  g_wo8l [D_MODEL * D_INNER];

// ---------------- helpers ----------------------------------------------------
__device__ __forceinline__ void cp16(void* dst_smem, const void* src, int sz) {
    uint32_t d = (uint32_t)__cvta_generic_to_shared(dst_smem);
    asm volatile("cp.async.cg.shared.global [%0], [%1], 16, %2;\n"
                 :: "r"(d), "l"(src), "r"(sz));
}
__device__ __forceinline__ void cp_commit() {
    asm volatile("cp.async.commit_group;\n");
}
template<int N_> __device__ __forceinline__ void cp_wait() {
    asm volatile("cp.async.wait_group %0;\n" :: "n"(N_));
}
__device__ __forceinline__ void h_split(float x, __half& h, __half& l) {
    h = __float2half_rn(x);
    l = __float2half_rn(x - __half2float(h));
}
__device__ __forceinline__ void h_split4(float4 v, uint2& hi, uint2& lo) {
    __half h0,l0,h1,l1,h2,l2,h3,l3;
    h_split(v.x,h0,l0); h_split(v.y,h1,l1);
    h_split(v.z,h2,l2); h_split(v.w,h3,l3);
    __half2 ha = __halves2half2(h0,h1), hb = __halves2half2(h2,h3);
    __half2 la = __halves2half2(l0,l1), lb = __halves2half2(l2,l3);
    hi.x = *(uint32_t*)&ha; hi.y = *(uint32_t*)&hb;
    lo.x = *(uint32_t*)&la; lo.y = *(uint32_t*)&lb;
}
// hi fp16 pack + residual floats
__device__ __forceinline__ void h_split4f(float4 v, uint2& hi, float4& lo) {
    __half h0 = __float2half_rn(v.x), h1 = __float2half_rn(v.y);
    __half h2 = __float2half_rn(v.z), h3 = __float2half_rn(v.w);
    lo.x = v.x - __half2float(h0); lo.y = v.y - __half2float(h1);
    lo.z = v.z - __half2float(h2); lo.w = v.w - __half2float(h3);
    __half2 ha = __halves2half2(h0,h1), hb = __halves2half2(h2,h3);
    hi.x = *(uint32_t*)&ha; hi.y = *(uint32_t*)&hb;
}
// pack 4 floats into 4 e4m3 bytes (x -> byte0)
__device__ __forceinline__ uint32_t e4m3x4(float4 v) {
    uint16_t a, b;
    asm("cvt.rn.satfinite.e4m3x2.f32 %0, %1, %2;" : "=h"(a) : "f"(v.y), "f"(v.x));
    asm("cvt.rn.satfinite.e4m3x2.f32 %0, %1, %2;" : "=h"(b) : "f"(v.w), "f"(v.z));
    return (uint32_t)a | ((uint32_t)b << 16);
}
__device__ __forceinline__ void mma16(float* c, const uint32_t* a, const uint32_t* b) {
    asm volatile(
        "mma.sync.aligned.m16n8k16.row.col.f32.f16.f16.f32 "
        "{%0,%1,%2,%3}, {%4,%5,%6,%7}, {%8,%9}, {%0,%1,%2,%3};\n"
        : "+f"(c[0]), "+f"(c[1]), "+f"(c[2]), "+f"(c[3])
        : "r"(a[0]), "r"(a[1]), "r"(a[2]), "r"(a[3]), "r"(b[0]), "r"(b[1]));
}
__device__ __forceinline__ void mma_f8(float* c, const uint32_t* a, const uint32_t* b) {
    asm volatile(
        "mma.sync.aligned.m16n8k32.row.col.f32.e4m3.e4m3.f32 "
        "{%0,%1,%2,%3}, {%4,%5,%6,%7}, {%8,%9}, {%0,%1,%2,%3};\n"
        : "+f"(c[0]), "+f"(c[1]), "+f"(c[2]), "+f"(c[3])
        : "r"(a[0]), "r"(a[1]), "r"(a[2]), "r"(a[3]), "r"(b[0]), "r"(b[1]));
}
#define LDSM_X4(r0, r1, r2, r3, addr)                                       \
    asm volatile("ldmatrix.sync.aligned.m8n8.x4.shared.b16 "                \
                 "{%0,%1,%2,%3}, [%4];"                                     \
                 : "=r"(r0), "=r"(r1), "=r"(r2), "=r"(r3) : "r"(addr))

// ================= hybrid GEMM: fp16 main + fp8 cross =======================
// C = (Ahi+Alo)(Bhi+Blo)^T; main hi*hi in fp16 k16 mma; cross (al*bh + ah*bl)
// via ONE fp8 k64 pass: A' = [al*2^11 | a8], B' = [b8 | bl*2^11], fp32 acc,
// scaled by 2^-11 at epilogue. CTA 128x128, K chunk 32, 3 stages, 1 CTA/SM.
// Stage layout (bytes): Ahi@0(10240) Bhi@10240 A8@20480(10240) B8@30720
#define HY_STAGE 40960
#define HY_SMEM  (3 * HY_STAGE)

template<int EPI>   // 0 none, 2 residual add
__global__ __launch_bounds__(256) void gemm_hy(
    const __half* __restrict__ Ahi, const uint8_t* __restrict__ A8h,
    const uint8_t* __restrict__ A8l, int lda,
    const __half* __restrict__ Bhi, const uint8_t* __restrict__ B8h,
    const uint8_t* __restrict__ B8l, int ldb,
    float* __restrict__ C, int ldc, int M, int N, int K,
    const float* __restrict__ res)
{
    extern __shared__ char smc[];
    int tid = threadIdx.x;
    int m0 = blockIdx.y * 128;
    int n0 = blockIdx.x * 128;
    int KT = K / 32;

    int lane = tid & 31, wid = tid >> 5;
    int p = lane >> 2, q = lane & 3;
    int wm = (wid & 1) * 64;
    int wn = (wid >> 1) * 32;

    float acc[4][4][4];   // main
    float ccc[4][4][4];   // cross (scaled by 2^11)
    #pragma unroll
    for (int i = 0; i < 4; i++)
        #pragma unroll
        for (int j = 0; j < 4; j++)
            #pragma unroll
            for (int r = 0; r < 4; r++) { acc[i][j][r] = 0.f; ccc[i][j][r] = 0.f; }

    auto load_stage = [&](int kt, int slot) {
        char* base = smc + slot * HY_STAGE;
        int k0 = kt * 32;
        #pragma unroll
        for (int c = tid; c < 2048; c += 256) {
            int seg = c >> 9, idx = c & 511;
            int r = idx >> 2, j = idx & 3;
            if (seg == 0) {
                cp16(base + r * 80 + j * 16,
                     Ahi + (size_t)(m0 + r) * lda + k0 + j * 8, 16);
            } else if (seg == 1) {
                cp16(base + 10240 + r * 80 + j * 16,
                     Bhi + (size_t)(n0 + r) * ldb + k0 + j * 8, 16);
            } else if (seg == 2) {
                const uint8_t* src = (j < 2) ? A8l : A8h;
                cp16(base + 20480 + r * 80 + j * 16,
                     src + (size_t)(m0 + r) * lda + k0 + (j & 1) * 16, 16);
            } else {
                const uint8_t* src = (j < 2) ? B8h : B8l;
                cp16(base + 30720 + r * 80 + j * 16,
                     src + (size_t)(n0 + r) * ldb + k0 + (j & 1) * 16, 16);
            }
        }
    };

    load_stage(0, 0); cp_commit();
    load_stage(1, 1); cp_commit();

    uint32_t smbase = (uint32_t)__cvta_generic_to_shared(smc);
    uint32_t a16_off = ((wm + (lane & 15)) * 40 + (lane >> 4) * 8) * 2;
    uint32_t b16_off = ((wn + (lane >> 4) * 8 + (lane & 7)) * 40
                        + ((lane >> 3) & 1) * 8) * 2;
    uint32_t a8_off  = (wm + (lane & 15)) * 80 + (lane >> 4) * 16;
    uint32_t b8_off  = (wn + (lane & 7) + ((lane & 16) ? 8 : 0)) * 80
                       + ((lane & 8) ? 16 : 0);

    for (int kt = 0; kt < KT; kt++) {
        cp_wait<1>();
        __syncthreads();
        if (kt + 2 < KT) load_stage(kt + 2, (kt + 2) % 3);
        cp_commit();

        uint32_t st = smbase + (kt % 3) * HY_STAGE;

        // ---- cross: fp8 k64 ([al|a] x [b|bl]) ----
        #pragma unroll
        for (int kh = 0; kh < 2; kh++) {
            uint32_t bf[4][2];
            uint32_t bb = st + 30720 + b8_off + kh * 32;
            LDSM_X4(bf[0][0], bf[0][1], bf[1][0], bf[1][1], bb);
            LDSM_X4(bf[2][0], bf[2][1], bf[3][0], bf[3][1], bb + 16 * 80);
            #pragma unroll
            for (int mi = 0; mi < 4; mi++) {
                uint32_t af[4];
                LDSM_X4(af[0], af[1], af[2], af[3],
                        st + 20480 + a8_off + mi * 16 * 80 + kh * 32);
                #pragma unroll
                for (int ni = 0; ni < 4; ni++)
                    mma_f8(ccc[mi][ni], af, bf[ni]);
            }
        }

        // ---- main: fp16 k16 x2 ----
        #pragma unroll
        for (int s = 0; s < 2; s++) {
            uint32_t ko = s * 32;
            uint32_t bh[4][2];
            uint32_t bb = st + 10240 + b16_off;
            LDSM_X4(bh[0][0], bh[0][1], bh[1][0], bh[1][1], bb + ko);
            LDSM_X4(bh[2][0], bh[2][1], bh[3][0], bh[3][1], bb + 16 * 80 + ko);
            #pragma unroll
            for (int mi = 0; mi < 4; mi++) {
                uint32_t ah[4];
                LDSM_X4(ah[0], ah[1], ah[2], ah[3],
                        st + a16_off + mi * 16 * 80 + ko);
                #pragma unroll
                for (int ni = 0; ni < 4; ni++)
                    mma16(acc[mi][ni], ah, bh[ni]);
            }
        }
        __syncthreads();
    }

    #pragma unroll
    for (int mi = 0; mi < 4; mi++) {
        int row = m0 + wm + mi * 16 + p;
        #pragma unroll
        for (int ni = 0; ni < 4; ni++) {
            int col = n0 + wn + ni * 8 + q * 2;
            float v[4];
            #pragma unroll
            for (int r = 0; r < 4; r++)
                v[r] = acc[mi][ni][r] + ccc[mi][ni][r] * CROSS_INV;
            if (EPI == 2) {
                v[0] += res[(size_t)row * ldc + col];
                v[1] += res[(size_t)row * ldc + col + 1];
                v[2] += res[(size_t)(row + 8) * ldc + col];
                v[3] += res[(size_t)(row + 8) * ldc + col + 1];
            }
            float* c0 = C + (size_t)row * ldc + col;
            float* c1 = C + (size_t)(row + 8) * ldc + col;
            c0[0] = v[0]; c0[1] = v[1];
            c1[0] = v[2]; c1[1] = v[3];
        }
    }
}

// ================= 3xFP16 GEMM (R7 proven) for small GEMMs ==================
#define RS_H    40
#define TILE_H  (128 * RS_H)
#define STAGE_H (4 * TILE_H)
#define G6_SMEM (2 * STAGE_H * 2)

template<int EPI, int SPLITK>   // EPI: 0 none, 1 softplus(acc+bias[n])
__global__ __launch_bounds__(256, 2) void gemm_f16x3(
    const __half* __restrict__ Ahi, const __half* __restrict__ Alo, int lda,
    const __half* __restrict__ Bhi, const __half* __restrict__ Blo, int ldb,
    float* __restrict__ C, int ldc, int M, int N, int K,
    const float* __restrict__ bias)
{
    extern __shared__ __half sm[];
    int tid = threadIdx.x;
    int m0 = blockIdx.y * 128;
    int n0 = blockIdx.x * 128;

    if (SPLITK > 1) {
        int z = blockIdx.z;
        int Ks = K / SPLITK;
        Ahi += (size_t)z * Ks; Alo += (size_t)z * Ks;
        Bhi += (size_t)z * Ks; Blo += (size_t)z * Ks;
        C += (size_t)z * M * ldc;
        K = Ks;
    }
    int KT = K / 32;

    int lane = tid & 31, wid = tid >> 5;
    int p = lane >> 2, q = lane & 3;
    int wm = (wid & 1) * 64;
    int wn = (wid >> 1) * 32;

    float acc[4][4][4];
    #pragma unroll
    for (int i = 0; i < 4; i++)
        #pragma unroll
        for (int j = 0; j < 4; j++)
            #pragma unroll
            for (int r = 0; r < 4; r++) acc[i][j][r] = 0.f;

    auto load_stage = [&](int kt, int slot) {
        __half* base = sm + slot * STAGE_H;
        int k0 = kt * 32;
        #pragma unroll
        for (int c = tid; c < 2048; c += 256) {
            int tile = c >> 9;
            int r = (c & 511) >> 2;
            int j = c & 3;
            __half* dst = base + tile * TILE_H + r * RS_H + j * 8;
            if (tile < 2) {
                const __half* src = (tile == 0 ? Ahi : Alo)
                                  + (size_t)(m0 + r) * lda + k0 + j * 8;
                cp16(dst, src, 16);
            } else {
                int n = n0 + r;
                int sz = (n < N) ? 16 : 0;
                int rr = sz ? n : 0;
                const __half* src = (tile == 2 ? Bhi : Blo)
                                  + (size_t)rr * ldb + k0 + j * 8;
                cp16(dst, src, sz);
            }
        }
    };

    load_stage(0, 0); cp_commit();
    if (KT > 1) load_stage(1, 1);
    cp_commit();

    uint32_t smbase = (uint32_t)__cvta_generic_to_shared(sm);
    uint32_t a_off = ((wm + (lane & 15)) * RS_H + (lane >> 4) * 8) * 2;
    uint32_t b_off = ((wn + (lane >> 4) * 8 + (lane & 7)) * RS_H
                      + ((lane >> 3) & 1) * 8) * 2;

    for (int kt = 0; kt < KT; kt++) {
        int slot = kt & 1;
        cp_wait<1>();
        __syncthreads();

        uint32_t st = smbase + slot * STAGE_H * 2;
        uint32_t aHi = st + a_off;
        uint32_t aLo = aHi + TILE_H * 2;
        uint32_t bHi = st + 2 * TILE_H * 2 + b_off;
        uint32_t bLo = bHi + TILE_H * 2;

        #pragma unroll
        for (int s = 0; s < 2; s++) {
            uint32_t ko = s * 32;
            uint32_t bh[4][2], bl[4][2];
            LDSM_X4(bh[0][0], bh[0][1], bh[1][0], bh[1][1], bHi + ko);
            LDSM_X4(bh[2][0], bh[2][1], bh[3][0], bh[3][1], bHi + 16 * RS_H * 2 + ko);
            LDSM_X4(bl[0][0], bl[0][1], bl[1][0], bl[1][1], bLo + ko);
            LDSM_X4(bl[2][0], bl[2][1], bl[3][0], bl[3][1], bLo + 16 * RS_H * 2 + ko);
            #pragma unroll
            for (int mi = 0; mi < 4; mi++) {
                uint32_t ah[4], al[4];
                LDSM_X4(ah[0], ah[1], ah[2], ah[3], aHi + mi * 16 * RS_H * 2 + ko);
                LDSM_X4(al[0], al[1], al[2], al[3], aLo + mi * 16 * RS_H * 2 + ko);
                #pragma unroll
                for (int ni = 0; ni < 4; ni++) {
                    mma16(acc[mi][ni], ah, bh[ni]);
                    mma16(acc[mi][ni], al, bh[ni]);
                    mma16(acc[mi][ni], ah, bl[ni]);
                }
            }
        }
        __syncthreads();
        if (kt + 2 < KT) load_stage(kt + 2, slot);
        cp_commit();
    }

    #pragma unroll
    for (int mi = 0; mi < 4; mi++) {
        int row = m0 + wm + mi * 16 + p;
        #pragma unroll
        for (int ni = 0; ni < 4; ni++) {
            int col = n0 + wn + ni * 8 + q * 2;
            if (col < N) {
                float v[4] = { acc[mi][ni][0], acc[mi][ni][1],
                               acc[mi][ni][2], acc[mi][ni][3] };
                if (EPI == 1) {
                    #pragma unroll
                    for (int r = 0; r < 4; r++) {
                        float t = v[r] + bias[col + (r & 1)];
                        float e = __expf(t);
                        v[r] = (t > 15.f) ? t : log1pf(e);
                    }
                }
                float* c0 = C + (size_t)row * ldc + col;
                float* c1 = C + (size_t)(row + 8) * ldc + col;
                c0[0] = v[0]; c0[1] = v[1];
                c1[0] = v[2]; c1[1] = v[3];
            }
        }
    }
}

// ---------------- weight splits ----------------------------------------------
__global__ __launch_bounds__(256) void split_kernel(      // fp16 hi/lo
    const float* __restrict__ src, __half* __restrict__ hi,
    __half* __restrict__ lo, int n)
{
    int i = (blockIdx.x * 256 + threadIdx.x) * 8;
    if (i >= n) return;
    float4 a = *(const float4*)(src + i);
    float4 b = *(const float4*)(src + i + 4);
    uint2 h0, l0, h1, l1;
    h_split4(a, h0, l0);
    h_split4(b, h1, l1);
    *(uint4*)(hi + i) = make_uint4(h0.x, h0.y, h1.x, h1.y);
    *(uint4*)(lo + i) = make_uint4(l0.x, l0.y, l1.x, l1.y);
}
__global__ __launch_bounds__(256) void split_hy_kernel(   // fp16 hi + fp8 h/l
    const float* __restrict__ src, __half* __restrict__ hi,
    uint8_t* __restrict__ h8, uint8_t* __restrict__ l8, int n)
{
    int i = (blockIdx.x * 256 + threadIdx.x) * 8;
    if (i >= n) return;
    float4 a = *(const float4*)(src + i);
    float4 b = *(const float4*)(src + i + 4);
    uint2 ha, hb; float4 la, lb;
    h_split4f(a, ha, la);
    h_split4f(b, hb, lb);
    *(uint4*)(hi + i) = make_uint4(ha.x, ha.y, hb.x, hb.y);
    *(uint2*)(h8 + i) = make_uint2(e4m3x4(a), e4m3x4(b));
    float4 las = make_float4(la.x*CROSS_SCALE, la.y*CROSS_SCALE,
                             la.z*CROSS_SCALE, la.w*CROSS_SCALE);
    float4 lbs = make_float4(lb.x*CROSS_SCALE, lb.y*CROSS_SCALE,
                             lb.z*CROSS_SCALE, lb.w*CROSS_SCALE);
    *(uint2*)(l8 + i) = make_uint2(e4m3x4(las), e4m3x4(lbs));
}

// ---------------- LayerNorm (fp16 hi + fp8 h/l) ------------------------------
__global__ __launch_bounds__(256) void ln_kernel(
    const float* __restrict__ x, const float* __restrict__ g,
    const float* __restrict__ b, __half* __restrict__ ohi,
    uint8_t* __restrict__ o8h, uint8_t* __restrict__ o8l)
{
    int row = blockIdx.x;
    const float4* xr = (const float4*)(x + (size_t)row * D_MODEL);
    float4 v = xr[threadIdx.x];
    float s  = v.x + v.y + v.z + v.w;
    float ss = v.x*v.x + v.y*v.y + v.z*v.z + v.w*v.w;
    #pragma unroll
    for (int o = 16; o; o >>= 1) {
        s  += __shfl_xor_sync(0xffffffffu, s, o);
        ss += __shfl_xor_sync(0xffffffffu, ss, o);
    }
    __shared__ float red[16];
    __shared__ float mu_s, rstd_s;
    int w = threadIdx.x >> 5, lane = threadIdx.x & 31;
    if (lane == 0) { red[w] = s; red[8 + w] = ss; }
    __syncthreads();
    if (threadIdx.x == 0) {
        float S = 0.f, SS = 0.f;
        #pragma unroll
        for (int i = 0; i < 8; i++) { S += red[i]; SS += red[8 + i]; }
        float mu = S * (1.f / D_MODEL);
        float var = SS * (1.f / D_MODEL) - mu * mu;
        mu_s = mu; rstd_s = rsqrtf(var + 1e-5f);
    }
    __syncthreads();
    float mu = mu_s, r = rstd_s;
    float4 gv = ((const float4*)g)[threadIdx.x];
    float4 bv = ((const float4*)b)[threadIdx.x];
    float4 o;
    o.x = (v.x - mu) * r * gv.x + bv.x;
    o.y = (v.y - mu) * r * gv.y + bv.y;
    o.z = (v.z - mu) * r * gv.z + bv.z;
    o.w = (v.w - mu) * r * gv.w + bv.w;
    uint2 h; float4 l;
    h_split4f(o, h, l);
    ((uint2*)(ohi + (size_t)row * D_MODEL))[threadIdx.x] = h;
    ((uint32_t*)(o8h + (size_t)row * D_MODEL))[threadIdx.x] = e4m3x4(o);
    float4 ls = make_float4(l.x*CROSS_SCALE, l.y*CROSS_SCALE,
                            l.z*CROSS_SCALE, l.w*CROSS_SCALE);
    ((uint32_t*)(o8l + (size_t)row * D_MODEL))[threadIdx.x] = e4m3x4(ls);
}

// ---------------- split-K reduce for x_proj (float4) --------------------------
__global__ __launch_bounds__(256) void xproj_reduce(
    const float* __restrict__ part, float* __restrict__ out,
    __half* __restrict__ ohi, __half* __restrict__ olo)
{
    int i = (blockIdx.x * 256 + threadIdx.x) * 4;
    if (i >= BL * XDBL_C) return;
    const int stride = BL * XDBL_C;
    float4 s = *(const float4*)(part + i);
    #pragma unroll
    for (int z = 1; z < XPROJ_SPLITK; z++) {
        float4 p = *(const float4*)(part + z * stride + i);
        s.x += p.x; s.y += p.y; s.z += p.z; s.w += p.w;
    }
    *(float4*)(out + i) = s;
    uint2 h, l;
    h_split4(s, h, l);
    *(uint2*)(ohi + i) = h;
    *(uint2*)(olo + i) = l;
}

// ---------------- causal depthwise conv (K=4) + SiLU -------------------------
__global__ __launch_bounds__(256) void conv_silu_kernel(
    const float* __restrict__ xz, const float* __restrict__ w,
    const float* __restrict__ bias,
    __half* __restrict__ uhi, __half* __restrict__ ulo)
{
    int idx = blockIdx.x * 256 + threadIdx.x;
    if (idx >= BL * D_INNER / 4) return;
    int d4 = (idx * 4) % D_INNER;
    int t  = (idx * 4 / D_INNER) % SEQ;
    int b  = idx * 4 / (D_INNER * SEQ);

    float4 acc = *(const float4*)(bias + d4);
    float4 wr[4];
    #pragma unroll
    for (int c = 0; c < 4; c++) wr[c] = *(const float4*)(w + (d4 + c) * CONV_K);

    #pragma unroll
    for (int k = 0; k < CONV_K; k++) {
        int ts = t - (CONV_K - 1) + k;
        if (ts >= 0) {
            float4 xv = *(const float4*)(xz + (size_t)(b * SEQ + ts) * (2 * D_INNER) + d4);
            acc.x += ((const float*)&wr[0])[k] * xv.x;
            acc.y += ((const float*)&wr[1])[k] * xv.y;
            acc.z += ((const float*)&wr[2])[k] * xv.z;
            acc.w += ((const float*)&wr[3])[k] * xv.w;
        }
    }
    float4 val;
    val.x = acc.x / (1.f + __expf(-acc.x));
    val.y = acc.y / (1.f + __expf(-acc.y));
    val.z = acc.z / (1.f + __expf(-acc.z));
    val.w = acc.w / (1.f + __expf(-acc.w));
    size_t oi = (size_t)(b * SEQ + t) * D_INNER + d4;
    uint2 h, l;
    h_split4(val, h, l);
    *(uint2*)(uhi + oi) = h;
    *(uint2*)(ulo + oi) = l;
}

// ---------------- selective scan (gate fused; y -> fp16 hi + fp8 h/l) --------
#define SC_DC 32
#define SC_TC 64
__global__ __launch_bounds__(SC_DC * D_STATE) void scan_kernel(
    const __half* __restrict__ uhi, const __half* __restrict__ ulo,
    const float* __restrict__ dl,
    const float* __restrict__ xdbl, const float* __restrict__ A_log,
    const float* __restrict__ xz, const float* __restrict__ Dp,
    __half* __restrict__ yhi, uint8_t* __restrict__ y8h,
    uint8_t* __restrict__ y8l)
{
    __shared__ float u_s [SC_TC][SC_DC];
    __shared__ float dl_s[SC_TC][SC_DC];
    __shared__ float B_s [SC_TC][D_STATE];
    __shared__ float C_s [SC_TC][D_STATE];
    __shared__ float y_s [SC_TC][SC_DC];

    int b  = blockIdx.y;
    int d0 = blockIdx.x * SC_DC;
    int tid = threadIdx.x;
    int g = tid >> 4;
    int n = tid & 15;
    int d = d0 + g;

    float a = -expf(A_log[d * D_STATE + n]);
    float s = 0.f;

    for (int t0 = 0; t0 < SEQ; t0 += SC_TC) {
        {
            int i = tid * 4;
            int tt = i >> 5, gg = i & 31;
            size_t gi = (size_t)(b * SEQ + t0 + tt) * D_INNER + d0 + gg;
            uint2 uh = *(const uint2*)(uhi + gi);
            uint2 ul = *(const uint2*)(ulo + gi);
            __half2 h0 = *(__half2*)&uh.x, h1 = *(__half2*)&uh.y;
            __half2 l0 = *(__half2*)&ul.x, l1 = *(__half2*)&ul.y;
            float4 uu;
            uu.x = __low2float(h0)  + __low2float(l0);
            uu.y = __high2float(h0) + __high2float(l0);
            uu.z = __low2float(h1)  + __low2float(l1);
            uu.w = __high2float(h1) + __high2float(l1);
            *(float4*)&u_s[tt][gg] = uu;
            *(float4*)&dl_s[tt][gg] = *(const float4*)(dl + gi);
        }
        {
            int i = tid * 4;
            int tt = i >> 5, pos = i & 31;
            const float* r = xdbl + (size_t)(b * SEQ + t0 + tt) * XDBL_C + DT_RANK;
            float4 v = *(const float4*)(r + pos);
            if (pos < 16) *(float4*)&B_s[tt][pos] = v;
            else          *(float4*)&C_s[tt][pos - 16] = v;
        }
        __syncthreads();
        #pragma unroll 4
        for (int t = 0; t < SC_TC; t++) {
            float dlt = dl_s[t][g];
            float dA  = __expf(dlt * a);
            float dbu = dlt * B_s[t][n] * u_s[t][g];
            s = fmaf(dA, s, dbu);
            float part = s * C_s[t][n];
            part += __shfl_xor_sync(0xffffffffu, part, 8);
            part += __shfl_xor_sync(0xffffffffu, part, 4);
            part += __shfl_xor_sync(0xffffffffu, part, 2);
            part += __shfl_xor_sync(0xffffffffu, part, 1);
            if (n == 0) y_s[t][g] = part;
        }
        __syncthreads();
        {
            int i = tid * 4;
            int tt = i >> 5, gg = i & 31;
            int rowg = b * SEQ + t0 + tt;
            float4 z = *(const float4*)(xz + (size_t)rowg * (2 * D_INNER) + D_INNER + d0 + gg);
            float4 uu = *(const float4*)&u_s[tt][gg];
            float4 yy = *(const float4*)&y_s[tt][gg];
            float4 dp = *(const float4*)(Dp + d0 + gg);
            float4 val;
            val.x = (yy.x + uu.x * dp.x) * (z.x / (1.f + __expf(-z.x)));
            val.y = (yy.y + uu.y * dp.y) * (z.y / (1.f + __expf(-z.y)));
            val.z = (yy.z + uu.z * dp.z) * (z.z / (1.f + __expf(-z.z)));
            val.w = (yy.w + uu.w * dp.w) * (z.w / (1.f + __expf(-z.w)));
            uint2 h; float4 l;
            h_split4f(val, h, l);
            size_t oi = (size_t)rowg * D_INNER + d0 + gg;
            *(uint2*)(yhi + oi) = h;
            *(uint32_t*)(y8h + oi) = e4m3x4(val);
            float4 ls = make_float4(l.x*CROSS_SCALE, l.y*CROSS_SCALE,
                                    l.z*CROSS_SCALE, l.w*CROSS_SCALE);
            *(uint32_t*)(y8l + oi) = e4m3x4(ls);
        }
        __syncthreads();
    }
}

// ---------------- launch ------------------------------------------------------
extern "C" void kernel_launch(void* const* d_in, const int* in_sizes, int n_in,
                              void* d_out, int out_size)
{
    const float* x      = (const float*)d_in[0];
    const float* ln_g   = (const float*)d_in[1];
    const float* ln_b   = (const float*)d_in[2];
    const float* W_in   = (const float*)d_in[3];
    const float* conv_w = (const float*)d_in[4];
    const float* conv_b = (const float*)d_in[5];
    const float* A_log  = (const float*)d_in[6];
    const float* D_prm  = (const float*)d_in[7];
    const float* x_proj = (const float*)d_in[8];
    const float* dt_w   = (const float*)d_in[9];
    const float* dt_b   = (const float*)d_in[10];
    const float* W_out  = (const float*)d_in[11];
    float* out = (float*)d_out;

    __half *xn_hi, *u_hi, *u_lo, *xd_hi, *xd_lo, *y_hi;
    __half *wi_hi, *xp_hi, *xp_lo, *dw_hi, *dw_lo, *wo_hi;
    uint8_t *xn8h, *xn8l, *y8h, *y8l, *wi8h, *wi8l, *wo8h, *wo8l;
    float *xz, *xdbl, *part, *dl;
    cudaGetSymbolAddress((void**)&xn_hi, g_xn_hi);
    cudaGetSymbolAddress((void**)&xn8h,  g_xn8h);
    cudaGetSymbolAddress((void**)&xn8l,  g_xn8l);
    cudaGetSymbolAddress((void**)&xz,    g_xz);
    cudaGetSymbolAddress((void**)&u_hi,  g_u_hi);
    cudaGetSymbolAddress((void**)&u_lo,  g_u_lo);
    cudaGetSymbolAddress((void**)&xdbl,  g_xdbl);
    cudaGetSymbolAddress((void**)&xd_hi, g_xd_hi);
    cudaGetSymbolAddress((void**)&xd_lo, g_xd_lo);
    cudaGetSymbolAddress((void**)&part,  g_part);
    cudaGetSymbolAddress((void**)&dl,    g_dl);
    cudaGetSymbolAddress((void**)&y_hi,  g_y_hi);
    cudaGetSymbolAddress((void**)&y8h,   g_y8h);
    cudaGetSymbolAddress((void**)&y8l,   g_y8l);
    cudaGetSymbolAddress((void**)&wi_hi, g_wi_hi);
    cudaGetSymbolAddress((void**)&wi8h,  g_wi8h);
    cudaGetSymbolAddress((void**)&wi8l,  g_wi8l);
    cudaGetSymbolAddress((void**)&xp_hi, g_xp_hi);
    cudaGetSymbolAddress((void**)&xp_lo, g_xp_lo);
    cudaGetSymbolAddress((void**)&dw_hi, g_dw_hi);
    cudaGetSymbolAddress((void**)&dw_lo, g_dw_lo);
    cudaGetSymbolAddress((void**)&wo_hi, g_wo_hi);
    cudaGetSymbolAddress((void**)&wo8h,  g_wo8h);
    cudaGetSymbolAddress((void**)&wo8l,  g_wo8l);

    cudaFuncSetAttribute(gemm_hy<0>, cudaFuncAttributeMaxDynamicSharedMemorySize, HY_SMEM);
    cudaFuncSetAttribute(gemm_hy<2>, cudaFuncAttributeMaxDynamicSharedMemorySize, HY_SMEM);
    cudaFuncSetAttribute(gemm_f16x3<0,XPROJ_SPLITK>, cudaFuncAttributeMaxDynamicSharedMemorySize, G6_SMEM);
    cudaFuncSetAttribute(gemm_f16x3<1,1>, cudaFuncAttributeMaxDynamicSharedMemorySize, G6_SMEM);

    // 0. weight splits
    split_hy_kernel<<<(2*D_INNER*D_MODEL/8 + 255)/256, 256>>>(W_in, wi_hi, wi8h, wi8l, 2*D_INNER*D_MODEL);
    split_hy_kernel<<<(D_MODEL*D_INNER/8  + 255)/256, 256>>>(W_out, wo_hi, wo8h, wo8l, D_MODEL*D_INNER);
    split_kernel<<<(XDBL_C*D_INNER/8  + 255)/256, 256>>>(x_proj, xp_hi, xp_lo, XDBL_C*D_INNER);
    split_kernel<<<(D_INNER*DT_RANK/8 + 255)/256, 256>>>(dt_w,   dw_hi, dw_lo, D_INNER*DT_RANK);

    // 1. LayerNorm -> xn (fp16 hi + fp8 h/l)
    ln_kernel<<<BL, 256>>>(x, ln_g, ln_b, xn_hi, xn8h, xn8l);

    // 2. xz = xn @ W_in^T   (4096 x 4096 x 1024)  [hybrid fp16+fp8]
    gemm_hy<0><<<dim3(2*D_INNER/128, BL/128), 256, HY_SMEM>>>(
        xn_hi, xn8h, xn8l, D_MODEL, wi_hi, wi8h, wi8l, D_MODEL,
        xz, 2*D_INNER, BL, 2*D_INNER, D_MODEL, nullptr);

    // 3. causal depthwise conv + SiLU -> u hi/lo
    conv_silu_kernel<<<(BL*D_INNER/4 + 255)/256, 256>>>(xz, conv_w, conv_b, u_hi, u_lo);

    // 4. x_dbl = u @ x_proj^T  (4096 x 96 x 2048), split-K=4  [3xfp16]
    gemm_f16x3<0,XPROJ_SPLITK><<<dim3(1, BL/128, XPROJ_SPLITK), 256, G6_SMEM>>>(
        u_hi, u_lo, D_INNER, xp_hi, xp_lo, D_INNER,
        part, XDBL_C, BL, XDBL_C, D_INNER, nullptr);
    xproj_reduce<<<(BL*XDBL_C/4 + 255)/256, 256>>>(part, xdbl, xd_hi, xd_lo);

    // 5. delta = softplus(dt_r @ dt_w^T + dt_b)  (4096 x 2048 x 64)  [3xfp16]
    gemm_f16x3<1,1><<<dim3(D_INNER/128, BL/128), 256, G6_SMEM>>>(
        xd_hi, xd_lo, XDBL_C, dw_hi, dw_lo, DT_RANK,
        dl, D_INNER, BL, D_INNER, DT_RANK, dt_b);

    // 6. selective scan + fused gate -> y (fp16 hi + fp8 h/l)
    scan_kernel<<<dim3(D_INNER/SC_DC, BSZ), SC_DC*D_STATE>>>(
        u_hi, u_lo, dl, xdbl, A_log, xz, D_prm, y_hi, y8h, y8l);

    // 7. out = y @ W_out^T + x  (4096 x 1024 x 2048)  [hybrid fp16+fp8]
    gemm_hy<2><<<dim3(D_MODEL/128, BL/128), 256, HY_SMEM>>>(
        y_hi, y8h, y8l, D_INNER, wo_hi, wo8h, wo8l, D_INNER,
        out, D_MODEL, BL, D_MODEL, D_INNER, x);
}

// round 10
// speedup vs baseline: 1.7016x; 1.7016x over previous
#include <cuda_runtime.h>
#include <cuda_fp16.h>
#include <math.h>
#include <stdint.h>

#define D_MODEL 1024
#define D_INNER 2048
#define D_STATE 16
#define DT_RANK 64
#define CONV_K  4
#define BSZ     2
#define SEQ     2048
#define BL      (BSZ*SEQ)             // 4096
#define XDBL_C  (DT_RANK + 2*D_STATE) // 96
#define XPROJ_SPLITK 4

// ---------------- scratch (static device globals) ---------------------------
__device__ __align__(16) __half g_xn_hi[BL * D_MODEL];
__device__ __align__(16) float  g_xz   [BL * 2 * D_INNER];
__device__ __align__(16) __half g_u_hi [BL * D_INNER];
__device__ __align__(16) __half g_u_lo [BL * D_INNER];
__device__ __align__(16) float  g_xdbl [BL * XDBL_C];
__device__ __align__(16) __half g_xd_hi[BL * XDBL_C];
__device__ __align__(16) __half g_xd_lo[BL * XDBL_C];
__device__ __align__(16) float  g_part [XPROJ_SPLITK * BL * XDBL_C];
__device__ __align__(16) float  g_dl   [BL * D_INNER];
__device__ __align__(16) __half g_y_hi [BL * D_INNER];
__device__ __align__(16) __half g_wi_hi[2 * D_INNER * D_MODEL];
__device__ __align__(16) __half g_xp_hi[XDBL_C * D_INNER];
__device__ __align__(16) __half g_xp_lo[XDBL_C * D_INNER];
__device__ __align__(16) __half g_dw_hi[D_INNER * DT_RANK];
__device__ __align__(16) __half g_dw_lo[D_INNER * DT_RANK];
__device__ __align__(16) __half g_wo_hi[D_MODEL * D_INNER];

// ---------------- helpers ----------------------------------------------------
__device__ __forceinline__ void cp16(void* dst_smem, const void* src, int sz) {
    uint32_t d = (uint32_t)__cvta_generic_to_shared(dst_smem);
    asm volatile("cp.async.cg.shared.global [%0], [%1], 16, %2;\n"
                 :: "r"(d), "l"(src), "r"(sz));
}
__device__ __forceinline__ void cp_commit() {
    asm volatile("cp.async.commit_group;\n");
}
template<int N_> __device__ __forceinline__ void cp_wait() {
    asm volatile("cp.async.wait_group %0;\n" :: "n"(N_));
}
__device__ __forceinline__ void h_split(float x, __half& h, __half& l) {
    h = __float2half_rn(x);
    l = __float2half_rn(x - __half2float(h));
}
__device__ __forceinline__ void h_split4(float4 v, uint2& hi, uint2& lo) {
    __half h0,l0,h1,l1,h2,l2,h3,l3;
    h_split(v.x,h0,l0); h_split(v.y,h1,l1);
    h_split(v.z,h2,l2); h_split(v.w,h3,l3);
    __half2 ha = __halves2half2(h0,h1), hb = __halves2half2(h2,h3);
    __half2 la = __halves2half2(l0,l1), lb = __halves2half2(l2,l3);
    hi.x = *(uint32_t*)&ha; hi.y = *(uint32_t*)&hb;
    lo.x = *(uint32_t*)&la; lo.y = *(uint32_t*)&lb;
}
__device__ __forceinline__ uint2 h_pack4(float4 v) {
    __half2 a = __halves2half2(__float2half_rn(v.x), __float2half_rn(v.y));
    __half2 b = __halves2half2(__float2half_rn(v.z), __float2half_rn(v.w));
    uint2 r; r.x = *(uint32_t*)&a; r.y = *(uint32_t*)&b;
    return r;
}
__device__ __forceinline__ void mma16(float* c, const uint32_t* a, const uint32_t* b) {
    asm volatile(
        "mma.sync.aligned.m16n8k16.row.col.f32.f16.f16.f32 "
        "{%0,%1,%2,%3}, {%4,%5,%6,%7}, {%8,%9}, {%0,%1,%2,%3};\n"
        : "+f"(c[0]), "+f"(c[1]), "+f"(c[2]), "+f"(c[3])
        : "r"(a[0]), "r"(a[1]), "r"(a[2]), "r"(a[3]), "r"(b[0]), "r"(b[1]));
}
#define LDSM_X4(r0, r1, r2, r3, addr)                                       \
    asm volatile("ldmatrix.sync.aligned.m8n8.x4.shared.b16 "                \
                 "{%0,%1,%2,%3}, [%4];"                                     \
                 : "=r"(r0), "=r"(r1), "=r"(r2), "=r"(r3) : "r"(addr))

#define RS_H    40
#define TILE_H  (128 * RS_H)      // 5120 halfs = 10240 B

// ================= single-pass fp16 GEMM (big GEMMs) ========================
// C[M,N] = Ahi[M,K] @ Bhi[N,K]^T ; CTA 128x128, K chunk 32, 3-stage pipeline.
// EPI: 0 none, 2 acc + res[m*ldc+n]
#define S1_STAGE_H (2 * TILE_H)           // 10240 halfs = 20480 B
#define G1_SMEM    (3 * S1_STAGE_H * 2)   // 61440 B

template<int EPI>
__global__ __launch_bounds__(256, 2) void gemm_1p(
    const __half* __restrict__ Ahi, int lda,
    const __half* __restrict__ Bhi, int ldb,
    float* __restrict__ C, int ldc, int M, int N, int K,
    const float* __restrict__ res)
{
    extern __shared__ __half sm[];
    int tid = threadIdx.x;
    int m0 = blockIdx.y * 128;
    int n0 = blockIdx.x * 128;
    int KT = K / 32;

    int lane = tid & 31, wid = tid >> 5;
    int p = lane >> 2, q = lane & 3;
    int wm = (wid & 1) * 64;
    int wn = (wid >> 1) * 32;

    float acc[4][4][4];
    #pragma unroll
    for (int i = 0; i < 4; i++)
        #pragma unroll
        for (int j = 0; j < 4; j++)
            #pragma unroll
            for (int r = 0; r < 4; r++) acc[i][j][r] = 0.f;

    auto load_stage = [&](int kt, int slot) {
        __half* base = sm + slot * S1_STAGE_H;
        int k0 = kt * 32;
        #pragma unroll
        for (int c = tid; c < 1024; c += 256) {
            int tile = c >> 9;            // 0:A 1:B
            int r = (c & 511) >> 2;
            int j = c & 3;
            __half* dst = base + tile * TILE_H + r * RS_H + j * 8;
            const __half* src = (tile == 0)
                ? Ahi + (size_t)(m0 + r) * lda + k0 + j * 8
                : Bhi + (size_t)(n0 + r) * ldb + k0 + j * 8;
            cp16(dst, src, 16);
        }
    };

    load_stage(0, 0); cp_commit();
    load_stage(1, 1); cp_commit();

    uint32_t smbase = (uint32_t)__cvta_generic_to_shared(sm);
    uint32_t a_off = ((wm + (lane & 15)) * RS_H + (lane >> 4) * 8) * 2;
    uint32_t b_off = ((wn + (lane >> 4) * 8 + (lane & 7)) * RS_H
                      + ((lane >> 3) & 1) * 8) * 2;

    for (int kt = 0; kt < KT; kt++) {
        cp_wait<1>();
        __syncthreads();
        if (kt + 2 < KT) load_stage(kt + 2, (kt + 2) % 3);
        cp_commit();

        uint32_t st = smbase + (kt % 3) * S1_STAGE_H * 2;
        uint32_t aHi = st + a_off;
        uint32_t bHi = st + TILE_H * 2 + b_off;

        #pragma unroll
        for (int s = 0; s < 2; s++) {
            uint32_t ko = s * 32;
            uint32_t bh[4][2];
            LDSM_X4(bh[0][0], bh[0][1], bh[1][0], bh[1][1], bHi + ko);
            LDSM_X4(bh[2][0], bh[2][1], bh[3][0], bh[3][1], bHi + 16 * RS_H * 2 + ko);
            #pragma unroll
            for (int mi = 0; mi < 4; mi++) {
                uint32_t ah[4];
                LDSM_X4(ah[0], ah[1], ah[2], ah[3], aHi + mi * 16 * RS_H * 2 + ko);
                #pragma unroll
                for (int ni = 0; ni < 4; ni++)
                    mma16(acc[mi][ni], ah, bh[ni]);
            }
        }
    }

    #pragma unroll
    for (int mi = 0; mi < 4; mi++) {
        int row = m0 + wm + mi * 16 + p;
        #pragma unroll
        for (int ni = 0; ni < 4; ni++) {
            int col = n0 + wn + ni * 8 + q * 2;
            float v[4] = { acc[mi][ni][0], acc[mi][ni][1],
                           acc[mi][ni][2], acc[mi][ni][3] };
            if (EPI == 2) {
                v[0] += res[(size_t)row * ldc + col];
                v[1] += res[(size_t)row * ldc + col + 1];
                v[2] += res[(size_t)(row + 8) * ldc + col];
                v[3] += res[(size_t)(row + 8) * ldc + col + 1];
            }
            float* c0 = C + (size_t)row * ldc + col;
            float* c1 = C + (size_t)(row + 8) * ldc + col;
            c0[0] = v[0]; c0[1] = v[1];
            c1[0] = v[2]; c1[1] = v[3];
        }
    }
}

// ================= 3xFP16 GEMM (R7 proven) for small GEMMs ==================
#define STAGE_H (4 * TILE_H)
#define G6_SMEM (2 * STAGE_H * 2)

template<int EPI, int SPLITK>   // EPI: 0 none, 1 softplus(acc+bias[n])
__global__ __launch_bounds__(256, 2) void gemm_f16x3(
    const __half* __restrict__ Ahi, const __half* __restrict__ Alo, int lda,
    const __half* __restrict__ Bhi, const __half* __restrict__ Blo, int ldb,
    float* __restrict__ C, int ldc, int M, int N, int K,
    const float* __restrict__ bias)
{
    extern __shared__ __half sm[];
    int tid = threadIdx.x;
    int m0 = blockIdx.y * 128;
    int n0 = blockIdx.x * 128;

    if (SPLITK > 1) {
        int z = blockIdx.z;
        int Ks = K / SPLITK;
        Ahi += (size_t)z * Ks; Alo += (size_t)z * Ks;
        Bhi += (size_t)z * Ks; Blo += (size_t)z * Ks;
        C += (size_t)z * M * ldc;
        K = Ks;
    }
    int KT = K / 32;

    int lane = tid & 31, wid = tid >> 5;
    int p = lane >> 2, q = lane & 3;
    int wm = (wid & 1) * 64;
    int wn = (wid >> 1) * 32;

    float acc[4][4][4];
    #pragma unroll
    for (int i = 0; i < 4; i++)
        #pragma unroll
        for (int j = 0; j < 4; j++)
            #pragma unroll
            for (int r = 0; r < 4; r++) acc[i][j][r] = 0.f;

    auto load_stage = [&](int kt, int slot) {
        __half* base = sm + slot * STAGE_H;
        int k0 = kt * 32;
        #pragma unroll
        for (int c = tid; c < 2048; c += 256) {
            int tile = c >> 9;
            int r = (c & 511) >> 2;
            int j = c & 3;
            __half* dst = base + tile * TILE_H + r * RS_H + j * 8;
            if (tile < 2) {
                const __half* src = (tile == 0 ? Ahi : Alo)
                                  + (size_t)(m0 + r) * lda + k0 + j * 8;
                cp16(dst, src, 16);
            } else {
                int n = n0 + r;
                int sz = (n < N) ? 16 : 0;
                int rr = sz ? n : 0;
                const __half* src = (tile == 2 ? Bhi : Blo)
                                  + (size_t)rr * ldb + k0 + j * 8;
                cp16(dst, src, sz);
            }
        }
    };

    load_stage(0, 0); cp_commit();
    if (KT > 1) load_stage(1, 1);
    cp_commit();

    uint32_t smbase = (uint32_t)__cvta_generic_to_shared(sm);
    uint32_t a_off = ((wm + (lane & 15)) * RS_H + (lane >> 4) * 8) * 2;
    uint32_t b_off = ((wn + (lane >> 4) * 8 + (lane & 7)) * RS_H
                      + ((lane >> 3) & 1) * 8) * 2;

    for (int kt = 0; kt < KT; kt++) {
        int slot = kt & 1;
        cp_wait<1>();
        __syncthreads();

        uint32_t st = smbase + slot * STAGE_H * 2;
        uint32_t aHi = st + a_off;
        uint32_t aLo = aHi + TILE_H * 2;
        uint32_t bHi = st + 2 * TILE_H * 2 + b_off;
        uint32_t bLo = bHi + TILE_H * 2;

        #pragma unroll
        for (int s = 0; s < 2; s++) {
            uint32_t ko = s * 32;
            uint32_t bh[4][2], bl[4][2];
            LDSM_X4(bh[0][0], bh[0][1], bh[1][0], bh[1][1], bHi + ko);
            LDSM_X4(bh[2][0], bh[2][1], bh[3][0], bh[3][1], bHi + 16 * RS_H * 2 + ko);
            LDSM_X4(bl[0][0], bl[0][1], bl[1][0], bl[1][1], bLo + ko);
            LDSM_X4(bl[2][0], bl[2][1], bl[3][0], bl[3][1], bLo + 16 * RS_H * 2 + ko);
            #pragma unroll
            for (int mi = 0; mi < 4; mi++) {
                uint32_t ah[4], al[4];
                LDSM_X4(ah[0], ah[1], ah[2], ah[3], aHi + mi * 16 * RS_H * 2 + ko);
                LDSM_X4(al[0], al[1], al[2], al[3], aLo + mi * 16 * RS_H * 2 + ko);
                #pragma unroll
                for (int ni = 0; ni < 4; ni++) {
                    mma16(acc[mi][ni], ah, bh[ni]);
                    mma16(acc[mi][ni], al, bh[ni]);
                    mma16(acc[mi][ni], ah, bl[ni]);
                }
            }
        }
        __syncthreads();
        if (kt + 2 < KT) load_stage(kt + 2, slot);
        cp_commit();
    }

    #pragma unroll
    for (int mi = 0; mi < 4; mi++) {
        int row = m0 + wm + mi * 16 + p;
        #pragma unroll
        for (int ni = 0; ni < 4; ni++) {
            int col = n0 + wn + ni * 8 + q * 2;
            if (col < N) {
                float v[4] = { acc[mi][ni][0], acc[mi][ni][1],
                               acc[mi][ni][2], acc[mi][ni][3] };
                if (EPI == 1) {
                    #pragma unroll
                    for (int r = 0; r < 4; r++) {
                        float t = v[r] + bias[col + (r & 1)];
                        float e = __expf(t);
                        v[r] = (t > 15.f) ? t : log1pf(e);
                    }
                }
                float* c0 = C + (size_t)row * ldc + col;
                float* c1 = C + (size_t)(row + 8) * ldc + col;
                c0[0] = v[0]; c0[1] = v[1];
                c1[0] = v[2]; c1[1] = v[3];
            }
        }
    }
}

// ---------------- weight splits ----------------------------------------------
__global__ __launch_bounds__(256) void split_kernel(     // fp16 hi/lo
    const float* __restrict__ src, __half* __restrict__ hi,
    __half* __restrict__ lo, int n)
{
    int i = (blockIdx.x * 256 + threadIdx.x) * 8;
    if (i >= n) return;
    float4 a = *(const float4*)(src + i);
    float4 b = *(const float4*)(src + i + 4);
    uint2 h0, l0, h1, l1;
    h_split4(a, h0, l0);
    h_split4(b, h1, l1);
    *(uint4*)(hi + i) = make_uint4(h0.x, h0.y, h1.x, h1.y);
    *(uint4*)(lo + i) = make_uint4(l0.x, l0.y, l1.x, l1.y);
}
__global__ __launch_bounds__(256) void split1_kernel(    // fp16 hi only
    const float* __restrict__ src, __half* __restrict__ hi, int n)
{
    int i = (blockIdx.x * 256 + threadIdx.x) * 8;
    if (i >= n) return;
    float4 a = *(const float4*)(src + i);
    float4 b = *(const float4*)(src + i + 4);
    uint2 h0 = h_pack4(a), h1 = h_pack4(b);
    *(uint4*)(hi + i) = make_uint4(h0.x, h0.y, h1.x, h1.y);
}

// ---------------- LayerNorm (hi only) -----------------------------------------
__global__ __launch_bounds__(256) void ln_kernel(
    const float* __restrict__ x, const float* __restrict__ g,
    const float* __restrict__ b, __half* __restrict__ ohi)
{
    int row = blockIdx.x;
    const float4* xr = (const float4*)(x + (size_t)row * D_MODEL);
    float4 v = xr[threadIdx.x];
    float s  = v.x + v.y + v.z + v.w;
    float ss = v.x*v.x + v.y*v.y + v.z*v.z + v.w*v.w;
    #pragma unroll
    for (int o = 16; o; o >>= 1) {
        s  += __shfl_xor_sync(0xffffffffu, s, o);
        ss += __shfl_xor_sync(0xffffffffu, ss, o);
    }
    __shared__ float red[16];
    __shared__ float mu_s, rstd_s;
    int w = threadIdx.x >> 5, lane = threadIdx.x & 31;
    if (lane == 0) { red[w] = s; red[8 + w] = ss; }
    __syncthreads();
    if (threadIdx.x == 0) {
        float S = 0.f, SS = 0.f;
        #pragma unroll
        for (int i = 0; i < 8; i++) { S += red[i]; SS += red[8 + i]; }
        float mu = S * (1.f / D_MODEL);
        float var = SS * (1.f / D_MODEL) - mu * mu;
        mu_s = mu; rstd_s = rsqrtf(var + 1e-5f);
    }
    __syncthreads();
    float mu = mu_s, r = rstd_s;
    float4 gv = ((const float4*)g)[threadIdx.x];
    float4 bv = ((const float4*)b)[threadIdx.x];
    float4 o;
    o.x = (v.x - mu) * r * gv.x + bv.x;
    o.y = (v.y - mu) * r * gv.y + bv.y;
    o.z = (v.z - mu) * r * gv.z + bv.z;
    o.w = (v.w - mu) * r * gv.w + bv.w;
    ((uint2*)(ohi + (size_t)row * D_MODEL))[threadIdx.x] = h_pack4(o);
}

// ---------------- split-K reduce for x_proj (float4) --------------------------
__global__ __launch_bounds__(256) void xproj_reduce(
    const float* __restrict__ part, float* __restrict__ out,
    __half* __restrict__ ohi, __half* __restrict__ olo)
{
    int i = (blockIdx.x * 256 + threadIdx.x) * 4;
    if (i >= BL * XDBL_C) return;
    const int stride = BL * XDBL_C;
    float4 s = *(const float4*)(part + i);
    #pragma unroll
    for (int z = 1; z < XPROJ_SPLITK; z++) {
        float4 p = *(const float4*)(part + z * stride + i);
        s.x += p.x; s.y += p.y; s.z += p.z; s.w += p.w;
    }
    *(float4*)(out + i) = s;
    uint2 h, l;
    h_split4(s, h, l);
    *(uint2*)(ohi + i) = h;
    *(uint2*)(olo + i) = l;
}

// ---------------- causal depthwise conv (K=4) + SiLU -------------------------
__global__ __launch_bounds__(256) void conv_silu_kernel(
    const float* __restrict__ xz, const float* __restrict__ w,
    const float* __restrict__ bias,
    __half* __restrict__ uhi, __half* __restrict__ ulo)
{
    int idx = blockIdx.x * 256 + threadIdx.x;
    if (idx >= BL * D_INNER / 4) return;
    int d4 = (idx * 4) % D_INNER;
    int t  = (idx * 4 / D_INNER) % SEQ;
    int b  = idx * 4 / (D_INNER * SEQ);

    float4 acc = *(const float4*)(bias + d4);
    float4 wr[4];
    #pragma unroll
    for (int c = 0; c < 4; c++) wr[c] = *(const float4*)(w + (d4 + c) * CONV_K);

    #pragma unroll
    for (int k = 0; k < CONV_K; k++) {
        int ts = t - (CONV_K - 1) + k;
        if (ts >= 0) {
            float4 xv = *(const float4*)(xz + (size_t)(b * SEQ + ts) * (2 * D_INNER) + d4);
            acc.x += ((const float*)&wr[0])[k] * xv.x;
            acc.y += ((const float*)&wr[1])[k] * xv.y;
            acc.z += ((const float*)&wr[2])[k] * xv.z;
            acc.w += ((const float*)&wr[3])[k] * xv.w;
        }
    }
    float4 val;
    val.x = acc.x / (1.f + __expf(-acc.x));
    val.y = acc.y / (1.f + __expf(-acc.y));
    val.z = acc.z / (1.f + __expf(-acc.z));
    val.w = acc.w / (1.f + __expf(-acc.w));
    size_t oi = (size_t)(b * SEQ + t) * D_INNER + d4;
    uint2 h, l;
    h_split4(val, h, l);
    *(uint2*)(uhi + oi) = h;
    *(uint2*)(ulo + oi) = l;
}

// ---------------- selective scan (gate fused; y hi only) ----------------------
#define SC_DC 32
#define SC_TC 64
__global__ __launch_bounds__(SC_DC * D_STATE) void scan_kernel(
    const __half* __restrict__ uhi, const __half* __restrict__ ulo,
    const float* __restrict__ dl,
    const float* __restrict__ xdbl, const float* __restrict__ A_log,
    const float* __restrict__ xz, const float* __restrict__ Dp,
    __half* __restrict__ yhi)
{
    __shared__ float u_s [SC_TC][SC_DC];
    __shared__ float dl_s[SC_TC][SC_DC];
    __shared__ float B_s [SC_TC][D_STATE];
    __shared__ float C_s [SC_TC][D_STATE];
    __shared__ float y_s [SC_TC][SC_DC];

    int b  = blockIdx.y;
    int d0 = blockIdx.x * SC_DC;
    int tid = threadIdx.x;
    int g = tid >> 4;
    int n = tid & 15;
    int d = d0 + g;

    float a = -expf(A_log[d * D_STATE + n]);
    float s = 0.f;

    for (int t0 = 0; t0 < SEQ; t0 += SC_TC) {
        {
            int i = tid * 4;
            int tt = i >> 5, gg = i & 31;
            size_t gi = (size_t)(b * SEQ + t0 + tt) * D_INNER + d0 + gg;
            uint2 uh = *(const uint2*)(uhi + gi);
            uint2 ul = *(const uint2*)(ulo + gi);
            __half2 h0 = *(__half2*)&uh.x, h1 = *(__half2*)&uh.y;
            __half2 l0 = *(__half2*)&ul.x, l1 = *(__half2*)&ul.y;
            float4 uu;
            uu.x = __low2float(h0)  + __low2float(l0);
            uu.y = __high2float(h0) + __high2float(l0);
            uu.z = __low2float(h1)  + __low2float(l1);
            uu.w = __high2float(h1) + __high2float(l1);
            *(float4*)&u_s[tt][gg] = uu;
            *(float4*)&dl_s[tt][gg] = *(const float4*)(dl + gi);
        }
        {
            int i = tid * 4;
            int tt = i >> 5, pos = i & 31;
            const float* r = xdbl + (size_t)(b * SEQ + t0 + tt) * XDBL_C + DT_RANK;
            float4 v = *(const float4*)(r + pos);
            if (pos < 16) *(float4*)&B_s[tt][pos] = v;
            else          *(float4*)&C_s[tt][pos - 16] = v;
        }
        __syncthreads();
        #pragma unroll 4
        for (int t = 0; t < SC_TC; t++) {
            float dlt = dl_s[t][g];
            float dA  = __expf(dlt * a);
            float dbu = dlt * B_s[t][n] * u_s[t][g];
            s = fmaf(dA, s, dbu);
            float part = s * C_s[t][n];
            part += __shfl_xor_sync(0xffffffffu, part, 8);
            part += __shfl_xor_sync(0xffffffffu, part, 4);
            part += __shfl_xor_sync(0xffffffffu, part, 2);
            part += __shfl_xor_sync(0xffffffffu, part, 1);
            if (n == 0) y_s[t][g] = part;
        }
        __syncthreads();
        {
            int i = tid * 4;
            int tt = i >> 5, gg = i & 31;
            int rowg = b * SEQ + t0 + tt;
            float4 z = *(const float4*)(xz + (size_t)rowg * (2 * D_INNER) + D_INNER + d0 + gg);
            float4 uu = *(const float4*)&u_s[tt][gg];
            float4 yy = *(const float4*)&y_s[tt][gg];
            float4 dp = *(const float4*)(Dp + d0 + gg);
            float4 val;
            val.x = (yy.x + uu.x * dp.x) * (z.x / (1.f + __expf(-z.x)));
            val.y = (yy.y + uu.y * dp.y) * (z.y / (1.f + __expf(-z.y)));
            val.z = (yy.z + uu.z * dp.z) * (z.z / (1.f + __expf(-z.z)));
            val.w = (yy.w + uu.w * dp.w) * (z.w / (1.f + __expf(-z.w)));
            size_t oi = (size_t)rowg * D_INNER + d0 + gg;
            *(uint2*)(yhi + oi) = h_pack4(val);
        }
        __syncthreads();
    }
}

// ---------------- launch ------------------------------------------------------
extern "C" void kernel_launch(void* const* d_in, const int* in_sizes, int n_in,
                              void* d_out, int out_size)
{
    const float* x      = (const float*)d_in[0];
    const float* ln_g   = (const float*)d_in[1];
    const float* ln_b   = (const float*)d_in[2];
    const float* W_in   = (const float*)d_in[3];
    const float* conv_w = (const float*)d_in[4];
    const float* conv_b = (const float*)d_in[5];
    const float* A_log  = (const float*)d_in[6];
    const float* D_prm  = (const float*)d_in[7];
    const float* x_proj = (const float*)d_in[8];
    const float* dt_w   = (const float*)d_in[9];
    const float* dt_b   = (const float*)d_in[10];
    const float* W_out  = (const float*)d_in[11];
    float* out = (float*)d_out;

    __half *xn_hi, *u_hi, *u_lo, *xd_hi, *xd_lo, *y_hi;
    __half *wi_hi, *xp_hi, *xp_lo, *dw_hi, *dw_lo, *wo_hi;
    float *xz, *xdbl, *part, *dl;
    cudaGetSymbolAddress((void**)&xn_hi, g_xn_hi);
    cudaGetSymbolAddress((void**)&xz,    g_xz);
    cudaGetSymbolAddress((void**)&u_hi,  g_u_hi);
    cudaGetSymbolAddress((void**)&u_lo,  g_u_lo);
    cudaGetSymbolAddress((void**)&xdbl,  g_xdbl);
    cudaGetSymbolAddress((void**)&xd_hi, g_xd_hi);
    cudaGetSymbolAddress((void**)&xd_lo, g_xd_lo);
    cudaGetSymbolAddress((void**)&part,  g_part);
    cudaGetSymbolAddress((void**)&dl,    g_dl);
    cudaGetSymbolAddress((void**)&y_hi,  g_y_hi);
    cudaGetSymbolAddress((void**)&wi_hi, g_wi_hi);
    cudaGetSymbolAddress((void**)&xp_hi, g_xp_hi);
    cudaGetSymbolAddress((void**)&xp_lo, g_xp_lo);
    cudaGetSymbolAddress((void**)&dw_hi, g_dw_hi);
    cudaGetSymbolAddress((void**)&dw_lo, g_dw_lo);
    cudaGetSymbolAddress((void**)&wo_hi, g_wo_hi);

    cudaFuncSetAttribute(gemm_1p<0>, cudaFuncAttributeMaxDynamicSharedMemorySize, G1_SMEM);
    cudaFuncSetAttribute(gemm_1p<2>, cudaFuncAttributeMaxDynamicSharedMemorySize, G1_SMEM);
    cudaFuncSetAttribute(gemm_f16x3<0,XPROJ_SPLITK>, cudaFuncAttributeMaxDynamicSharedMemorySize, G6_SMEM);
    cudaFuncSetAttribute(gemm_f16x3<1,1>, cudaFuncAttributeMaxDynamicSharedMemorySize, G6_SMEM);

    // 0. weight splits
    split1_kernel<<<(2*D_INNER*D_MODEL/8 + 255)/256, 256>>>(W_in,  wi_hi, 2*D_INNER*D_MODEL);
    split1_kernel<<<(D_MODEL*D_INNER/8  + 255)/256, 256>>>(W_out, wo_hi, D_MODEL*D_INNER);
    split_kernel<<<(XDBL_C*D_INNER/8  + 255)/256, 256>>>(x_proj, xp_hi, xp_lo, XDBL_C*D_INNER);
    split_kernel<<<(D_INNER*DT_RANK/8 + 255)/256, 256>>>(dt_w,   dw_hi, dw_lo, D_INNER*DT_RANK);

    // 1. LayerNorm -> xn hi
    ln_kernel<<<BL, 256>>>(x, ln_g, ln_b, xn_hi);

    // 2. xz = xn @ W_in^T   (4096 x 4096 x 1024)  [1-pass fp16]
    gemm_1p<0><<<dim3(2*D_INNER/128, BL/128), 256, G1_SMEM>>>(
        xn_hi, D_MODEL, wi_hi, D_MODEL,
        xz, 2*D_INNER, BL, 2*D_INNER, D_MODEL, nullptr);

    // 3. causal depthwise conv + SiLU -> u hi/lo
    conv_silu_kernel<<<(BL*D_INNER/4 + 255)/256, 256>>>(xz, conv_w, conv_b, u_hi, u_lo);

    // 4. x_dbl = u @ x_proj^T  (4096 x 96 x 2048), split-K=4  [3xfp16]
    gemm_f16x3<0,XPROJ_SPLITK><<<dim3(1, BL/128, XPROJ_SPLITK), 256, G6_SMEM>>>(
        u_hi, u_lo, D_INNER, xp_hi, xp_lo, D_INNER,
        part, XDBL_C, BL, XDBL_C, D_INNER, nullptr);
    xproj_reduce<<<(BL*XDBL_C/4 + 255)/256, 256>>>(part, xdbl, xd_hi, xd_lo);

    // 5. delta = softplus(dt_r @ dt_w^T + dt_b)  (4096 x 2048 x 64)  [3xfp16]
    gemm_f16x3<1,1><<<dim3(D_INNER/128, BL/128), 256, G6_SMEM>>>(
        xd_hi, xd_lo, XDBL_C, dw_hi, dw_lo, DT_RANK,
        dl, D_INNER, BL, D_INNER, DT_RANK, dt_b);

    // 6. selective scan + fused gate -> y hi
    scan_kernel<<<dim3(D_INNER/SC_DC, BSZ), SC_DC*D_STATE>>>(
        u_hi, u_lo, dl, xdbl, A_log, xz, D_prm, y_hi);

    // 7. out = y @ W_out^T + x  (4096 x 1024 x 2048)  [1-pass fp16]
    gemm_1p<2><<<dim3(D_MODEL/128, BL/128), 256, G1_SMEM>>>(
        y_hi, D_INNER, wo_hi, D_INNER,
        out, D_MODEL, BL, D_MODEL, D_INNER, x);
}

// round 11
// speedup vs baseline: 1.7935x; 1.0540x over previous
#include <cuda_runtime.h>
#include <cuda_fp16.h>
#include <math.h>
#include <stdint.h>

#define D_MODEL 1024
#define D_INNER 2048
#define D_STATE 16
#define DT_RANK 64
#define CONV_K  4
#define BSZ     2
#define SEQ     2048
#define BL      (BSZ*SEQ)             // 4096
#define XDBL_C  (DT_RANK + 2*D_STATE) // 96
#define XPROJ_SPLITK 4

// ---------------- scratch (static device globals) ---------------------------
__device__ __align__(16) __half g_xn_hi[BL * D_MODEL];
__device__ __align__(16) float  g_xz   [BL * 2 * D_INNER];
__device__ __align__(16) __half g_u_hi [BL * D_INNER];
__device__ __align__(16) __half g_u_lo [BL * D_INNER];
__device__ __align__(16) float  g_xdbl [BL * XDBL_C];
__device__ __align__(16) __half g_xd_hi[BL * XDBL_C];
__device__ __align__(16) float  g_part [XPROJ_SPLITK * BL * XDBL_C];
__device__ __align__(16) __half g_dl   [BL * D_INNER];
__device__ __align__(16) __half g_y_hi [BL * D_INNER];
__device__ __align__(16) __half g_wi_hi[2 * D_INNER * D_MODEL];
__device__ __align__(16) __half g_xp_hi[XDBL_C * D_INNER];
__device__ __align__(16) __half g_dw_hi[D_INNER * DT_RANK];
__device__ __align__(16) __half g_wo_hi[D_MODEL * D_INNER];

// ---------------- helpers ----------------------------------------------------
__device__ __forceinline__ void cp16(void* dst_smem, const void* src, int sz) {
    uint32_t d = (uint32_t)__cvta_generic_to_shared(dst_smem);
    asm volatile("cp.async.cg.shared.global [%0], [%1], 16, %2;\n"
                 :: "r"(d), "l"(src), "r"(sz));
}
__device__ __forceinline__ void cp_commit() {
    asm volatile("cp.async.commit_group;\n");
}
template<int N_> __device__ __forceinline__ void cp_wait() {
    asm volatile("cp.async.wait_group %0;\n" :: "n"(N_));
}
__device__ __forceinline__ void h_split(float x, __half& h, __half& l) {
    h = __float2half_rn(x);
    l = __float2half_rn(x - __half2float(h));
}
__device__ __forceinline__ void h_split4(float4 v, uint2& hi, uint2& lo) {
    __half h0,l0,h1,l1,h2,l2,h3,l3;
    h_split(v.x,h0,l0); h_split(v.y,h1,l1);
    h_split(v.z,h2,l2); h_split(v.w,h3,l3);
    __half2 ha = __halves2half2(h0,h1), hb = __halves2half2(h2,h3);
    __half2 la = __halves2half2(l0,l1), lb = __halves2half2(l2,l3);
    hi.x = *(uint32_t*)&ha; hi.y = *(uint32_t*)&hb;
    lo.x = *(uint32_t*)&la; lo.y = *(uint32_t*)&lb;
}
__device__ __forceinline__ uint2 h_pack4(float4 v) {
    __half2 a = __halves2half2(__float2half_rn(v.x), __float2half_rn(v.y));
    __half2 b = __halves2half2(__float2half_rn(v.z), __float2half_rn(v.w));
    uint2 r; r.x = *(uint32_t*)&a; r.y = *(uint32_t*)&b;
    return r;
}
__device__ __forceinline__ void mma16(float* c, const uint32_t* a, const uint32_t* b) {
    asm volatile(
        "mma.sync.aligned.m16n8k16.row.col.f32.f16.f16.f32 "
        "{%0,%1,%2,%3}, {%4,%5,%6,%7}, {%8,%9}, {%0,%1,%2,%3};\n"
        : "+f"(c[0]), "+f"(c[1]), "+f"(c[2]), "+f"(c[3])
        : "r"(a[0]), "r"(a[1]), "r"(a[2]), "r"(a[3]), "r"(b[0]), "r"(b[1]));
}
#define LDSM_X4(r0, r1, r2, r3, addr)                                       \
    asm volatile("ldmatrix.sync.aligned.m8n8.x4.shared.b16 "                \
                 "{%0,%1,%2,%3}, [%4];"                                     \
                 : "=r"(r0), "=r"(r1), "=r"(r2), "=r"(r3) : "r"(addr))

#define RS_H    40
#define TILE_H  (128 * RS_H)      // 5120 halfs = 10240 B

// ================= single-pass fp16 GEMM (all GEMMs) ========================
// C[M,N] = Ahi[M,K] @ Bhi[N,K]^T ; CTA 128x128, K chunk 32, 3-stage pipeline.
// EPI: 0 none (fp32 out), 1 softplus(acc+bias[n]) -> HALF out, 2 acc+res (fp32)
#define S1_STAGE_H (2 * TILE_H)           // 10240 halfs = 20480 B
#define G1_SMEM    (3 * S1_STAGE_H * 2)   // 61440 B

template<int EPI, int SPLITK>
__global__ __launch_bounds__(256, 2) void gemm_1p(
    const __half* __restrict__ Ahi, int lda,
    const __half* __restrict__ Bhi, int ldb,
    void* __restrict__ Cout, int ldc, int M, int N, int K,
    const float* __restrict__ bias, const float* __restrict__ res)
{
    extern __shared__ __half sm[];
    int tid = threadIdx.x;
    int m0 = blockIdx.y * 128;
    int n0 = blockIdx.x * 128;

    float* Cf = (float*)Cout;
    __half* Ch = (__half*)Cout;

    if (SPLITK > 1) {
        int z = blockIdx.z;
        int Ks = K / SPLITK;
        Ahi += (size_t)z * Ks;
        Bhi += (size_t)z * Ks;
        Cf += (size_t)z * M * ldc;
        K = Ks;
    }
    int KT = K / 32;

    int lane = tid & 31, wid = tid >> 5;
    int p = lane >> 2, q = lane & 3;
    int wm = (wid & 1) * 64;
    int wn = (wid >> 1) * 32;

    float acc[4][4][4];
    #pragma unroll
    for (int i = 0; i < 4; i++)
        #pragma unroll
        for (int j = 0; j < 4; j++)
            #pragma unroll
            for (int r = 0; r < 4; r++) acc[i][j][r] = 0.f;

    auto load_stage = [&](int kt, int slot) {
        __half* base = sm + slot * S1_STAGE_H;
        int k0 = kt * 32;
        #pragma unroll
        for (int c = tid; c < 1024; c += 256) {
            int tile = c >> 9;            // 0:A 1:B
            int r = (c & 511) >> 2;
            int j = c & 3;
            __half* dst = base + tile * TILE_H + r * RS_H + j * 8;
            if (tile == 0) {
                cp16(dst, Ahi + (size_t)(m0 + r) * lda + k0 + j * 8, 16);
            } else {
                int n = n0 + r;
                int sz = (n < N) ? 16 : 0;
                int rr = sz ? n : 0;
                cp16(dst, Bhi + (size_t)rr * ldb + k0 + j * 8, sz);
            }
        }
    };

    load_stage(0, 0); cp_commit();
    if (KT > 1) load_stage(1, 1);
    cp_commit();

    uint32_t smbase = (uint32_t)__cvta_generic_to_shared(sm);
    uint32_t a_off = ((wm + (lane & 15)) * RS_H + (lane >> 4) * 8) * 2;
    uint32_t b_off = ((wn + (lane >> 4) * 8 + (lane & 7)) * RS_H
                      + ((lane >> 3) & 1) * 8) * 2;

    for (int kt = 0; kt < KT; kt++) {
        cp_wait<1>();
        __syncthreads();
        if (kt + 2 < KT) load_stage(kt + 2, (kt + 2) % 3);
        cp_commit();

        uint32_t st = smbase + (kt % 3) * S1_STAGE_H * 2;
        uint32_t aHi = st + a_off;
        uint32_t bHi = st + TILE_H * 2 + b_off;

        #pragma unroll
        for (int s = 0; s < 2; s++) {
            uint32_t ko = s * 32;
            uint32_t bh[4][2];
            LDSM_X4(bh[0][0], bh[0][1], bh[1][0], bh[1][1], bHi + ko);
            LDSM_X4(bh[2][0], bh[2][1], bh[3][0], bh[3][1], bHi + 16 * RS_H * 2 + ko);
            #pragma unroll
            for (int mi = 0; mi < 4; mi++) {
                uint32_t ah[4];
                LDSM_X4(ah[0], ah[1], ah[2], ah[3], aHi + mi * 16 * RS_H * 2 + ko);
                #pragma unroll
                for (int ni = 0; ni < 4; ni++)
                    mma16(acc[mi][ni], ah, bh[ni]);
            }
        }
        __syncthreads();
    }

    #pragma unroll
    for (int mi = 0; mi < 4; mi++) {
        int row = m0 + wm + mi * 16 + p;
        #pragma unroll
        for (int ni = 0; ni < 4; ni++) {
            int col = n0 + wn + ni * 8 + q * 2;
            if (col < N) {
                float v[4] = { acc[mi][ni][0], acc[mi][ni][1],
                               acc[mi][ni][2], acc[mi][ni][3] };
                if (EPI == 1) {
                    #pragma unroll
                    for (int r = 0; r < 4; r++) {
                        float t = v[r] + bias[col + (r & 1)];
                        float e = __expf(t);
                        v[r] = (t > 15.f) ? t : log1pf(e);
                    }
                    __half2 v01 = __halves2half2(__float2half_rn(v[0]),
                                                 __float2half_rn(v[1]));
                    __half2 v23 = __halves2half2(__float2half_rn(v[2]),
                                                 __float2half_rn(v[3]));
                    *(__half2*)(Ch + (size_t)row * ldc + col) = v01;
                    *(__half2*)(Ch + (size_t)(row + 8) * ldc + col) = v23;
                } else {
                    if (EPI == 2) {
                        v[0] += res[(size_t)row * ldc + col];
                        v[1] += res[(size_t)row * ldc + col + 1];
                        v[2] += res[(size_t)(row + 8) * ldc + col];
                        v[3] += res[(size_t)(row + 8) * ldc + col + 1];
                    }
                    float* c0 = Cf + (size_t)row * ldc + col;
                    float* c1 = Cf + (size_t)(row + 8) * ldc + col;
                    c0[0] = v[0]; c0[1] = v[1];
                    c1[0] = v[2]; c1[1] = v[3];
                }
            }
        }
    }
}

// ---------------- weight split (fp16 hi only) ---------------------------------
__global__ __launch_bounds__(256) void split1_kernel(
    const float* __restrict__ src, __half* __restrict__ hi, int n)
{
    int i = (blockIdx.x * 256 + threadIdx.x) * 8;
    if (i >= n) return;
    float4 a = *(const float4*)(src + i);
    float4 b = *(const float4*)(src + i + 4);
    uint2 h0 = h_pack4(a), h1 = h_pack4(b);
    *(uint4*)(hi + i) = make_uint4(h0.x, h0.y, h1.x, h1.y);
}

// ---------------- LayerNorm (hi only) -----------------------------------------
__global__ __launch_bounds__(256) void ln_kernel(
    const float* __restrict__ x, const float* __restrict__ g,
    const float* __restrict__ b, __half* __restrict__ ohi)
{
    int row = blockIdx.x;
    const float4* xr = (const float4*)(x + (size_t)row * D_MODEL);
    float4 v = xr[threadIdx.x];
    float s  = v.x + v.y + v.z + v.w;
    float ss = v.x*v.x + v.y*v.y + v.z*v.z + v.w*v.w;
    #pragma unroll
    for (int o = 16; o; o >>= 1) {
        s  += __shfl_xor_sync(0xffffffffu, s, o);
        ss += __shfl_xor_sync(0xffffffffu, ss, o);
    }
    __shared__ float red[16];
    __shared__ float mu_s, rstd_s;
    int w = threadIdx.x >> 5, lane = threadIdx.x & 31;
    if (lane == 0) { red[w] = s; red[8 + w] = ss; }
    __syncthreads();
    if (threadIdx.x == 0) {
        float S = 0.f, SS = 0.f;
        #pragma unroll
        for (int i = 0; i < 8; i++) { S += red[i]; SS += red[8 + i]; }
        float mu = S * (1.f / D_MODEL);
        float var = SS * (1.f / D_MODEL) - mu * mu;
        mu_s = mu; rstd_s = rsqrtf(var + 1e-5f);
    }
    __syncthreads();
    float mu = mu_s, r = rstd_s;
    float4 gv = ((const float4*)g)[threadIdx.x];
    float4 bv = ((const float4*)b)[threadIdx.x];
    float4 o;
    o.x = (v.x - mu) * r * gv.x + bv.x;
    o.y = (v.y - mu) * r * gv.y + bv.y;
    o.z = (v.z - mu) * r * gv.z + bv.z;
    o.w = (v.w - mu) * r * gv.w + bv.w;
    ((uint2*)(ohi + (size_t)row * D_MODEL))[threadIdx.x] = h_pack4(o);
}

// ---------------- split-K reduce for x_proj (fp32 + hi) -----------------------
__global__ __launch_bounds__(256) void xproj_reduce(
    const float* __restrict__ part, float* __restrict__ out,
    __half* __restrict__ ohi)
{
    int i = (blockIdx.x * 256 + threadIdx.x) * 4;
    if (i >= BL * XDBL_C) return;
    const int stride = BL * XDBL_C;
    float4 s = *(const float4*)(part + i);
    #pragma unroll
    for (int z = 1; z < XPROJ_SPLITK; z++) {
        float4 p = *(const float4*)(part + z * stride + i);
        s.x += p.x; s.y += p.y; s.z += p.z; s.w += p.w;
    }
    *(float4*)(out + i) = s;
    *(uint2*)(ohi + i) = h_pack4(s);
}

// ---------------- causal depthwise conv (K=4) + SiLU -------------------------
__global__ __launch_bounds__(256) void conv_silu_kernel(
    const float* __restrict__ xz, const float* __restrict__ w,
    const float* __restrict__ bias,
    __half* __restrict__ uhi, __half* __restrict__ ulo)
{
    int idx = blockIdx.x * 256 + threadIdx.x;
    if (idx >= BL * D_INNER / 4) return;
    int d4 = (idx * 4) % D_INNER;
    int t  = (idx * 4 / D_INNER) % SEQ;
    int b  = idx * 4 / (D_INNER * SEQ);

    float4 acc = *(const float4*)(bias + d4);
    float4 wr[4];
    #pragma unroll
    for (int c = 0; c < 4; c++) wr[c] = *(const float4*)(w + (d4 + c) * CONV_K);

    #pragma unroll
    for (int k = 0; k < CONV_K; k++) {
        int ts = t - (CONV_K - 1) + k;
        if (ts >= 0) {
            float4 xv = *(const float4*)(xz + (size_t)(b * SEQ + ts) * (2 * D_INNER) + d4);
            acc.x += ((const float*)&wr[0])[k] * xv.x;
            acc.y += ((const float*)&wr[1])[k] * xv.y;
            acc.z += ((const float*)&wr[2])[k] * xv.z;
            acc.w += ((const float*)&wr[3])[k] * xv.w;
        }
    }
    float4 val;
    val.x = acc.x / (1.f + __expf(-acc.x));
    val.y = acc.y / (1.f + __expf(-acc.y));
    val.z = acc.z / (1.f + __expf(-acc.z));
    val.w = acc.w / (1.f + __expf(-acc.w));
    size_t oi = (size_t)(b * SEQ + t) * D_INNER + d4;
    uint2 h, l;
    h_split4(val, h, l);
    *(uint2*)(uhi + oi) = h;
    *(uint2*)(ulo + oi) = l;
}

// ---------------- selective scan (gate fused; dl fp16; y hi only) -------------
#define SC_DC 32
#define SC_TC 64
__global__ __launch_bounds__(SC_DC * D_STATE) void scan_kernel(
    const __half* __restrict__ uhi, const __half* __restrict__ ulo,
    const __half* __restrict__ dl,
    const float* __restrict__ xdbl, const float* __restrict__ A_log,
    const float* __restrict__ xz, const float* __restrict__ Dp,
    __half* __restrict__ yhi)
{
    __shared__ float u_s [SC_TC][SC_DC];
    __shared__ float dl_s[SC_TC][SC_DC];
    __shared__ float B_s [SC_TC][D_STATE];
    __shared__ float C_s [SC_TC][D_STATE];
    __shared__ float y_s [SC_TC][SC_DC];

    int b  = blockIdx.y;
    int d0 = blockIdx.x * SC_DC;
    int tid = threadIdx.x;
    int g = tid >> 4;
    int n = tid & 15;
    int d = d0 + g;

    float a = -expf(A_log[d * D_STATE + n]);
    float s = 0.f;

    for (int t0 = 0; t0 < SEQ; t0 += SC_TC) {
        {
            int i = tid * 4;
            int tt = i >> 5, gg = i & 31;
            size_t gi = (size_t)(b * SEQ + t0 + tt) * D_INNER + d0 + gg;
            uint2 uh = *(const uint2*)(uhi + gi);
            uint2 ul = *(const uint2*)(ulo + gi);
            __half2 h0 = *(__half2*)&uh.x, h1 = *(__half2*)&uh.y;
            __half2 l0 = *(__half2*)&ul.x, l1 = *(__half2*)&ul.y;
            float4 uu;
            uu.x = __low2float(h0)  + __low2float(l0);
            uu.y = __high2float(h0) + __high2float(l0);
            uu.z = __low2float(h1)  + __low2float(l1);
            uu.w = __high2float(h1) + __high2float(l1);
            *(float4*)&u_s[tt][gg] = uu;
            uint2 dh = *(const uint2*)(dl + gi);
            __half2 d0h = *(__half2*)&dh.x, d1h = *(__half2*)&dh.y;
            float4 dd;
            dd.x = __low2float(d0h);  dd.y = __high2float(d0h);
            dd.z = __low2float(d1h);  dd.w = __high2float(d1h);
            *(float4*)&dl_s[tt][gg] = dd;
        }
        {
            int i = tid * 4;
            int tt = i >> 5, pos = i & 31;
            const float* r = xdbl + (size_t)(b * SEQ + t0 + tt) * XDBL_C + DT_RANK;
            float4 v = *(const float4*)(r + pos);
            if (pos < 16) *(float4*)&B_s[tt][pos] = v;
            else          *(float4*)&C_s[tt][pos - 16] = v;
        }
        __syncthreads();
        #pragma unroll 4
        for (int t = 0; t < SC_TC; t++) {
            float dlt = dl_s[t][g];
            float dA  = __expf(dlt * a);
            float dbu = dlt * B_s[t][n] * u_s[t][g];
            s = fmaf(dA, s, dbu);
            float part = s * C_s[t][n];
            part += __shfl_xor_sync(0xffffffffu, part, 8);
            part += __shfl_xor_sync(0xffffffffu, part, 4);
            part += __shfl_xor_sync(0xffffffffu, part, 2);
            part += __shfl_xor_sync(0xffffffffu, part, 1);
            if (n == 0) y_s[t][g] = part;
        }
        __syncthreads();
        {
            int i = tid * 4;
            int tt = i >> 5, gg = i & 31;
            int rowg = b * SEQ + t0 + tt;
            float4 z = *(const float4*)(xz + (size_t)rowg * (2 * D_INNER) + D_INNER + d0 + gg);
            float4 uu = *(const float4*)&u_s[tt][gg];
            float4 yy = *(const float4*)&y_s[tt][gg];
            float4 dp = *(const float4*)(Dp + d0 + gg);
            float4 val;
            val.x = (yy.x + uu.x * dp.x) * (z.x / (1.f + __expf(-z.x)));
            val.y = (yy.y + uu.y * dp.y) * (z.y / (1.f + __expf(-z.y)));
            val.z = (yy.z + uu.z * dp.z) * (z.z / (1.f + __expf(-z.z)));
            val.w = (yy.w + uu.w * dp.w) * (z.w / (1.f + __expf(-z.w)));
            size_t oi = (size_t)rowg * D_INNER + d0 + gg;
            *(uint2*)(yhi + oi) = h_pack4(val);
        }
        __syncthreads();
    }
}

// ---------------- launch ------------------------------------------------------
extern "C" void kernel_launch(void* const* d_in, const int* in_sizes, int n_in,
                              void* d_out, int out_size)
{
    const float* x      = (const float*)d_in[0];
    const float* ln_g   = (const float*)d_in[1];
    const float* ln_b   = (const float*)d_in[2];
    const float* W_in   = (const float*)d_in[3];
    const float* conv_w = (const float*)d_in[4];
    const float* conv_b = (const float*)d_in[5];
    const float* A_log  = (const float*)d_in[6];
    const float* D_prm  = (const float*)d_in[7];
    const float* x_proj = (const float*)d_in[8];
    const float* dt_w   = (const float*)d_in[9];
    const float* dt_b   = (const float*)d_in[10];
    const float* W_out  = (const float*)d_in[11];
    float* out = (float*)d_out;

    __half *xn_hi, *u_hi, *u_lo, *xd_hi, *dl, *y_hi;
    __half *wi_hi, *xp_hi, *dw_hi, *wo_hi;
    float *xz, *xdbl, *part;
    cudaGetSymbolAddress((void**)&xn_hi, g_xn_hi);
    cudaGetSymbolAddress((void**)&xz,    g_xz);
    cudaGetSymbolAddress((void**)&u_hi,  g_u_hi);
    cudaGetSymbolAddress((void**)&u_lo,  g_u_lo);
    cudaGetSymbolAddress((void**)&xdbl,  g_xdbl);
    cudaGetSymbolAddress((void**)&xd_hi, g_xd_hi);
    cudaGetSymbolAddress((void**)&part,  g_part);
    cudaGetSymbolAddress((void**)&dl,    g_dl);
    cudaGetSymbolAddress((void**)&y_hi,  g_y_hi);
    cudaGetSymbolAddress((void**)&wi_hi, g_wi_hi);
    cudaGetSymbolAddress((void**)&xp_hi, g_xp_hi);
    cudaGetSymbolAddress((void**)&dw_hi, g_dw_hi);
    cudaGetSymbolAddress((void**)&wo_hi, g_wo_hi);

    cudaFuncSetAttribute(gemm_1p<0,1>, cudaFuncAttributeMaxDynamicSharedMemorySize, G1_SMEM);
    cudaFuncSetAttribute(gemm_1p<0,XPROJ_SPLITK>, cudaFuncAttributeMaxDynamicSharedMemorySize, G1_SMEM);
    cudaFuncSetAttribute(gemm_1p<1,1>, cudaFuncAttributeMaxDynamicSharedMemorySize, G1_SMEM);
    cudaFuncSetAttribute(gemm_1p<2,1>, cudaFuncAttributeMaxDynamicSharedMemorySize, G1_SMEM);

    // 0. weight splits (hi only)
    split1_kernel<<<(2*D_INNER*D_MODEL/8 + 255)/256, 256>>>(W_in,   wi_hi, 2*D_INNER*D_MODEL);
    split1_kernel<<<(D_MODEL*D_INNER/8  + 255)/256, 256>>>(W_out,  wo_hi, D_MODEL*D_INNER);
    split1_kernel<<<(XDBL_C*D_INNER/8   + 255)/256, 256>>>(x_proj, xp_hi, XDBL_C*D_INNER);
    split1_kernel<<<(D_INNER*DT_RANK/8  + 255)/256, 256>>>(dt_w,   dw_hi, D_INNER*DT_RANK);

    // 1. LayerNorm -> xn hi
    ln_kernel<<<BL, 256>>>(x, ln_g, ln_b, xn_hi);

    // 2. xz = xn @ W_in^T   (4096 x 4096 x 1024)
    gemm_1p<0,1><<<dim3(2*D_INNER/128, BL/128), 256, G1_SMEM>>>(
        xn_hi, D_MODEL, wi_hi, D_MODEL,
        xz, 2*D_INNER, BL, 2*D_INNER, D_MODEL, nullptr, nullptr);

    // 3. causal depthwise conv + SiLU -> u hi/lo
    conv_silu_kernel<<<(BL*D_INNER/4 + 255)/256, 256>>>(xz, conv_w, conv_b, u_hi, u_lo);

    // 4. x_dbl = u @ x_proj^T  (4096 x 96 x 2048), split-K=4
    gemm_1p<0,XPROJ_SPLITK><<<dim3(1, BL/128, XPROJ_SPLITK), 256, G1_SMEM>>>(
        u_hi, D_INNER, xp_hi, D_INNER,
        part, XDBL_C, BL, XDBL_C, D_INNER, nullptr, nullptr);
    xproj_reduce<<<(BL*XDBL_C/4 + 255)/256, 256>>>(part, xdbl, xd_hi);

    // 5. delta = softplus(dt_r @ dt_w^T + dt_b) -> HALF  (4096 x 2048 x 64)
    gemm_1p<1,1><<<dim3(D_INNER/128, BL/128), 256, G1_SMEM>>>(
        xd_hi, XDBL_C, dw_hi, DT_RANK,
        dl, D_INNER, BL, D_INNER, DT_RANK, dt_b, nullptr);

    // 6. selective scan + fused gate -> y hi
    scan_kernel<<<dim3(D_INNER/SC_DC, BSZ), SC_DC*D_STATE>>>(
        u_hi, u_lo, dl, xdbl, A_log, xz, D_prm, y_hi);

    // 7. out = y @ W_out^T + x  (4096 x 1024 x 2048)
    gemm_1p<2,1><<<dim3(D_MODEL/128, BL/128), 256, G1_SMEM>>>(
        y_hi, D_INNER, wo_hi, D_INNER,
        out, D_MODEL, BL, D_MODEL, D_INNER, nullptr, x);
}

// round 12
// speedup vs baseline: 1.8529x; 1.0332x over previous
#include <cuda_runtime.h>
#include <cuda_fp16.h>
#include <math.h>
#include <stdint.h>

#define D_MODEL 1024
#define D_INNER 2048
#define D_STATE 16
#define DT_RANK 64
#define CONV_K  4
#define BSZ     2
#define SEQ     2048
#define BL      (BSZ*SEQ)             // 4096
#define XDBL_C  (DT_RANK + 2*D_STATE) // 96
#define XPROJ_SPLITK 4

// ---------------- scratch (static device globals) ---------------------------
__device__ __align__(16) __half g_xn_hi[BL * D_MODEL];
__device__ __align__(16) __half g_xz_h [BL * 2 * D_INNER];
__device__ __align__(16) __half g_u_hi [BL * D_INNER];
__device__ __align__(16) float  g_xdbl [BL * XDBL_C];
__device__ __align__(16) __half g_xd_hi[BL * XDBL_C];
__device__ __align__(16) float  g_part [XPROJ_SPLITK * BL * XDBL_C];
__device__ __align__(16) __half g_dl   [BL * D_INNER];
__device__ __align__(16) __half g_y_hi [BL * D_INNER];
__device__ __align__(16) __half g_wi_hi[2 * D_INNER * D_MODEL];
__device__ __align__(16) __half g_xp_hi[XDBL_C * D_INNER];
__device__ __align__(16) __half g_dw_hi[D_INNER * DT_RANK];
__device__ __align__(16) __half g_wo_hi[D_MODEL * D_INNER];

// ---------------- helpers ----------------------------------------------------
__device__ __forceinline__ void cp16(void* dst_smem, const void* src, int sz) {
    uint32_t d = (uint32_t)__cvta_generic_to_shared(dst_smem);
    asm volatile("cp.async.cg.shared.global [%0], [%1], 16, %2;\n"
                 :: "r"(d), "l"(src), "r"(sz));
}
__device__ __forceinline__ void cp_commit() {
    asm volatile("cp.async.commit_group;\n");
}
template<int N_> __device__ __forceinline__ void cp_wait() {
    asm volatile("cp.async.wait_group %0;\n" :: "n"(N_));
}
__device__ __forceinline__ uint2 h_pack4(float4 v) {
    __half2 a = __halves2half2(__float2half_rn(v.x), __float2half_rn(v.y));
    __half2 b = __halves2half2(__float2half_rn(v.z), __float2half_rn(v.w));
    uint2 r; r.x = *(uint32_t*)&a; r.y = *(uint32_t*)&b;
    return r;
}
__device__ __forceinline__ float4 h_unpack4(uint2 h) {
    __half2 a = *(__half2*)&h.x, b = *(__half2*)&h.y;
    return make_float4(__low2float(a), __high2float(a),
                       __low2float(b), __high2float(b));
}
__device__ __forceinline__ void mma16(float* c, const uint32_t* a, const uint32_t* b) {
    asm volatile(
        "mma.sync.aligned.m16n8k16.row.col.f32.f16.f16.f32 "
        "{%0,%1,%2,%3}, {%4,%5,%6,%7}, {%8,%9}, {%0,%1,%2,%3};\n"
        : "+f"(c[0]), "+f"(c[1]), "+f"(c[2]), "+f"(c[3])
        : "r"(a[0]), "r"(a[1]), "r"(a[2]), "r"(a[3]), "r"(b[0]), "r"(b[1]));
}
#define LDSM_X4(r0, r1, r2, r3, addr)                                       \
    asm volatile("ldmatrix.sync.aligned.m8n8.x4.shared.b16 "                \
                 "{%0,%1,%2,%3}, [%4];"                                     \
                 : "=r"(r0), "=r"(r1), "=r"(r2), "=r"(r3) : "r"(addr))

#define RS_H    40
#define TILE_H  (128 * RS_H)      // 5120 halfs = 10240 B

// ================= single-pass fp16 GEMM ====================================
// C[M,N] = Ahi[M,K] @ Bhi[N,K]^T ; CTA 128x128, K chunk 32, 3-stage pipeline.
// EPI: 0 fp32 out | 1 softplus(acc+bias[n]) -> half | 2 fp32 + res | 3 half out
#define S1_STAGE_H (2 * TILE_H)
#define G1_SMEM    (3 * S1_STAGE_H * 2)   // 61440 B

template<int EPI, int SPLITK>
__global__ __launch_bounds__(256, 2) void gemm_1p(
    const __half* __restrict__ Ahi, int lda,
    const __half* __restrict__ Bhi, int ldb,
    void* __restrict__ Cout, int ldc, int M, int N, int K,
    const float* __restrict__ bias, const float* __restrict__ res)
{
    extern __shared__ __half sm[];
    int tid = threadIdx.x;
    int m0 = blockIdx.y * 128;
    int n0 = blockIdx.x * 128;

    float* Cf = (float*)Cout;
    __half* Ch = (__half*)Cout;

    if (SPLITK > 1) {
        int z = blockIdx.z;
        int Ks = K / SPLITK;
        Ahi += (size_t)z * Ks;
        Bhi += (size_t)z * Ks;
        Cf += (size_t)z * M * ldc;
        K = Ks;
    }
    int KT = K / 32;

    int lane = tid & 31, wid = tid >> 5;
    int p = lane >> 2, q = lane & 3;
    int wm = (wid & 1) * 64;
    int wn = (wid >> 1) * 32;

    float acc[4][4][4];
    #pragma unroll
    for (int i = 0; i < 4; i++)
        #pragma unroll
        for (int j = 0; j < 4; j++)
            #pragma unroll
            for (int r = 0; r < 4; r++) acc[i][j][r] = 0.f;

    auto load_stage = [&](int kt, int slot) {
        __half* base = sm + slot * S1_STAGE_H;
        int k0 = kt * 32;
        #pragma unroll
        for (int c = tid; c < 1024; c += 256) {
            int tile = c >> 9;            // 0:A 1:B
            int r = (c & 511) >> 2;
            int j = c & 3;
            __half* dst = base + tile * TILE_H + r * RS_H + j * 8;
            if (tile == 0) {
                cp16(dst, Ahi + (size_t)(m0 + r) * lda + k0 + j * 8, 16);
            } else {
                int n = n0 + r;
                int sz = (n < N) ? 16 : 0;
                int rr = sz ? n : 0;
                cp16(dst, Bhi + (size_t)rr * ldb + k0 + j * 8, sz);
            }
        }
    };

    load_stage(0, 0); cp_commit();
    if (KT > 1) load_stage(1, 1);
    cp_commit();

    uint32_t smbase = (uint32_t)__cvta_generic_to_shared(sm);
    uint32_t a_off = ((wm + (lane & 15)) * RS_H + (lane >> 4) * 8) * 2;
    uint32_t b_off = ((wn + (lane >> 4) * 8 + (lane & 7)) * RS_H
                      + ((lane >> 3) & 1) * 8) * 2;

    for (int kt = 0; kt < KT; kt++) {
        cp_wait<1>();
        __syncthreads();
        if (kt + 2 < KT) load_stage(kt + 2, (kt + 2) % 3);
        cp_commit();

        uint32_t st = smbase + (kt % 3) * S1_STAGE_H * 2;
        uint32_t aHi = st + a_off;
        uint32_t bHi = st + TILE_H * 2 + b_off;

        #pragma unroll
        for (int s = 0; s < 2; s++) {
            uint32_t ko = s * 32;
            uint32_t bh[4][2];
            LDSM_X4(bh[0][0], bh[0][1], bh[1][0], bh[1][1], bHi + ko);
            LDSM_X4(bh[2][0], bh[2][1], bh[3][0], bh[3][1], bHi + 16 * RS_H * 2 + ko);
            #pragma unroll
            for (int mi = 0; mi < 4; mi++) {
                uint32_t ah[4];
                LDSM_X4(ah[0], ah[1], ah[2], ah[3], aHi + mi * 16 * RS_H * 2 + ko);
                #pragma unroll
                for (int ni = 0; ni < 4; ni++)
                    mma16(acc[mi][ni], ah, bh[ni]);
            }
        }
        __syncthreads();
    }

    #pragma unroll
    for (int mi = 0; mi < 4; mi++) {
        int row = m0 + wm + mi * 16 + p;
        #pragma unroll
        for (int ni = 0; ni < 4; ni++) {
            int col = n0 + wn + ni * 8 + q * 2;
            if (col < N) {
                float v[4] = { acc[mi][ni][0], acc[mi][ni][1],
                               acc[mi][ni][2], acc[mi][ni][3] };
                if (EPI == 1) {
                    #pragma unroll
                    for (int r = 0; r < 4; r++) {
                        float t = v[r] + bias[col + (r & 1)];
                        float e = __expf(t);
                        v[r] = (t > 15.f) ? t : log1pf(e);
                    }
                }
                if (EPI == 1 || EPI == 3) {
                    __half2 v01 = __halves2half2(__float2half_rn(v[0]),
                                                 __float2half_rn(v[1]));
                    __half2 v23 = __halves2half2(__float2half_rn(v[2]),
                                                 __float2half_rn(v[3]));
                    *(__half2*)(Ch + (size_t)row * ldc + col) = v01;
                    *(__half2*)(Ch + (size_t)(row + 8) * ldc + col) = v23;
                } else {
                    if (EPI == 2) {
                        v[0] += res[(size_t)row * ldc + col];
                        v[1] += res[(size_t)row * ldc + col + 1];
                        v[2] += res[(size_t)(row + 8) * ldc + col];
                        v[3] += res[(size_t)(row + 8) * ldc + col + 1];
                    }
                    float* c0 = Cf + (size_t)row * ldc + col;
                    float* c1 = Cf + (size_t)(row + 8) * ldc + col;
                    c0[0] = v[0]; c0[1] = v[1];
                    c1[0] = v[2]; c1[1] = v[3];
                }
            }
        }
    }
}

// ---------------- fused weight splits (all 4 in one launch) -------------------
#define N_WI  (2 * D_INNER * D_MODEL)   // 4194304
#define N_WO  (D_MODEL * D_INNER)       // 2097152
#define N_XP  (XDBL_C * D_INNER)        // 196608
#define N_DW  (D_INNER * DT_RANK)       // 131072
#define N_SPLIT_TOT (N_WI + N_WO + N_XP + N_DW)

__global__ __launch_bounds__(256) void split_all_kernel(
    const float* __restrict__ wi, const float* __restrict__ wo,
    const float* __restrict__ xp, const float* __restrict__ dw,
    __half* __restrict__ wi_h, __half* __restrict__ wo_h,
    __half* __restrict__ xp_h, __half* __restrict__ dw_h)
{
    int i = (blockIdx.x * 256 + threadIdx.x) * 8;
    if (i >= N_SPLIT_TOT) return;
    const float* src; __half* dst; int off;
    if (i < N_WI)                    { src = wi; dst = wi_h; off = i; }
    else if (i < N_WI + N_WO)        { src = wo; dst = wo_h; off = i - N_WI; }
    else if (i < N_WI + N_WO + N_XP) { src = xp; dst = xp_h; off = i - N_WI - N_WO; }
    else                             { src = dw; dst = dw_h; off = i - N_WI - N_WO - N_XP; }
    float4 a = *(const float4*)(src + off);
    float4 b = *(const float4*)(src + off + 4);
    uint2 h0 = h_pack4(a), h1 = h_pack4(b);
    *(uint4*)(dst + off) = make_uint4(h0.x, h0.y, h1.x, h1.y);
}

// ---------------- LayerNorm (hi only) -----------------------------------------
__global__ __launch_bounds__(256) void ln_kernel(
    const float* __restrict__ x, const float* __restrict__ g,
    const float* __restrict__ b, __half* __restrict__ ohi)
{
    int row = blockIdx.x;
    const float4* xr = (const float4*)(x + (size_t)row * D_MODEL);
    float4 v = xr[threadIdx.x];
    float s  = v.x + v.y + v.z + v.w;
    float ss = v.x*v.x + v.y*v.y + v.z*v.z + v.w*v.w;
    #pragma unroll
    for (int o = 16; o; o >>= 1) {
        s  += __shfl_xor_sync(0xffffffffu, s, o);
        ss += __shfl_xor_sync(0xffffffffu, ss, o);
    }
    __shared__ float red[16];
    __shared__ float mu_s, rstd_s;
    int w = threadIdx.x >> 5, lane = threadIdx.x & 31;
    if (lane == 0) { red[w] = s; red[8 + w] = ss; }
    __syncthreads();
    if (threadIdx.x == 0) {
        float S = 0.f, SS = 0.f;
        #pragma unroll
        for (int i = 0; i < 8; i++) { S += red[i]; SS += red[8 + i]; }
        float mu = S * (1.f / D_MODEL);
        float var = SS * (1.f / D_MODEL) - mu * mu;
        mu_s = mu; rstd_s = rsqrtf(var + 1e-5f);
    }
    __syncthreads();
    float mu = mu_s, r = rstd_s;
    float4 gv = ((const float4*)g)[threadIdx.x];
    float4 bv = ((const float4*)b)[threadIdx.x];
    float4 o;
    o.x = (v.x - mu) * r * gv.x + bv.x;
    o.y = (v.y - mu) * r * gv.y + bv.y;
    o.z = (v.z - mu) * r * gv.z + bv.z;
    o.w = (v.w - mu) * r * gv.w + bv.w;
    ((uint2*)(ohi + (size_t)row * D_MODEL))[threadIdx.x] = h_pack4(o);
}

// ---------------- split-K reduce for x_proj (fp32 + hi) -----------------------
__global__ __launch_bounds__(256) void xproj_reduce(
    const float* __restrict__ part, float* __restrict__ out,
    __half* __restrict__ ohi)
{
    int i = (blockIdx.x * 256 + threadIdx.x) * 4;
    if (i >= BL * XDBL_C) return;
    const int stride = BL * XDBL_C;
    float4 s = *(const float4*)(part + i);
    #pragma unroll
    for (int z = 1; z < XPROJ_SPLITK; z++) {
        float4 p = *(const float4*)(part + z * stride + i);
        s.x += p.x; s.y += p.y; s.z += p.z; s.w += p.w;
    }
    *(float4*)(out + i) = s;
    *(uint2*)(ohi + i) = h_pack4(s);
}

// ---------------- causal depthwise conv (K=4) + SiLU (fp16 in/out) ------------
__global__ __launch_bounds__(256) void conv_silu_kernel(
    const __half* __restrict__ xz, const float* __restrict__ w,
    const float* __restrict__ bias, __half* __restrict__ uhi)
{
    int idx = blockIdx.x * 256 + threadIdx.x;
    if (idx >= BL * D_INNER / 4) return;
    int d4 = (idx * 4) % D_INNER;
    int t  = (idx * 4 / D_INNER) % SEQ;
    int b  = idx * 4 / (D_INNER * SEQ);

    float4 acc = *(const float4*)(bias + d4);
    float4 wr[4];
    #pragma unroll
    for (int c = 0; c < 4; c++) wr[c] = *(const float4*)(w + (d4 + c) * CONV_K);

    #pragma unroll
    for (int k = 0; k < CONV_K; k++) {
        int ts = t - (CONV_K - 1) + k;
        if (ts >= 0) {
            uint2 xh = *(const uint2*)(xz + (size_t)(b * SEQ + ts) * (2 * D_INNER) + d4);
            float4 xv = h_unpack4(xh);
            acc.x += ((const float*)&wr[0])[k] * xv.x;
            acc.y += ((const float*)&wr[1])[k] * xv.y;
            acc.z += ((const float*)&wr[2])[k] * xv.z;
            acc.w += ((const float*)&wr[3])[k] * xv.w;
        }
    }
    float4 val;
    val.x = acc.x / (1.f + __expf(-acc.x));
    val.y = acc.y / (1.f + __expf(-acc.y));
    val.z = acc.z / (1.f + __expf(-acc.z));
    val.w = acc.w / (1.f + __expf(-acc.w));
    size_t oi = (size_t)(b * SEQ + t) * D_INNER + d4;
    *(uint2*)(uhi + oi) = h_pack4(val);
}

// ---------------- selective scan (gate fused; all-fp16 streams) ---------------
#define SC_DC 16
#define SC_TC 64
__global__ __launch_bounds__(SC_DC * D_STATE) void scan_kernel(
    const __half* __restrict__ uhi, const __half* __restrict__ dl,
    const float* __restrict__ xdbl, const float* __restrict__ A_log,
    const __half* __restrict__ xz, const float* __restrict__ Dp,
    __half* __restrict__ yhi)
{
    __shared__ float u_s [SC_TC][SC_DC];
    __shared__ float dl_s[SC_TC][SC_DC];
    __shared__ float B_s [SC_TC][D_STATE];
    __shared__ float C_s [SC_TC][D_STATE];
    __shared__ float y_s [SC_TC][SC_DC];

    int b  = blockIdx.y;
    int d0 = blockIdx.x * SC_DC;
    int tid = threadIdx.x;               // 256 threads
    int g = tid >> 4;                    // channel 0..15
    int n = tid & 15;                    // state 0..15
    int d = d0 + g;

    float a = -expf(A_log[d * D_STATE + n]);
    float s = 0.f;

    for (int t0 = 0; t0 < SEQ; t0 += SC_TC) {
        // stage u, dl: 64 x 16 halfs = 1024 elems = 256 thr * 4
        {
            int i = tid * 4;
            int tt = i >> 4, gg = i & 15;
            size_t gi = (size_t)(b * SEQ + t0 + tt) * D_INNER + d0 + gg;
            *(float4*)&u_s [tt][gg] = h_unpack4(*(const uint2*)(uhi + gi));
            *(float4*)&dl_s[tt][gg] = h_unpack4(*(const uint2*)(dl + gi));
        }
        // stage B,C: 64 rows x 32 floats = 2048 = 256 thr * 8 (two float4)
        for (int i = tid * 4; i < SC_TC * 32; i += 1024) {
            int tt = i >> 5, pos = i & 31;
            const float* r = xdbl + (size_t)(b * SEQ + t0 + tt) * XDBL_C + DT_RANK;
            float4 v = *(const float4*)(r + pos);
            if (pos < 16) *(float4*)&B_s[tt][pos] = v;
            else          *(float4*)&C_s[tt][pos - 16] = v;
        }
        __syncthreads();
        #pragma unroll 4
        for (int t = 0; t < SC_TC; t++) {
            float dlt = dl_s[t][g];
            float dA  = __expf(dlt * a);
            float dbu = dlt * B_s[t][n] * u_s[t][g];
            s = fmaf(dA, s, dbu);
            float part = s * C_s[t][n];
            part += __shfl_xor_sync(0xffffffffu, part, 8);
            part += __shfl_xor_sync(0xffffffffu, part, 4);
            part += __shfl_xor_sync(0xffffffffu, part, 2);
            part += __shfl_xor_sync(0xffffffffu, part, 1);
            if (n == 0) y_s[t][g] = part;
        }
        __syncthreads();
        // fused gate: y = (scan_y + u*D) * silu(z)
        {
            int i = tid * 4;
            int tt = i >> 4, gg = i & 15;
            int rowg = b * SEQ + t0 + tt;
            uint2 zh = *(const uint2*)(xz + (size_t)rowg * (2 * D_INNER) + D_INNER + d0 + gg);
            float4 z = h_unpack4(zh);
            float4 uu = *(const float4*)&u_s[tt][gg];
            float4 yy = *(const float4*)&y_s[tt][gg];
            float4 dp = *(const float4*)(Dp + d0 + gg);
            float4 val;
            val.x = (yy.x + uu.x * dp.x) * (z.x / (1.f + __expf(-z.x)));
            val.y = (yy.y + uu.y * dp.y) * (z.y / (1.f + __expf(-z.y)));
            val.z = (yy.z + uu.z * dp.z) * (z.z / (1.f + __expf(-z.z)));
            val.w = (yy.w + uu.w * dp.w) * (z.w / (1.f + __expf(-z.w)));
            size_t oi = (size_t)rowg * D_INNER + d0 + gg;
            *(uint2*)(yhi + oi) = h_pack4(val);
        }
        __syncthreads();
    }
}

// ---------------- launch ------------------------------------------------------
extern "C" void kernel_launch(void* const* d_in, const int* in_sizes, int n_in,
                              void* d_out, int out_size)
{
    const float* x      = (const float*)d_in[0];
    const float* ln_g   = (const float*)d_in[1];
    const float* ln_b   = (const float*)d_in[2];
    const float* W_in   = (const float*)d_in[3];
    const float* conv_w = (const float*)d_in[4];
    const float* conv_b = (const float*)d_in[5];
    const float* A_log  = (const float*)d_in[6];
    const float* D_prm  = (const float*)d_in[7];
    const float* x_proj = (const float*)d_in[8];
    const float* dt_w   = (const float*)d_in[9];
    const float* dt_b   = (const float*)d_in[10];
    const float* W_out  = (const float*)d_in[11];
    float* out = (float*)d_out;

    __half *xn_hi, *xz_h, *u_hi, *xd_hi, *dl, *y_hi;
    __half *wi_hi, *xp_hi, *dw_hi, *wo_hi;
    float *xdbl, *part;
    cudaGetSymbolAddress((void**)&xn_hi, g_xn_hi);
    cudaGetSymbolAddress((void**)&xz_h,  g_xz_h);
    cudaGetSymbolAddress((void**)&u_hi,  g_u_hi);
    cudaGetSymbolAddress((void**)&xdbl,  g_xdbl);
    cudaGetSymbolAddress((void**)&xd_hi, g_xd_hi);
    cudaGetSymbolAddress((void**)&part,  g_part);
    cudaGetSymbolAddress((void**)&dl,    g_dl);
    cudaGetSymbolAddress((void**)&y_hi,  g_y_hi);
    cudaGetSymbolAddress((void**)&wi_hi, g_wi_hi);
    cudaGetSymbolAddress((void**)&xp_hi, g_xp_hi);
    cudaGetSymbolAddress((void**)&dw_hi, g_dw_hi);
    cudaGetSymbolAddress((void**)&wo_hi, g_wo_hi);

    cudaFuncSetAttribute(gemm_1p<3,1>, cudaFuncAttributeMaxDynamicSharedMemorySize, G1_SMEM);
    cudaFuncSetAttribute(gemm_1p<0,XPROJ_SPLITK>, cudaFuncAttributeMaxDynamicSharedMemorySize, G1_SMEM);
    cudaFuncSetAttribute(gemm_1p<1,1>, cudaFuncAttributeMaxDynamicSharedMemorySize, G1_SMEM);
    cudaFuncSetAttribute(gemm_1p<2,1>, cudaFuncAttributeMaxDynamicSharedMemorySize, G1_SMEM);

    // 0. all weight splits in one launch
    split_all_kernel<<<(N_SPLIT_TOT/8 + 255)/256, 256>>>(
        W_in, W_out, x_proj, dt_w, wi_hi, wo_hi, xp_hi, dw_hi);

    // 1. LayerNorm -> xn hi
    ln_kernel<<<BL, 256>>>(x, ln_g, ln_b, xn_hi);

    // 2. xz = xn @ W_in^T -> fp16  (4096 x 4096 x 1024)
    gemm_1p<3,1><<<dim3(2*D_INNER/128, BL/128), 256, G1_SMEM>>>(
        xn_hi, D_MODEL, wi_hi, D_MODEL,
        xz_h, 2*D_INNER, BL, 2*D_INNER, D_MODEL, nullptr, nullptr);

    // 3. causal depthwise conv + SiLU -> u hi
    conv_silu_kernel<<<(BL*D_INNER/4 + 255)/256, 256>>>(xz_h, conv_w, conv_b, u_hi);

    // 4. x_dbl = u @ x_proj^T  (4096 x 96 x 2048), split-K=4
    gemm_1p<0,XPROJ_SPLITK><<<dim3(1, BL/128, XPROJ_SPLITK), 256, G1_SMEM>>>(
        u_hi, D_INNER, xp_hi, D_INNER,
        part, XDBL_C, BL, XDBL_C, D_INNER, nullptr, nullptr);
    xproj_reduce<<<(BL*XDBL_C/4 + 255)/256, 256>>>(part, xdbl, xd_hi);

    // 5. delta = softplus(dt_r @ dt_w^T + dt_b) -> fp16  (4096 x 2048 x 64)
    gemm_1p<1,1><<<dim3(D_INNER/128, BL/128), 256, G1_SMEM>>>(
        xd_hi, XDBL_C, dw_hi, DT_RANK,
        dl, D_INNER, BL, D_INNER, DT_RANK, dt_b, nullptr);

    // 6. selective scan + fused gate -> y hi
    scan_kernel<<<dim3(D_INNER/SC_DC, BSZ), SC_DC*D_STATE>>>(
        u_hi, dl, xdbl, A_log, xz_h, D_prm, y_hi);

    // 7. out = y @ W_out^T + x  (4096 x 1024 x 2048)
    gemm_1p<2,1><<<dim3(D_MODEL/128, BL/128), 256, G1_SMEM>>>(
        y_hi, D_INNER, wo_hi, D_INNER,
        out, D_MODEL, BL, D_MODEL, D_INNER, nullptr, x);
}

// round 13
// speedup vs baseline: 1.8743x; 1.0115x over previous
#include <cuda_runtime.h>
#include <cuda_fp16.h>
#include <math.h>
#include <stdint.h>

#define D_MODEL 1024
#define D_INNER 2048
#define D_STATE 16
#define DT_RANK 64
#define CONV_K  4
#define BSZ     2
#define SEQ     2048
#define BL      (BSZ*SEQ)             // 4096
#define XDBL_C  (DT_RANK + 2*D_STATE) // 96
#define XPROJ_SPLITK 4

// ---------------- scratch (static device globals) ---------------------------
__device__ __align__(16) __half g_xn_hi[BL * D_MODEL];
__device__ __align__(16) __half g_xz_h [BL * 2 * D_INNER];
__device__ __align__(16) __half g_u_hi [BL * D_INNER];
__device__ __align__(16) float  g_xdbl [BL * XDBL_C];
__device__ __align__(16) __half g_xd_hi[BL * XDBL_C];
__device__ __align__(16) float  g_part [XPROJ_SPLITK * BL * XDBL_C];
__device__ __align__(16) __half g_dl   [BL * D_INNER];
__device__ __align__(16) __half g_y_hi [BL * D_INNER];
__device__ __align__(16) __half g_wi_hi[2 * D_INNER * D_MODEL];
__device__ __align__(16) __half g_xp_hi[XDBL_C * D_INNER];
__device__ __align__(16) __half g_dw_hi[D_INNER * DT_RANK];
__device__ __align__(16) __half g_wo_hi[D_MODEL * D_INNER];

// ---------------- helpers ----------------------------------------------------
__device__ __forceinline__ void cp16(void* dst_smem, const void* src, int sz) {
    uint32_t d = (uint32_t)__cvta_generic_to_shared(dst_smem);
    asm volatile("cp.async.cg.shared.global [%0], [%1], 16, %2;\n"
                 :: "r"(d), "l"(src), "r"(sz));
}
__device__ __forceinline__ void cp_commit() {
    asm volatile("cp.async.commit_group;\n");
}
template<int N_> __device__ __forceinline__ void cp_wait() {
    asm volatile("cp.async.wait_group %0;\n" :: "n"(N_));
}
__device__ __forceinline__ uint2 h_pack4(float4 v) {
    __half2 a = __halves2half2(__float2half_rn(v.x), __float2half_rn(v.y));
    __half2 b = __halves2half2(__float2half_rn(v.z), __float2half_rn(v.w));
    uint2 r; r.x = *(uint32_t*)&a; r.y = *(uint32_t*)&b;
    return r;
}
__device__ __forceinline__ float4 h_unpack4(uint2 h) {
    __half2 a = *(__half2*)&h.x, b = *(__half2*)&h.y;
    return make_float4(__low2float(a), __high2float(a),
                       __low2float(b), __high2float(b));
}
__device__ __forceinline__ void mma16(float* c, const uint32_t* a, const uint32_t* b) {
    asm volatile(
        "mma.sync.aligned.m16n8k16.row.col.f32.f16.f16.f32 "
        "{%0,%1,%2,%3}, {%4,%5,%6,%7}, {%8,%9}, {%0,%1,%2,%3};\n"
        : "+f"(c[0]), "+f"(c[1]), "+f"(c[2]), "+f"(c[3])
        : "r"(a[0]), "r"(a[1]), "r"(a[2]), "r"(a[3]), "r"(b[0]), "r"(b[1]));
}
#define LDSM_X4(r0, r1, r2, r3, addr)                                       \
    asm volatile("ldmatrix.sync.aligned.m8n8.x4.shared.b16 "                \
                 "{%0,%1,%2,%3}, [%4];"                                     \
                 : "=r"(r0), "=r"(r1), "=r"(r2), "=r"(r3) : "r"(addr))

#define RS_H    40
#define TILE_H  (128 * RS_H)      // 5120 halfs = 10240 B

// ================= single-pass fp16 GEMM ====================================
// EPI: 0 fp32 out | 1 softplus(acc+bias[n]) -> half | 2 fp32 + res | 3 half out
#define S1_STAGE_H (2 * TILE_H)
#define G1_SMEM    (3 * S1_STAGE_H * 2)   // 61440 B

template<int EPI, int SPLITK>
__global__ __launch_bounds__(256, 2) void gemm_1p(
    const __half* __restrict__ Ahi, int lda,
    const __half* __restrict__ Bhi, int ldb,
    void* __restrict__ Cout, int ldc, int M, int N, int K,
    const float* __restrict__ bias, const float* __restrict__ res)
{
    extern __shared__ __half sm[];
    int tid = threadIdx.x;
    int m0 = blockIdx.y * 128;
    int n0 = blockIdx.x * 128;

    float* Cf = (float*)Cout;
    __half* Ch = (__half*)Cout;

    if (SPLITK > 1) {
        int z = blockIdx.z;
        int Ks = K / SPLITK;
        Ahi += (size_t)z * Ks;
        Bhi += (size_t)z * Ks;
        Cf += (size_t)z * M * ldc;
        K = Ks;
    }
    int KT = K / 32;

    int lane = tid & 31, wid = tid >> 5;
    int p = lane >> 2, q = lane & 3;
    int wm = (wid & 1) * 64;
    int wn = (wid >> 1) * 32;

    float acc[4][4][4];
    #pragma unroll
    for (int i = 0; i < 4; i++)
        #pragma unroll
        for (int j = 0; j < 4; j++)
            #pragma unroll
            for (int r = 0; r < 4; r++) acc[i][j][r] = 0.f;

    auto load_stage = [&](int kt, int slot) {
        __half* base = sm + slot * S1_STAGE_H;
        int k0 = kt * 32;
        #pragma unroll
        for (int c = tid; c < 1024; c += 256) {
            int tile = c >> 9;            // 0:A 1:B
            int r = (c & 511) >> 2;
            int j = c & 3;
            __half* dst = base + tile * TILE_H + r * RS_H + j * 8;
            if (tile == 0) {
                cp16(dst, Ahi + (size_t)(m0 + r) * lda + k0 + j * 8, 16);
            } else {
                int n = n0 + r;
                int sz = (n < N) ? 16 : 0;
                int rr = sz ? n : 0;
                cp16(dst, Bhi + (size_t)rr * ldb + k0 + j * 8, sz);
            }
        }
    };

    load_stage(0, 0); cp_commit();
    if (KT > 1) load_stage(1, 1);
    cp_commit();

    uint32_t smbase = (uint32_t)__cvta_generic_to_shared(sm);
    uint32_t a_off = ((wm + (lane & 15)) * RS_H + (lane >> 4) * 8) * 2;
    uint32_t b_off = ((wn + (lane >> 4) * 8 + (lane & 7)) * RS_H
                      + ((lane >> 3) & 1) * 8) * 2;

    for (int kt = 0; kt < KT; kt++) {
        cp_wait<1>();
        __syncthreads();
        if (kt + 2 < KT) load_stage(kt + 2, (kt + 2) % 3);
        cp_commit();

        uint32_t st = smbase + (kt % 3) * S1_STAGE_H * 2;
        uint32_t aHi = st + a_off;
        uint32_t bHi = st + TILE_H * 2 + b_off;

        #pragma unroll
        for (int s = 0; s < 2; s++) {
            uint32_t ko = s * 32;
            uint32_t bh[4][2];
            LDSM_X4(bh[0][0], bh[0][1], bh[1][0], bh[1][1], bHi + ko);
            LDSM_X4(bh[2][0], bh[2][1], bh[3][0], bh[3][1], bHi + 16 * RS_H * 2 + ko);
            #pragma unroll
            for (int mi = 0; mi < 4; mi++) {
                uint32_t ah[4];
                LDSM_X4(ah[0], ah[1], ah[2], ah[3], aHi + mi * 16 * RS_H * 2 + ko);
                #pragma unroll
                for (int ni = 0; ni < 4; ni++)
                    mma16(acc[mi][ni], ah, bh[ni]);
            }
        }
        __syncthreads();
    }

    #pragma unroll
    for (int mi = 0; mi < 4; mi++) {
        int row = m0 + wm + mi * 16 + p;
        #pragma unroll
        for (int ni = 0; ni < 4; ni++) {
            int col = n0 + wn + ni * 8 + q * 2;
            if (col < N) {
                float v[4] = { acc[mi][ni][0], acc[mi][ni][1],
                               acc[mi][ni][2], acc[mi][ni][3] };
                if (EPI == 1) {
                    #pragma unroll
                    for (int r = 0; r < 4; r++) {
                        float t = v[r] + bias[col + (r & 1)];
                        float e = __expf(t);
                        v[r] = (t > 15.f) ? t : log1pf(e);
                    }
                }
                if (EPI == 1 || EPI == 3) {
                    __half2 v01 = __halves2half2(__float2half_rn(v[0]),
                                                 __float2half_rn(v[1]));
                    __half2 v23 = __halves2half2(__float2half_rn(v[2]),
                                                 __float2half_rn(v[3]));
                    *(__half2*)(Ch + (size_t)row * ldc + col) = v01;
                    *(__half2*)(Ch + (size_t)(row + 8) * ldc + col) = v23;
                } else {
                    if (EPI == 2) {
                        v[0] += res[(size_t)row * ldc + col];
                        v[1] += res[(size_t)row * ldc + col + 1];
                        v[2] += res[(size_t)(row + 8) * ldc + col];
                        v[3] += res[(size_t)(row + 8) * ldc + col + 1];
                    }
                    float* c0 = Cf + (size_t)row * ldc + col;
                    float* c1 = Cf + (size_t)(row + 8) * ldc + col;
                    c0[0] = v[0]; c0[1] = v[1];
                    c1[0] = v[2]; c1[1] = v[3];
                }
            }
        }
    }
}

// ---------------- fused weight splits (all 4 in one launch) -------------------
#define N_WI  (2 * D_INNER * D_MODEL)
#define N_WO  (D_MODEL * D_INNER)
#define N_XP  (XDBL_C * D_INNER)
#define N_DW  (D_INNER * DT_RANK)
#define N_SPLIT_TOT (N_WI + N_WO + N_XP + N_DW)

__global__ __launch_bounds__(256) void split_all_kernel(
    const float* __restrict__ wi, const float* __restrict__ wo,
    const float* __restrict__ xp, const float* __restrict__ dw,
    __half* __restrict__ wi_h, __half* __restrict__ wo_h,
    __half* __restrict__ xp_h, __half* __restrict__ dw_h)
{
    int i = (blockIdx.x * 256 + threadIdx.x) * 8;
    if (i >= N_SPLIT_TOT) return;
    const float* src; __half* dst; int off;
    if (i < N_WI)                    { src = wi; dst = wi_h; off = i; }
    else if (i < N_WI + N_WO)        { src = wo; dst = wo_h; off = i - N_WI; }
    else if (i < N_WI + N_WO + N_XP) { src = xp; dst = xp_h; off = i - N_WI - N_WO; }
    else                             { src = dw; dst = dw_h; off = i - N_WI - N_WO - N_XP; }
    float4 a = *(const float4*)(src + off);
    float4 b = *(const float4*)(src + off + 4);
    uint2 h0 = h_pack4(a), h1 = h_pack4(b);
    *(uint4*)(dst + off) = make_uint4(h0.x, h0.y, h1.x, h1.y);
}

// ---------------- LayerNorm (hi only) -----------------------------------------
__global__ __launch_bounds__(256) void ln_kernel(
    const float* __restrict__ x, const float* __restrict__ g,
    const float* __restrict__ b, __half* __restrict__ ohi)
{
    int row = blockIdx.x;
    const float4* xr = (const float4*)(x + (size_t)row * D_MODEL);
    float4 v = xr[threadIdx.x];
    float s  = v.x + v.y + v.z + v.w;
    float ss = v.x*v.x + v.y*v.y + v.z*v.z + v.w*v.w;
    #pragma unroll
    for (int o = 16; o; o >>= 1) {
        s  += __shfl_xor_sync(0xffffffffu, s, o);
        ss += __shfl_xor_sync(0xffffffffu, ss, o);
    }
    __shared__ float red[16];
    __shared__ float mu_s, rstd_s;
    int w = threadIdx.x >> 5, lane = threadIdx.x & 31;
    if (lane == 0) { red[w] = s; red[8 + w] = ss; }
    __syncthreads();
    if (threadIdx.x == 0) {
        float S = 0.f, SS = 0.f;
        #pragma unroll
        for (int i = 0; i < 8; i++) { S += red[i]; SS += red[8 + i]; }
        float mu = S * (1.f / D_MODEL);
        float var = SS * (1.f / D_MODEL) - mu * mu;
        mu_s = mu; rstd_s = rsqrtf(var + 1e-5f);
    }
    __syncthreads();
    float mu = mu_s, r = rstd_s;
    float4 gv = ((const float4*)g)[threadIdx.x];
    float4 bv = ((const float4*)b)[threadIdx.x];
    float4 o;
    o.x = (v.x - mu) * r * gv.x + bv.x;
    o.y = (v.y - mu) * r * gv.y + bv.y;
    o.z = (v.z - mu) * r * gv.z + bv.z;
    o.w = (v.w - mu) * r * gv.w + bv.w;
    ((uint2*)(ohi + (size_t)row * D_MODEL))[threadIdx.x] = h_pack4(o);
}

// ---------------- split-K reduce for x_proj (fp32 + hi) -----------------------
__global__ __launch_bounds__(256) void xproj_reduce(
    const float* __restrict__ part, float* __restrict__ out,
    __half* __restrict__ ohi)
{
    int i = (blockIdx.x * 256 + threadIdx.x) * 4;
    if (i >= BL * XDBL_C) return;
    const int stride = BL * XDBL_C;
    float4 s = *(const float4*)(part + i);
    #pragma unroll
    for (int z = 1; z < XPROJ_SPLITK; z++) {
        float4 p = *(const float4*)(part + z * stride + i);
        s.x += p.x; s.y += p.y; s.z += p.z; s.w += p.w;
    }
    *(float4*)(out + i) = s;
    *(uint2*)(ohi + i) = h_pack4(s);
}

// ---------------- causal depthwise conv (K=4) + SiLU, time-tiled x4 ----------
// Thread computes 4 channels x 4 consecutive timesteps: 7 input rows -> 4 outputs
__global__ __launch_bounds__(256) void conv_silu_kernel(
    const __half* __restrict__ xz, const float* __restrict__ w,
    const float* __restrict__ bias, __half* __restrict__ uhi)
{
    const int ND4 = D_INNER / 4;          // 512 channel quads
    const int NT4 = SEQ / 4;              // 512 time quads
    int idx = blockIdx.x * 256 + threadIdx.x;
    if (idx >= BSZ * NT4 * ND4) return;
    int d4 = (idx % ND4) * 4;
    int t0 = ((idx / ND4) % NT4) * 4;
    int b  = idx / (ND4 * NT4);

    float4 bi = *(const float4*)(bias + d4);
    float4 wr[4];
    #pragma unroll
    for (int c = 0; c < 4; c++) wr[c] = *(const float4*)(w + (d4 + c) * CONV_K);

    // load 7 input rows: t0-3 .. t0+3
    float4 xv[7];
    #pragma unroll
    for (int j = 0; j < 7; j++) {
        int ts = t0 - 3 + j;
        if (ts >= 0) {
            uint2 xh = *(const uint2*)(xz + (size_t)(b * SEQ + ts) * (2 * D_INNER) + d4);
            xv[j] = h_unpack4(xh);
        } else {
            xv[j] = make_float4(0.f, 0.f, 0.f, 0.f);
        }
    }

    #pragma unroll
    for (int o = 0; o < 4; o++) {
        float4 acc = bi;
        #pragma unroll
        for (int k = 0; k < CONV_K; k++) {
            float4 xk = xv[o + k];
            acc.x += ((const float*)&wr[0])[k] * xk.x;
            acc.y += ((const float*)&wr[1])[k] * xk.y;
            acc.z += ((const float*)&wr[2])[k] * xk.z;
            acc.w += ((const float*)&wr[3])[k] * xk.w;
        }
        float4 val;
        val.x = acc.x / (1.f + __expf(-acc.x));
        val.y = acc.y / (1.f + __expf(-acc.y));
        val.z = acc.z / (1.f + __expf(-acc.z));
        val.w = acc.w / (1.f + __expf(-acc.w));
        size_t oi = (size_t)(b * SEQ + t0 + o) * D_INNER + d4;
        *(uint2*)(uhi + oi) = h_pack4(val);
    }
}

// ---------------- selective scan (gate fused; all-fp16 streams) ---------------
#define SC_DC 16
#define SC_TC 64
__global__ __launch_bounds__(SC_DC * D_STATE) void scan_kernel(
    const __half* __restrict__ uhi, const __half* __restrict__ dl,
    const float* __restrict__ xdbl, const float* __restrict__ A_log,
    const __half* __restrict__ xz, const float* __restrict__ Dp,
    __half* __restrict__ yhi)
{
    __shared__ float u_s [SC_TC][SC_DC];
    __shared__ float dl_s[SC_TC][SC_DC];
    __shared__ float B_s [SC_TC][D_STATE];
    __shared__ float C_s [SC_TC][D_STATE];
    __shared__ float y_s [SC_TC][SC_DC];

    int b  = blockIdx.y;
    int d0 = blockIdx.x * SC_DC;
    int tid = threadIdx.x;
    int g = tid >> 4;
    int n = tid & 15;
    int d = d0 + g;

    float a = -expf(A_log[d * D_STATE + n]);
    float s = 0.f;

    for (int t0 = 0; t0 < SEQ; t0 += SC_TC) {
        {
            int i = tid * 4;
            int tt = i >> 4, gg = i & 15;
            size_t gi = (size_t)(b * SEQ + t0 + tt) * D_INNER + d0 + gg;
            *(float4*)&u_s [tt][gg] = h_unpack4(*(const uint2*)(uhi + gi));
            *(float4*)&dl_s[tt][gg] = h_unpack4(*(const uint2*)(dl + gi));
        }
        for (int i = tid * 4; i < SC_TC * 32; i += 1024) {
            int tt = i >> 5, pos = i & 31;
            const float* r = xdbl + (size_t)(b * SEQ + t0 + tt) * XDBL_C + DT_RANK;
            float4 v = *(const float4*)(r + pos);
            if (pos < 16) *(float4*)&B_s[tt][pos] = v;
            else          *(float4*)&C_s[tt][pos - 16] = v;
        }
        __syncthreads();
        #pragma unroll 4
        for (int t = 0; t < SC_TC; t++) {
            float dlt = dl_s[t][g];
            float dA  = __expf(dlt * a);
            float dbu = dlt * B_s[t][n] * u_s[t][g];
            s = fmaf(dA, s, dbu);
            float part = s * C_s[t][n];
            part += __shfl_xor_sync(0xffffffffu, part, 8);
            part += __shfl_xor_sync(0xffffffffu, part, 4);
            part += __shfl_xor_sync(0xffffffffu, part, 2);
            part += __shfl_xor_sync(0xffffffffu, part, 1);
            if (n == 0) y_s[t][g] = part;
        }
        __syncthreads();
        {
            int i = tid * 4;
            int tt = i >> 4, gg = i & 15;
            int rowg = b * SEQ + t0 + tt;
            uint2 zh = *(const uint2*)(xz + (size_t)rowg * (2 * D_INNER) + D_INNER + d0 + gg);
            float4 z = h_unpack4(zh);
            float4 uu = *(const float4*)&u_s[tt][gg];
            float4 yy = *(const float4*)&y_s[tt][gg];
            float4 dp = *(const float4*)(Dp + d0 + gg);
            float4 val;
            val.x = (yy.x + uu.x * dp.x) * (z.x / (1.f + __expf(-z.x)));
            val.y = (yy.y + uu.y * dp.y) * (z.y / (1.f + __expf(-z.y)));
            val.z = (yy.z + uu.z * dp.z) * (z.z / (1.f + __expf(-z.z)));
            val.w = (yy.w + uu.w * dp.w) * (z.w / (1.f + __expf(-z.w)));
            size_t oi = (size_t)rowg * D_INNER + d0 + gg;
            *(uint2*)(yhi + oi) = h_pack4(val);
        }
        __syncthreads();
    }
}

// ---------------- launch ------------------------------------------------------
extern "C" void kernel_launch(void* const* d_in, const int* in_sizes, int n_in,
                              void* d_out, int out_size)
{
    const float* x      = (const float*)d_in[0];
    const float* ln_g   = (const float*)d_in[1];
    const float* ln_b   = (const float*)d_in[2];
    const float* W_in   = (const float*)d_in[3];
    const float* conv_w = (const float*)d_in[4];
    const float* conv_b = (const float*)d_in[5];
    const float* A_log  = (const float*)d_in[6];
    const float* D_prm  = (const float*)d_in[7];
    const float* x_proj = (const float*)d_in[8];
    const float* dt_w   = (const float*)d_in[9];
    const float* dt_b   = (const float*)d_in[10];
    const float* W_out  = (const float*)d_in[11];
    float* out = (float*)d_out;

    __half *xn_hi, *xz_h, *u_hi, *xd_hi, *dl, *y_hi;
    __half *wi_hi, *xp_hi, *dw_hi, *wo_hi;
    float *xdbl, *part;
    cudaGetSymbolAddress((void**)&xn_hi, g_xn_hi);
    cudaGetSymbolAddress((void**)&xz_h,  g_xz_h);
    cudaGetSymbolAddress((void**)&u_hi,  g_u_hi);
    cudaGetSymbolAddress((void**)&xdbl,  g_xdbl);
    cudaGetSymbolAddress((void**)&xd_hi, g_xd_hi);
    cudaGetSymbolAddress((void**)&part,  g_part);
    cudaGetSymbolAddress((void**)&dl,    g_dl);
    cudaGetSymbolAddress((void**)&y_hi,  g_y_hi);
    cudaGetSymbolAddress((void**)&wi_hi, g_wi_hi);
    cudaGetSymbolAddress((void**)&xp_hi, g_xp_hi);
    cudaGetSymbolAddress((void**)&dw_hi, g_dw_hi);
    cudaGetSymbolAddress((void**)&wo_hi, g_wo_hi);

    cudaFuncSetAttribute(gemm_1p<3,1>, cudaFuncAttributeMaxDynamicSharedMemorySize, G1_SMEM);
    cudaFuncSetAttribute(gemm_1p<0,XPROJ_SPLITK>, cudaFuncAttributeMaxDynamicSharedMemorySize, G1_SMEM);
    cudaFuncSetAttribute(gemm_1p<1,1>, cudaFuncAttributeMaxDynamicSharedMemorySize, G1_SMEM);
    cudaFuncSetAttribute(gemm_1p<2,1>, cudaFuncAttributeMaxDynamicSharedMemorySize, G1_SMEM);

    // 0. all weight splits in one launch
    split_all_kernel<<<(N_SPLIT_TOT/8 + 255)/256, 256>>>(
        W_in, W_out, x_proj, dt_w, wi_hi, wo_hi, xp_hi, dw_hi);

    // 1. LayerNorm -> xn hi
    ln_kernel<<<BL, 256>>>(x, ln_g, ln_b, xn_hi);

    // 2. xz = xn @ W_in^T -> fp16  (4096 x 4096 x 1024)
    gemm_1p<3,1><<<dim3(2*D_INNER/128, BL/128), 256, G1_SMEM>>>(
        xn_hi, D_MODEL, wi_hi, D_MODEL,
        xz_h, 2*D_INNER, BL, 2*D_INNER, D_MODEL, nullptr, nullptr);

    // 3. causal depthwise conv + SiLU -> u hi (time-tiled x4)
    conv_silu_kernel<<<(BL*D_INNER/16 + 255)/256, 256>>>(xz_h, conv_w, conv_b, u_hi);

    // 4. x_dbl = u @ x_proj^T  (4096 x 96 x 2048), split-K=4
    gemm_1p<0,XPROJ_SPLITK><<<dim3(1, BL/128, XPROJ_SPLITK), 256, G1_SMEM>>>(
        u_hi, D_INNER, xp_hi, D_INNER,
        part, XDBL_C, BL, XDBL_C, D_INNER, nullptr, nullptr);
    xproj_reduce<<<(BL*XDBL_C/4 + 255)/256, 256>>>(part, xdbl, xd_hi);

    // 5. delta = softplus(dt_r @ dt_w^T + dt_b) -> fp16  (4096 x 2048 x 64)
    gemm_1p<1,1><<<dim3(D_INNER/128, BL/128), 256, G1_SMEM>>>(
        xd_hi, XDBL_C, dw_hi, DT_RANK,
        dl, D_INNER, BL, D_INNER, DT_RANK, dt_b, nullptr);

    // 6. selective scan + fused gate -> y hi
    scan_kernel<<<dim3(D_INNER/SC_DC, BSZ), SC_DC*D_STATE>>>(
        u_hi, dl, xdbl, A_log, xz_h, D_prm, y_hi);

    // 7. out = y @ W_out^T + x  (4096 x 1024 x 2048)
    gemm_1p<2,1><<<dim3(D_MODEL/128, BL/128), 256, G1_SMEM>>>(
        y_hi, D_INNER, wo_hi, D_INNER,
        out, D_MODEL, BL, D_MODEL, D_INNER, nullptr, x);
}

// round 14
// speedup vs baseline: 1.9159x; 1.0222x over previous
#include <cuda_runtime.h>
#include <cuda_fp16.h>
#include <math.h>
#include <stdint.h>

#define D_MODEL 1024
#define D_INNER 2048
#define D_STATE 16
#define DT_RANK 64
#define CONV_K  4
#define BSZ     2
#define SEQ     2048
#define BL      (BSZ*SEQ)             // 4096
#define XDBL_C  (DT_RANK + 2*D_STATE) // 96
#define XPROJ_SPLITK 8

// ---------------- scratch (static device globals) ---------------------------
__device__ __align__(16) __half g_xn_hi[BL * D_MODEL];
__device__ __align__(16) __half g_xz_h [BL * 2 * D_INNER];
__device__ __align__(16) __half g_u_hi [BL * D_INNER];
__device__ __align__(16) float  g_xdbl [BL * XDBL_C];
__device__ __align__(16) __half g_xd_hi[BL * XDBL_C];
__device__ __align__(16) float  g_part [XPROJ_SPLITK * BL * XDBL_C];
__device__ __align__(16) __half g_dl   [BL * D_INNER];
__device__ __align__(16) __half g_y_hi [BL * D_INNER];
__device__ __align__(16) __half g_wi_hi[2 * D_INNER * D_MODEL];
__device__ __align__(16) __half g_xp_hi[XDBL_C * D_INNER];
__device__ __align__(16) __half g_dw_hi[D_INNER * DT_RANK];
__device__ __align__(16) __half g_wo_hi[D_MODEL * D_INNER];

// ---------------- helpers ----------------------------------------------------
__device__ __forceinline__ void cp16(void* dst_smem, const void* src, int sz) {
    uint32_t d = (uint32_t)__cvta_generic_to_shared(dst_smem);
    asm volatile("cp.async.cg.shared.global [%0], [%1], 16, %2;\n"
                 :: "r"(d), "l"(src), "r"(sz));
}
__device__ __forceinline__ void cp_commit() {
    asm volatile("cp.async.commit_group;\n");
}
template<int N_> __device__ __forceinline__ void cp_wait() {
    asm volatile("cp.async.wait_group %0;\n" :: "n"(N_));
}
__device__ __forceinline__ uint2 h_pack4(float4 v) {
    __half2 a = __halves2half2(__float2half_rn(v.x), __float2half_rn(v.y));
    __half2 b = __halves2half2(__float2half_rn(v.z), __float2half_rn(v.w));
    uint2 r; r.x = *(uint32_t*)&a; r.y = *(uint32_t*)&b;
    return r;
}
__device__ __forceinline__ float4 h_unpack4(uint2 h) {
    __half2 a = *(__half2*)&h.x, b = *(__half2*)&h.y;
    return make_float4(__low2float(a), __high2float(a),
                       __low2float(b), __high2float(b));
}
__device__ __forceinline__ void mma16(float* c, const uint32_t* a, const uint32_t* b) {
    asm volatile(
        "mma.sync.aligned.m16n8k16.row.col.f32.f16.f16.f32 "
        "{%0,%1,%2,%3}, {%4,%5,%6,%7}, {%8,%9}, {%0,%1,%2,%3};\n"
        : "+f"(c[0]), "+f"(c[1]), "+f"(c[2]), "+f"(c[3])
        : "r"(a[0]), "r"(a[1]), "r"(a[2]), "r"(a[3]), "r"(b[0]), "r"(b[1]));
}
#define LDSM_X4(r0, r1, r2, r3, addr)                                       \
    asm volatile("ldmatrix.sync.aligned.m8n8.x4.shared.b16 "                \
                 "{%0,%1,%2,%3}, [%4];"                                     \
                 : "=r"(r0), "=r"(r1), "=r"(r2), "=r"(r3) : "r"(addr))

#define RS_H    40
#define TILE_H  (128 * RS_H)      // 5120 halfs = 10240 B

// ================= single-pass fp16 GEMM, 4-stage pipeline ==================
// EPI: 0 fp32 out | 1 softplus(acc+bias[n]) -> half | 2 fp32 + res | 3 half out
#define S1_STAGE_H (2 * TILE_H)           // 20480 B
#define G1_SMEM    (4 * S1_STAGE_H * 2)   // 81920 B

template<int EPI, int SPLITK>
__global__ __launch_bounds__(256, 2) void gemm_1p(
    const __half* __restrict__ Ahi, int lda,
    const __half* __restrict__ Bhi, int ldb,
    void* __restrict__ Cout, int ldc, int M, int N, int K,
    const float* __restrict__ bias, const float* __restrict__ res)
{
    extern __shared__ __half sm[];
    int tid = threadIdx.x;
    int m0 = blockIdx.y * 128;
    int n0 = blockIdx.x * 128;

    float* Cf = (float*)Cout;
    __half* Ch = (__half*)Cout;

    if (SPLITK > 1) {
        int z = blockIdx.z;
        int Ks = K / SPLITK;
        Ahi += (size_t)z * Ks;
        Bhi += (size_t)z * Ks;
        Cf += (size_t)z * M * ldc;
        K = Ks;
    }
    int KT = K / 32;

    int lane = tid & 31, wid = tid >> 5;
    int p = lane >> 2, q = lane & 3;
    int wm = (wid & 1) * 64;
    int wn = (wid >> 1) * 32;

    float acc[4][4][4];
    #pragma unroll
    for (int i = 0; i < 4; i++)
        #pragma unroll
        for (int j = 0; j < 4; j++)
            #pragma unroll
            for (int r = 0; r < 4; r++) acc[i][j][r] = 0.f;

    auto load_stage = [&](int kt, int slot) {
        __half* base = sm + slot * S1_STAGE_H;
        int k0 = kt * 32;
        #pragma unroll
        for (int c = tid; c < 1024; c += 256) {
            int tile = c >> 9;            // 0:A 1:B
            int r = (c & 511) >> 2;
            int j = c & 3;
            __half* dst = base + tile * TILE_H + r * RS_H + j * 8;
            if (tile == 0) {
                cp16(dst, Ahi + (size_t)(m0 + r) * lda + k0 + j * 8, 16);
            } else {
                int n = n0 + r;
                int sz = (n < N) ? 16 : 0;
                int rr = sz ? n : 0;
                cp16(dst, Bhi + (size_t)rr * ldb + k0 + j * 8, sz);
            }
        }
    };

    // prologue: stages 0,1,2 (empty commits if KT small keep the count right)
    load_stage(0, 0); cp_commit();
    if (KT > 1) load_stage(1, 1);
    cp_commit();
    if (KT > 2) load_stage(2, 2);
    cp_commit();

    uint32_t smbase = (uint32_t)__cvta_generic_to_shared(sm);
    uint32_t a_off = ((wm + (lane & 15)) * RS_H + (lane >> 4) * 8) * 2;
    uint32_t b_off = ((wn + (lane >> 4) * 8 + (lane & 7)) * RS_H
                      + ((lane >> 3) & 1) * 8) * 2;

    for (int kt = 0; kt < KT; kt++) {
        cp_wait<2>();
        __syncthreads();
        if (kt + 3 < KT) load_stage(kt + 3, (kt + 3) & 3);
        cp_commit();

        uint32_t st = smbase + (kt & 3) * S1_STAGE_H * 2;
        uint32_t aHi = st + a_off;
        uint32_t bHi = st + TILE_H * 2 + b_off;

        #pragma unroll
        for (int s = 0; s < 2; s++) {
            uint32_t ko = s * 32;
            uint32_t bh[4][2];
            LDSM_X4(bh[0][0], bh[0][1], bh[1][0], bh[1][1], bHi + ko);
            LDSM_X4(bh[2][0], bh[2][1], bh[3][0], bh[3][1], bHi + 16 * RS_H * 2 + ko);
            #pragma unroll
            for (int mi = 0; mi < 4; mi++) {
                uint32_t ah[4];
                LDSM_X4(ah[0], ah[1], ah[2], ah[3], aHi + mi * 16 * RS_H * 2 + ko);
                #pragma unroll
                for (int ni = 0; ni < 4; ni++)
                    mma16(acc[mi][ni], ah, bh[ni]);
            }
        }
    }

    #pragma unroll
    for (int mi = 0; mi < 4; mi++) {
        int row = m0 + wm + mi * 16 + p;
        #pragma unroll
        for (int ni = 0; ni < 4; ni++) {
            int col = n0 + wn + ni * 8 + q * 2;
            if (col < N) {
                float v[4] = { acc[mi][ni][0], acc[mi][ni][1],
                               acc[mi][ni][2], acc[mi][ni][3] };
                if (EPI == 1) {
                    #pragma unroll
                    for (int r = 0; r < 4; r++) {
                        float t = v[r] + bias[col + (r & 1)];
                        float e = __expf(t);
                        v[r] = (t > 15.f) ? t : log1pf(e);
                    }
                }
                if (EPI == 1 || EPI == 3) {
                    __half2 v01 = __halves2half2(__float2half_rn(v[0]),
                                                 __float2half_rn(v[1]));
                    __half2 v23 = __halves2half2(__float2half_rn(v[2]),
                                                 __float2half_rn(v[3]));
                    *(__half2*)(Ch + (size_t)row * ldc + col) = v01;
                    *(__half2*)(Ch + (size_t)(row + 8) * ldc + col) = v23;
                } else {
                    if (EPI == 2) {
                        v[0] += res[(size_t)row * ldc + col];
                        v[1] += res[(size_t)row * ldc + col + 1];
                        v[2] += res[(size_t)(row + 8) * ldc + col];
                        v[3] += res[(size_t)(row + 8) * ldc + col + 1];
                    }
                    float* c0 = Cf + (size_t)row * ldc + col;
                    float* c1 = Cf + (size_t)(row + 8) * ldc + col;
                    c0[0] = v[0]; c0[1] = v[1];
                    c1[0] = v[2]; c1[1] = v[3];
                }
            }
        }
    }
}

// ---------------- fused weight splits (all 4 in one launch) -------------------
#define N_WI  (2 * D_INNER * D_MODEL)
#define N_WO  (D_MODEL * D_INNER)
#define N_XP  (XDBL_C * D_INNER)
#define N_DW  (D_INNER * DT_RANK)
#define N_SPLIT_TOT (N_WI + N_WO + N_XP + N_DW)

__global__ __launch_bounds__(256) void split_all_kernel(
    const float* __restrict__ wi, const float* __restrict__ wo,
    const float* __restrict__ xp, const float* __restrict__ dw,
    __half* __restrict__ wi_h, __half* __restrict__ wo_h,
    __half* __restrict__ xp_h, __half* __restrict__ dw_h)
{
    int i = (blockIdx.x * 256 + threadIdx.x) * 8;
    if (i >= N_SPLIT_TOT) return;
    const float* src; __half* dst; int off;
    if (i < N_WI)                    { src = wi; dst = wi_h; off = i; }
    else if (i < N_WI + N_WO)        { src = wo; dst = wo_h; off = i - N_WI; }
    else if (i < N_WI + N_WO + N_XP) { src = xp; dst = xp_h; off = i - N_WI - N_WO; }
    else                             { src = dw; dst = dw_h; off = i - N_WI - N_WO - N_XP; }
    float4 a = *(const float4*)(src + off);
    float4 b = *(const float4*)(src + off + 4);
    uint2 h0 = h_pack4(a), h1 = h_pack4(b);
    *(uint4*)(dst + off) = make_uint4(h0.x, h0.y, h1.x, h1.y);
}

// ---------------- LayerNorm (hi only) -----------------------------------------
__global__ __launch_bounds__(256) void ln_kernel(
    const float* __restrict__ x, const float* __restrict__ g,
    const float* __restrict__ b, __half* __restrict__ ohi)
{
    int row = blockIdx.x;
    const float4* xr = (const float4*)(x + (size_t)row * D_MODEL);
    float4 v = xr[threadIdx.x];
    float s  = v.x + v.y + v.z + v.w;
    float ss = v.x*v.x + v.y*v.y + v.z*v.z + v.w*v.w;
    #pragma unroll
    for (int o = 16; o; o >>= 1) {
        s  += __shfl_xor_sync(0xffffffffu, s, o);
        ss += __shfl_xor_sync(0xffffffffu, ss, o);
    }
    __shared__ float red[16];
    __shared__ float mu_s, rstd_s;
    int w = threadIdx.x >> 5, lane = threadIdx.x & 31;
    if (lane == 0) { red[w] = s; red[8 + w] = ss; }
    __syncthreads();
    if (threadIdx.x == 0) {
        float S = 0.f, SS = 0.f;
        #pragma unroll
        for (int i = 0; i < 8; i++) { S += red[i]; SS += red[8 + i]; }
        float mu = S * (1.f / D_MODEL);
        float var = SS * (1.f / D_MODEL) - mu * mu;
        mu_s = mu; rstd_s = rsqrtf(var + 1e-5f);
    }
    __syncthreads();
    float mu = mu_s, r = rstd_s;
    float4 gv = ((const float4*)g)[threadIdx.x];
    float4 bv = ((const float4*)b)[threadIdx.x];
    float4 o;
    o.x = (v.x - mu) * r * gv.x + bv.x;
    o.y = (v.y - mu) * r * gv.y + bv.y;
    o.z = (v.z - mu) * r * gv.z + bv.z;
    o.w = (v.w - mu) * r * gv.w + bv.w;
    ((uint2*)(ohi + (size_t)row * D_MODEL))[threadIdx.x] = h_pack4(o);
}

// ---------------- split-K reduce for x_proj (fp32 + hi) -----------------------
__global__ __launch_bounds__(256) void xproj_reduce(
    const float* __restrict__ part, float* __restrict__ out,
    __half* __restrict__ ohi)
{
    int i = (blockIdx.x * 256 + threadIdx.x) * 4;
    if (i >= BL * XDBL_C) return;
    const int stride = BL * XDBL_C;
    float4 s = *(const float4*)(part + i);
    #pragma unroll
    for (int z = 1; z < XPROJ_SPLITK; z++) {
        float4 p = *(const float4*)(part + z * stride + i);
        s.x += p.x; s.y += p.y; s.z += p.z; s.w += p.w;
    }
    *(float4*)(out + i) = s;
    *(uint2*)(ohi + i) = h_pack4(s);
}

// ---------------- causal depthwise conv (K=4) + SiLU, time-tiled x4 ----------
__global__ __launch_bounds__(256) void conv_silu_kernel(
    const __half* __restrict__ xz, const float* __restrict__ w,
    const float* __restrict__ bias, __half* __restrict__ uhi)
{
    const int ND4 = D_INNER / 4;
    const int NT4 = SEQ / 4;
    int idx = blockIdx.x * 256 + threadIdx.x;
    if (idx >= BSZ * NT4 * ND4) return;
    int d4 = (idx % ND4) * 4;
    int t0 = ((idx / ND4) % NT4) * 4;
    int b  = idx / (ND4 * NT4);

    float4 bi = *(const float4*)(bias + d4);
    float4 wr[4];
    #pragma unroll
    for (int c = 0; c < 4; c++) wr[c] = *(const float4*)(w + (d4 + c) * CONV_K);

    float4 xv[7];
    #pragma unroll
    for (int j = 0; j < 7; j++) {
        int ts = t0 - 3 + j;
        if (ts >= 0) {
            uint2 xh = *(const uint2*)(xz + (size_t)(b * SEQ + ts) * (2 * D_INNER) + d4);
            xv[j] = h_unpack4(xh);
        } else {
            xv[j] = make_float4(0.f, 0.f, 0.f, 0.f);
        }
    }

    #pragma unroll
    for (int o = 0; o < 4; o++) {
        float4 acc = bi;
        #pragma unroll
        for (int k = 0; k < CONV_K; k++) {
            float4 xk = xv[o + k];
            acc.x += ((const float*)&wr[0])[k] * xk.x;
            acc.y += ((const float*)&wr[1])[k] * xk.y;
            acc.z += ((const float*)&wr[2])[k] * xk.z;
            acc.w += ((const float*)&wr[3])[k] * xk.w;
        }
        float4 val;
        val.x = acc.x / (1.f + __expf(-acc.x));
        val.y = acc.y / (1.f + __expf(-acc.y));
        val.z = acc.z / (1.f + __expf(-acc.z));
        val.w = acc.w / (1.f + __expf(-acc.w));
        size_t oi = (size_t)(b * SEQ + t0 + o) * D_INNER + d4;
        *(uint2*)(uhi + oi) = h_pack4(val);
    }
}

// ---------------- selective scan (gate fused; all-fp16 streams) ---------------
#define SC_DC 16
#define SC_TC 64
__global__ __launch_bounds__(SC_DC * D_STATE) void scan_kernel(
    const __half* __restrict__ uhi, const __half* __restrict__ dl,
    const float* __restrict__ xdbl, const float* __restrict__ A_log,
    const __half* __restrict__ xz, const float* __restrict__ Dp,
    __half* __restrict__ yhi)
{
    __shared__ float u_s [SC_TC][SC_DC];
    __shared__ float dl_s[SC_TC][SC_DC];
    __shared__ float B_s [SC_TC][D_STATE];
    __shared__ float C_s [SC_TC][D_STATE];
    __shared__ float y_s [SC_TC][SC_DC];

    int b  = blockIdx.y;
    int d0 = blockIdx.x * SC_DC;
    int tid = threadIdx.x;
    int g = tid >> 4;
    int n = tid & 15;
    int d = d0 + g;

    float a = -expf(A_log[d * D_STATE + n]);
    float s = 0.f;

    for (int t0 = 0; t0 < SEQ; t0 += SC_TC) {
        {
            int i = tid * 4;
            int tt = i >> 4, gg = i & 15;
            size_t gi = (size_t)(b * SEQ + t0 + tt) * D_INNER + d0 + gg;
            *(float4*)&u_s [tt][gg] = h_unpack4(*(const uint2*)(uhi + gi));
            *(float4*)&dl_s[tt][gg] = h_unpack4(*(const uint2*)(dl + gi));
        }
        for (int i = tid * 4; i < SC_TC * 32; i += 1024) {
            int tt = i >> 5, pos = i & 31;
            const float* r = xdbl + (size_t)(b * SEQ + t0 + tt) * XDBL_C + DT_RANK;
            float4 v = *(const float4*)(r + pos);
            if (pos < 16) *(float4*)&B_s[tt][pos] = v;
            else          *(float4*)&C_s[tt][pos - 16] = v;
        }
        __syncthreads();
        #pragma unroll 4
        for (int t = 0; t < SC_TC; t++) {
            float dlt = dl_s[t][g];
            float dA  = __expf(dlt * a);
            float dbu = dlt * B_s[t][n] * u_s[t][g];
            s = fmaf(dA, s, dbu);
            float part = s * C_s[t][n];
            part += __shfl_xor_sync(0xffffffffu, part, 8);
            part += __shfl_xor_sync(0xffffffffu, part, 4);
            part += __shfl_xor_sync(0xffffffffu, part, 2);
            part += __shfl_xor_sync(0xffffffffu, part, 1);
            if (n == 0) y_s[t][g] = part;
        }
        __syncthreads();
        {
            int i = tid * 4;
            int tt = i >> 4, gg = i & 15;
            int rowg = b * SEQ + t0 + tt;
            uint2 zh = *(const uint2*)(xz + (size_t)rowg * (2 * D_INNER) + D_INNER + d0 + gg);
            float4 z = h_unpack4(zh);
            float4 uu = *(const float4*)&u_s[tt][gg];
            float4 yy = *(const float4*)&y_s[tt][gg];
            float4 dp = *(const float4*)(Dp + d0 + gg);
            float4 val;
            val.x = (yy.x + uu.x * dp.x) * (z.x / (1.f + __expf(-z.x)));
            val.y = (yy.y + uu.y * dp.y) * (z.y / (1.f + __expf(-z.y)));
            val.z = (yy.z + uu.z * dp.z) * (z.z / (1.f + __expf(-z.z)));
            val.w = (yy.w + uu.w * dp.w) * (z.w / (1.f + __expf(-z.w)));
            size_t oi = (size_t)rowg * D_INNER + d0 + gg;
            *(uint2*)(yhi + oi) = h_pack4(val);
        }
        __syncthreads();
    }
}

// ---------------- launch ------------------------------------------------------
extern "C" void kernel_launch(void* const* d_in, const int* in_sizes, int n_in,
                              void* d_out, int out_size)
{
    const float* x      = (const float*)d_in[0];
    const float* ln_g   = (const float*)d_in[1];
    const float* ln_b   = (const float*)d_in[2];
    const float* W_in   = (const float*)d_in[3];
    const float* conv_w = (const float*)d_in[4];
    const float* conv_b = (const float*)d_in[5];
    const float* A_log  = (const float*)d_in[6];
    const float* D_prm  = (const float*)d_in[7];
    const float* x_proj = (const float*)d_in[8];
    const float* dt_w   = (const float*)d_in[9];
    const float* dt_b   = (const float*)d_in[10];
    const float* W_out  = (const float*)d_in[11];
    float* out = (float*)d_out;

    __half *xn_hi, *xz_h, *u_hi, *xd_hi, *dl, *y_hi;
    __half *wi_hi, *xp_hi, *dw_hi, *wo_hi;
    float *xdbl, *part;
    cudaGetSymbolAddress((void**)&xn_hi, g_xn_hi);
    cudaGetSymbolAddress((void**)&xz_h,  g_xz_h);
    cudaGetSymbolAddress((void**)&u_hi,  g_u_hi);
    cudaGetSymbolAddress((void**)&xdbl,  g_xdbl);
    cudaGetSymbolAddress((void**)&xd_hi, g_xd_hi);
    cudaGetSymbolAddress((void**)&part,  g_part);
    cudaGetSymbolAddress((void**)&dl,    g_dl);
    cudaGetSymbolAddress((void**)&y_hi,  g_y_hi);
    cudaGetSymbolAddress((void**)&wi_hi, g_wi_hi);
    cudaGetSymbolAddress((void**)&xp_hi, g_xp_hi);
    cudaGetSymbolAddress((void**)&dw_hi, g_dw_hi);
    cudaGetSymbolAddress((void**)&wo_hi, g_wo_hi);

    cudaFuncSetAttribute(gemm_1p<3,1>, cudaFuncAttributeMaxDynamicSharedMemorySize, G1_SMEM);
    cudaFuncSetAttribute(gemm_1p<0,XPROJ_SPLITK>, cudaFuncAttributeMaxDynamicSharedMemorySize, G1_SMEM);
    cudaFuncSetAttribute(gemm_1p<1,1>, cudaFuncAttributeMaxDynamicSharedMemorySize, G1_SMEM);
    cudaFuncSetAttribute(gemm_1p<2,1>, cudaFuncAttributeMaxDynamicSharedMemorySize, G1_SMEM);

    // 0. all weight splits in one launch
    split_all_kernel<<<(N_SPLIT_TOT/8 + 255)/256, 256>>>(
        W_in, W_out, x_proj, dt_w, wi_hi, wo_hi, xp_hi, dw_hi);

    // 1. LayerNorm -> xn hi
    ln_kernel<<<BL, 256>>>(x, ln_g, ln_b, xn_hi);

    // 2. xz = xn @ W_in^T -> fp16  (4096 x 4096 x 1024)
    gemm_1p<3,1><<<dim3(2*D_INNER/128, BL/128), 256, G1_SMEM>>>(
        xn_hi, D_MODEL, wi_hi, D_MODEL,
        xz_h, 2*D_INNER, BL, 2*D_INNER, D_MODEL, nullptr, nullptr);

    // 3. causal depthwise conv + SiLU -> u hi (time-tiled x4)
    conv_silu_kernel<<<(BL*D_INNER/16 + 255)/256, 256>>>(xz_h, conv_w, conv_b, u_hi);

    // 4. x_dbl = u @ x_proj^T  (4096 x 96 x 2048), split-K=8
    gemm_1p<0,XPROJ_SPLITK><<<dim3(1, BL/128, XPROJ_SPLITK), 256, G1_SMEM>>>(
        u_hi, D_INNER, xp_hi, D_INNER,
        part, XDBL_C, BL, XDBL_C, D_INNER, nullptr, nullptr);
    xproj_reduce<<<(BL*XDBL_C/4 + 255)/256, 256>>>(part, xdbl, xd_hi);

    // 5. delta = softplus(dt_r @ dt_w^T + dt_b) -> fp16  (4096 x 2048 x 64)
    gemm_1p<1,1><<<dim3(D_INNER/128, BL/128), 256, G1_SMEM>>>(
        xd_hi, XDBL_C, dw_hi, DT_RANK,
        dl, D_INNER, BL, D_INNER, DT_RANK, dt_b, nullptr);

    // 6. selective scan + fused gate -> y hi
    scan_kernel<<<dim3(D_INNER/SC_DC, BSZ), SC_DC*D_STATE>>>(
        u_hi, dl, xdbl, A_log, xz_h, D_prm, y_hi);

    // 7. out = y @ W_out^T + x  (4096 x 1024 x 2048)
    gemm_1p<2,1><<<dim3(D_MODEL/128, BL/128), 256, G1_SMEM>>>(
        y_hi, D_INNER, wo_hi, D_INNER,
        out, D_MODEL, BL, D_MODEL, D_INNER, nullptr, x);
}

// round 15
// speedup vs baseline: 1.9843x; 1.0357x over previous
#include <cuda_runtime.h>
#include <cuda_fp16.h>
#include <math.h>
#include <stdint.h>

#define D_MODEL 1024
#define D_INNER 2048
#define D_STATE 16
#define DT_RANK 64
#define CONV_K  4
#define BSZ     2
#define SEQ     2048
#define BL      (BSZ*SEQ)             // 4096
#define XDBL_C  (DT_RANK + 2*D_STATE) // 96
#define XPROJ_SPLITK 8

// ---------------- scratch (static device globals) ---------------------------
__device__ __align__(16) __half g_xn_hi[BL * D_MODEL];
__device__ __align__(16) __half g_xz_h [BL * 2 * D_INNER];
__device__ __align__(16) __half g_u_hi [BL * D_INNER];
__device__ __align__(16) float  g_xdbl [BL * XDBL_C];
__device__ __align__(16) __half g_xd_hi[BL * XDBL_C];
__device__ __align__(16) float  g_part [XPROJ_SPLITK * BL * XDBL_C];
__device__ __align__(16) __half g_dl   [BL * D_INNER];
__device__ __align__(16) __half g_y_hi [BL * D_INNER];
__device__ __align__(16) __half g_wi_hi[2 * D_INNER * D_MODEL];
__device__ __align__(16) __half g_xp_hi[XDBL_C * D_INNER];
__device__ __align__(16) __half g_dw_hi[D_INNER * DT_RANK];
__device__ __align__(16) __half g_wo_hi[D_MODEL * D_INNER];

// ---------------- helpers ----------------------------------------------------
__device__ __forceinline__ void cp16(void* dst_smem, const void* src, int sz) {
    uint32_t d = (uint32_t)__cvta_generic_to_shared(dst_smem);
    asm volatile("cp.async.cg.shared.global [%0], [%1], 16, %2;\n"
                 :: "r"(d), "l"(src), "r"(sz));
}
__device__ __forceinline__ void cp_commit() {
    asm volatile("cp.async.commit_group;\n");
}
template<int N_> __device__ __forceinline__ void cp_wait() {
    asm volatile("cp.async.wait_group %0;\n" :: "n"(N_));
}
__device__ __forceinline__ uint2 h_pack4(float4 v) {
    __half2 a = __halves2half2(__float2half_rn(v.x), __float2half_rn(v.y));
    __half2 b = __halves2half2(__float2half_rn(v.z), __float2half_rn(v.w));
    uint2 r; r.x = *(uint32_t*)&a; r.y = *(uint32_t*)&b;
    return r;
}
__device__ __forceinline__ float4 h_unpack4(uint2 h) {
    __half2 a = *(__half2*)&h.x, b = *(__half2*)&h.y;
    return make_float4(__low2float(a), __high2float(a),
                       __low2float(b), __high2float(b));
}
__device__ __forceinline__ void mma16(float* c, const uint32_t* a, const uint32_t* b) {
    asm volatile(
        "mma.sync.aligned.m16n8k16.row.col.f32.f16.f16.f32 "
        "{%0,%1,%2,%3}, {%4,%5,%6,%7}, {%8,%9}, {%0,%1,%2,%3};\n"
        : "+f"(c[0]), "+f"(c[1]), "+f"(c[2]), "+f"(c[3])
        : "r"(a[0]), "r"(a[1]), "r"(a[2]), "r"(a[3]), "r"(b[0]), "r"(b[1]));
}
#define LDSM_X4(r0, r1, r2, r3, addr)                                       \
    asm volatile("ldmatrix.sync.aligned.m8n8.x4.shared.b16 "                \
                 "{%0,%1,%2,%3}, [%4];"                                     \
                 : "=r"(r0), "=r"(r1), "=r"(r2), "=r"(r3) : "r"(addr))

// K-chunk 64: rows of 64 halfs padded to 72 (conflict-free ldmatrix: 8-row
// groups hit word offsets 36k mod 32 = 4k, disjoint 4-word segments)
#define RS_H    72
#define TILE_H  (128 * RS_H)              // 9216 halfs = 18432 B

// ================= single-pass fp16 GEMM, K-chunk 64, 3-stage ===============
// EPI: 0 fp32 out | 1 softplus(acc+bias[n]) -> half | 2 fp32 + res | 3 half out
#define S1_STAGE_H (2 * TILE_H)           // 36864 B
#define G1_SMEM    (3 * S1_STAGE_H * 2)   // 110592 B

template<int EPI, int SPLITK>
__global__ __launch_bounds__(256, 2) void gemm_1p(
    const __half* __restrict__ Ahi, int lda,
    const __half* __restrict__ Bhi, int ldb,
    void* __restrict__ Cout, int ldc, int M, int N, int K,
    const float* __restrict__ bias, const float* __restrict__ res)
{
    extern __shared__ __half sm[];
    int tid = threadIdx.x;
    int m0 = blockIdx.y * 128;
    int n0 = blockIdx.x * 128;

    float* Cf = (float*)Cout;
    __half* Ch = (__half*)Cout;

    if (SPLITK > 1) {
        int z = blockIdx.z;
        int Ks = K / SPLITK;
        Ahi += (size_t)z * Ks;
        Bhi += (size_t)z * Ks;
        Cf += (size_t)z * M * ldc;
        K = Ks;
    }
    int KT = K / 64;

    int lane = tid & 31, wid = tid >> 5;
    int p = lane >> 2, q = lane & 3;
    int wm = (wid & 1) * 64;
    int wn = (wid >> 1) * 32;

    float acc[4][4][4];
    #pragma unroll
    for (int i = 0; i < 4; i++)
        #pragma unroll
        for (int j = 0; j < 4; j++)
            #pragma unroll
            for (int r = 0; r < 4; r++) acc[i][j][r] = 0.f;

    auto load_stage = [&](int kt, int slot) {
        __half* base = sm + slot * S1_STAGE_H;
        int k0 = kt * 64;
        #pragma unroll
        for (int c = tid; c < 2048; c += 256) {
            int tile = c >> 10;           // 0:A 1:B
            int idx = c & 1023;
            int r = idx >> 3;
            int j = idx & 7;
            __half* dst = base + tile * TILE_H + r * RS_H + j * 8;
            if (tile == 0) {
                cp16(dst, Ahi + (size_t)(m0 + r) * lda + k0 + j * 8, 16);
            } else {
                int n = n0 + r;
                int sz = (n < N) ? 16 : 0;
                int rr = sz ? n : 0;
                cp16(dst, Bhi + (size_t)rr * ldb + k0 + j * 8, sz);
            }
        }
    };

    // prologue: 2 stages ahead (empty commit keeps group count if KT==1)
    load_stage(0, 0); cp_commit();
    if (KT > 1) load_stage(1, 1);
    cp_commit();

    uint32_t smbase = (uint32_t)__cvta_generic_to_shared(sm);
    uint32_t a_off = ((wm + (lane & 15)) * RS_H + (lane >> 4) * 8) * 2;
    uint32_t b_off = ((wn + (lane >> 4) * 8 + (lane & 7)) * RS_H
                      + ((lane >> 3) & 1) * 8) * 2;

    for (int kt = 0; kt < KT; kt++) {
        cp_wait<1>();
        __syncthreads();
        if (kt + 2 < KT) load_stage(kt + 2, (kt + 2) % 3);
        cp_commit();

        uint32_t st = smbase + (kt % 3) * S1_STAGE_H * 2;
        uint32_t aHi = st + a_off;
        uint32_t bHi = st + TILE_H * 2 + b_off;

        #pragma unroll
        for (int s = 0; s < 4; s++) {
            uint32_t ko = s * 32;                     // k16 step = 16 halfs
            uint32_t bh[4][2];
            LDSM_X4(bh[0][0], bh[0][1], bh[1][0], bh[1][1], bHi + ko);
            LDSM_X4(bh[2][0], bh[2][1], bh[3][0], bh[3][1], bHi + 16 * RS_H * 2 + ko);
            #pragma unroll
            for (int mi = 0; mi < 4; mi++) {
                uint32_t ah[4];
                LDSM_X4(ah[0], ah[1], ah[2], ah[3], aHi + mi * 16 * RS_H * 2 + ko);
                #pragma unroll
                for (int ni = 0; ni < 4; ni++)
                    mma16(acc[mi][ni], ah, bh[ni]);
            }
        }
    }

    #pragma unroll
    for (int mi = 0; mi < 4; mi++) {
        int row = m0 + wm + mi * 16 + p;
        #pragma unroll
        for (int ni = 0; ni < 4; ni++) {
            int col = n0 + wn + ni * 8 + q * 2;
            if (col < N) {
                float v[4] = { acc[mi][ni][0], acc[mi][ni][1],
                               acc[mi][ni][2], acc[mi][ni][3] };
                if (EPI == 1) {
                    #pragma unroll
                    for (int r = 0; r < 4; r++) {
                        float t = v[r] + bias[col + (r & 1)];
                        float e = __expf(t);
                        v[r] = (t > 15.f) ? t : log1pf(e);
                    }
                }
                if (EPI == 1 || EPI == 3) {
                    __half2 v01 = __halves2half2(__float2half_rn(v[0]),
                                                 __float2half_rn(v[1]));
                    __half2 v23 = __halves2half2(__float2half_rn(v[2]),
                                                 __float2half_rn(v[3]));
                    *(__half2*)(Ch + (size_t)row * ldc + col) = v01;
                    *(__half2*)(Ch + (size_t)(row + 8) * ldc + col) = v23;
                } else {
                    if (EPI == 2) {
                        v[0] += res[(size_t)row * ldc + col];
                        v[1] += res[(size_t)row * ldc + col + 1];
                        v[2] += res[(size_t)(row + 8) * ldc + col];
                        v[3] += res[(size_t)(row + 8) * ldc + col + 1];
                    }
                    float* c0 = Cf + (size_t)row * ldc + col;
                    float* c1 = Cf + (size_t)(row + 8) * ldc + col;
                    c0[0] = v[0]; c0[1] = v[1];
                    c1[0] = v[2]; c1[1] = v[3];
                }
            }
        }
    }
}

// ---------------- fused weight splits (all 4 in one launch) -------------------
#define N_WI  (2 * D_INNER * D_MODEL)
#define N_WO  (D_MODEL * D_INNER)
#define N_XP  (XDBL_C * D_INNER)
#define N_DW  (D_INNER * DT_RANK)
#define N_SPLIT_TOT (N_WI + N_WO + N_XP + N_DW)

__global__ __launch_bounds__(256) void split_all_kernel(
    const float* __restrict__ wi, const float* __restrict__ wo,
    const float* __restrict__ xp, const float* __restrict__ dw,
    __half* __restrict__ wi_h, __half* __restrict__ wo_h,
    __half* __restrict__ xp_h, __half* __restrict__ dw_h)
{
    int i = (blockIdx.x * 256 + threadIdx.x) * 8;
    if (i >= N_SPLIT_TOT) return;
    const float* src; __half* dst; int off;
    if (i < N_WI)                    { src = wi; dst = wi_h; off = i; }
    else if (i < N_WI + N_WO)        { src = wo; dst = wo_h; off = i - N_WI; }
    else if (i < N_WI + N_WO + N_XP) { src = xp; dst = xp_h; off = i - N_WI - N_WO; }
    else                             { src = dw; dst = dw_h; off = i - N_WI - N_WO - N_XP; }
    float4 a = *(const float4*)(src + off);
    float4 b = *(const float4*)(src + off + 4);
    uint2 h0 = h_pack4(a), h1 = h_pack4(b);
    *(uint4*)(dst + off) = make_uint4(h0.x, h0.y, h1.x, h1.y);
}

// ---------------- LayerNorm (hi only) -----------------------------------------
__global__ __launch_bounds__(256) void ln_kernel(
    const float* __restrict__ x, const float* __restrict__ g,
    const float* __restrict__ b, __half* __restrict__ ohi)
{
    int row = blockIdx.x;
    const float4* xr = (const float4*)(x + (size_t)row * D_MODEL);
    float4 v = xr[threadIdx.x];
    float s  = v.x + v.y + v.z + v.w;
    float ss = v.x*v.x + v.y*v.y + v.z*v.z + v.w*v.w;
    #pragma unroll
    for (int o = 16; o; o >>= 1) {
        s  += __shfl_xor_sync(0xffffffffu, s, o);
        ss += __shfl_xor_sync(0xffffffffu, ss, o);
    }
    __shared__ float red[16];
    __shared__ float mu_s, rstd_s;
    int w = threadIdx.x >> 5, lane = threadIdx.x & 31;
    if (lane == 0) { red[w] = s; red[8 + w] = ss; }
    __syncthreads();
    if (threadIdx.x == 0) {
        float S = 0.f, SS = 0.f;
        #pragma unroll
        for (int i = 0; i < 8; i++) { S += red[i]; SS += red[8 + i]; }
        float mu = S * (1.f / D_MODEL);
        float var = SS * (1.f / D_MODEL) - mu * mu;
        mu_s = mu; rstd_s = rsqrtf(var + 1e-5f);
    }
    __syncthreads();
    float mu = mu_s, r = rstd_s;
    float4 gv = ((const float4*)g)[threadIdx.x];
    float4 bv = ((const float4*)b)[threadIdx.x];
    float4 o;
    o.x = (v.x - mu) * r * gv.x + bv.x;
    o.y = (v.y - mu) * r * gv.y + bv.y;
    o.z = (v.z - mu) * r * gv.z + bv.z;
    o.w = (v.w - mu) * r * gv.w + bv.w;
    ((uint2*)(ohi + (size_t)row * D_MODEL))[threadIdx.x] = h_pack4(o);
}

// ---------------- split-K reduce for x_proj (fp32 + hi) -----------------------
__global__ __launch_bounds__(256) void xproj_reduce(
    const float* __restrict__ part, float* __restrict__ out,
    __half* __restrict__ ohi)
{
    int i = (blockIdx.x * 256 + threadIdx.x) * 4;
    if (i >= BL * XDBL_C) return;
    const int stride = BL * XDBL_C;
    float4 s = *(const float4*)(part + i);
    #pragma unroll
    for (int z = 1; z < XPROJ_SPLITK; z++) {
        float4 p = *(const float4*)(part + z * stride + i);
        s.x += p.x; s.y += p.y; s.z += p.z; s.w += p.w;
    }
    *(float4*)(out + i) = s;
    *(uint2*)(ohi + i) = h_pack4(s);
}

// ---------------- causal depthwise conv (K=4) + SiLU, time-tiled x4 ----------
__global__ __launch_bounds__(256) void conv_silu_kernel(
    const __half* __restrict__ xz, const float* __restrict__ w,
    const float* __restrict__ bias, __half* __restrict__ uhi)
{
    const int ND4 = D_INNER / 4;
    const int NT4 = SEQ / 4;
    int idx = blockIdx.x * 256 + threadIdx.x;
    if (idx >= BSZ * NT4 * ND4) return;
    int d4 = (idx % ND4) * 4;
    int t0 = ((idx / ND4) % NT4) * 4;
    int b  = idx / (ND4 * NT4);

    float4 bi = *(const float4*)(bias + d4);
    float4 wr[4];
    #pragma unroll
    for (int c = 0; c < 4; c++) wr[c] = *(const float4*)(w + (d4 + c) * CONV_K);

    float4 xv[7];
    #pragma unroll
    for (int j = 0; j < 7; j++) {
        int ts = t0 - 3 + j;
        if (ts >= 0) {
            uint2 xh = *(const uint2*)(xz + (size_t)(b * SEQ + ts) * (2 * D_INNER) + d4);
            xv[j] = h_unpack4(xh);
        } else {
            xv[j] = make_float4(0.f, 0.f, 0.f, 0.f);
        }
    }

    #pragma unroll
    for (int o = 0; o < 4; o++) {
        float4 acc = bi;
        #pragma unroll
        for (int k = 0; k < CONV_K; k++) {
            float4 xk = xv[o + k];
            acc.x += ((const float*)&wr[0])[k] * xk.x;
            acc.y += ((const float*)&wr[1])[k] * xk.y;
            acc.z += ((const float*)&wr[2])[k] * xk.z;
            acc.w += ((const float*)&wr[3])[k] * xk.w;
        }
        float4 val;
        val.x = acc.x / (1.f + __expf(-acc.x));
        val.y = acc.y / (1.f + __expf(-acc.y));
        val.z = acc.z / (1.f + __expf(-acc.z));
        val.w = acc.w / (1.f + __expf(-acc.w));
        size_t oi = (size_t)(b * SEQ + t0 + o) * D_INNER + d4;
        *(uint2*)(uhi + oi) = h_pack4(val);
    }
}

// ---------------- selective scan (gate fused; du pre-staged) ------------------
#define SC_DC 16
#define SC_TC 64
__global__ __launch_bounds__(SC_DC * D_STATE) void scan_kernel(
    const __half* __restrict__ uhi, const __half* __restrict__ dl,
    const float* __restrict__ xdbl, const float* __restrict__ A_log,
    const __half* __restrict__ xz, const float* __restrict__ Dp,
    __half* __restrict__ yhi)
{
    __shared__ float u_s [SC_TC][SC_DC];
    __shared__ float du_s[SC_TC][SC_DC];   // dl * u
    __shared__ float dl_s[SC_TC][SC_DC];
    __shared__ float B_s [SC_TC][D_STATE];
    __shared__ float C_s [SC_TC][D_STATE];
    __shared__ float y_s [SC_TC][SC_DC];

    int b  = blockIdx.y;
    int d0 = blockIdx.x * SC_DC;
    int tid = threadIdx.x;
    int g = tid >> 4;
    int n = tid & 15;
    int d = d0 + g;

    float a = -expf(A_log[d * D_STATE + n]);
    float s = 0.f;

    for (int t0 = 0; t0 < SEQ; t0 += SC_TC) {
        {
            int i = tid * 4;
            int tt = i >> 4, gg = i & 15;
            size_t gi = (size_t)(b * SEQ + t0 + tt) * D_INNER + d0 + gg;
            float4 uu = h_unpack4(*(const uint2*)(uhi + gi));
            float4 dd = h_unpack4(*(const uint2*)(dl + gi));
            *(float4*)&u_s [tt][gg] = uu;
            *(float4*)&dl_s[tt][gg] = dd;
            float4 du = make_float4(dd.x*uu.x, dd.y*uu.y, dd.z*uu.z, dd.w*uu.w);
            *(float4*)&du_s[tt][gg] = du;
        }
        for (int i = tid * 4; i < SC_TC * 32; i += 1024) {
            int tt = i >> 5, pos = i & 31;
            const float* r = xdbl + (size_t)(b * SEQ + t0 + tt) * XDBL_C + DT_RANK;
            float4 v = *(const float4*)(r + pos);
            if (pos < 16) *(float4*)&B_s[tt][pos] = v;
            else          *(float4*)&C_s[tt][pos - 16] = v;
        }
        __syncthreads();
        #pragma unroll 4
        for (int t = 0; t < SC_TC; t++) {
            float dA  = __expf(dl_s[t][g] * a);
            float dbu = du_s[t][g] * B_s[t][n];
            s = fmaf(dA, s, dbu);
            float part = s * C_s[t][n];
            part += __shfl_xor_sync(0xffffffffu, part, 8);
            part += __shfl_xor_sync(0xffffffffu, part, 4);
            part += __shfl_xor_sync(0xffffffffu, part, 2);
            part += __shfl_xor_sync(0xffffffffu, part, 1);
            if (n == 0) y_s[t][g] = part;
        }
        __syncthreads();
        {
            int i = tid * 4;
            int tt = i >> 4, gg = i & 15;
            int rowg = b * SEQ + t0 + tt;
            uint2 zh = *(const uint2*)(xz + (size_t)rowg * (2 * D_INNER) + D_INNER + d0 + gg);
            float4 z = h_unpack4(zh);
            float4 uu = *(const float4*)&u_s[tt][gg];
            float4 yy = *(const float4*)&y_s[tt][gg];
            float4 dp = *(const float4*)(Dp + d0 + gg);
            float4 val;
            val.x = (yy.x + uu.x * dp.x) * (z.x / (1.f + __expf(-z.x)));
            val.y = (yy.y + uu.y * dp.y) * (z.y / (1.f + __expf(-z.y)));
            val.z = (yy.z + uu.z * dp.z) * (z.z / (1.f + __expf(-z.z)));
            val.w = (yy.w + uu.w * dp.w) * (z.w / (1.f + __expf(-z.w)));
            size_t oi = (size_t)rowg * D_INNER + d0 + gg;
            *(uint2*)(yhi + oi) = h_pack4(val);
        }
        __syncthreads();
    }
}

// ---------------- launch ------------------------------------------------------
extern "C" void kernel_launch(void* const* d_in, const int* in_sizes, int n_in,
                              void* d_out, int out_size)
{
    const float* x      = (const float*)d_in[0];
    const float* ln_g   = (const float*)d_in[1];
    const float* ln_b   = (const float*)d_in[2];
    const float* W_in   = (const float*)d_in[3];
    const float* conv_w = (const float*)d_in[4];
    const float* conv_b = (const float*)d_in[5];
    const float* A_log  = (const float*)d_in[6];
    const float* D_prm  = (const float*)d_in[7];
    const float* x_proj = (const float*)d_in[8];
    const float* dt_w   = (const float*)d_in[9];
    const float* dt_b   = (const float*)d_in[10];
    const float* W_out  = (const float*)d_in[11];
    float* out = (float*)d_out;

    __half *xn_hi, *xz_h, *u_hi, *xd_hi, *dl, *y_hi;
    __half *wi_hi, *xp_hi, *dw_hi, *wo_hi;
    float *xdbl, *part;
    cudaGetSymbolAddress((void**)&xn_hi, g_xn_hi);
    cudaGetSymbolAddress((void**)&xz_h,  g_xz_h);
    cudaGetSymbolAddress((void**)&u_hi,  g_u_hi);
    cudaGetSymbolAddress((void**)&xdbl,  g_xdbl);
    cudaGetSymbolAddress((void**)&xd_hi, g_xd_hi);
    cudaGetSymbolAddress((void**)&part,  g_part);
    cudaGetSymbolAddress((void**)&dl,    g_dl);
    cudaGetSymbolAddress((void**)&y_hi,  g_y_hi);
    cudaGetSymbolAddress((void**)&wi_hi, g_wi_hi);
    cudaGetSymbolAddress((void**)&xp_hi, g_xp_hi);
    cudaGetSymbolAddress((void**)&dw_hi, g_dw_hi);
    cudaGetSymbolAddress((void**)&wo_hi, g_wo_hi);

    cudaFuncSetAttribute(gemm_1p<3,1>, cudaFuncAttributeMaxDynamicSharedMemorySize, G1_SMEM);
    cudaFuncSetAttribute(gemm_1p<0,XPROJ_SPLITK>, cudaFuncAttributeMaxDynamicSharedMemorySize, G1_SMEM);
    cudaFuncSetAttribute(gemm_1p<1,1>, cudaFuncAttributeMaxDynamicSharedMemorySize, G1_SMEM);
    cudaFuncSetAttribute(gemm_1p<2,1>, cudaFuncAttributeMaxDynamicSharedMemorySize, G1_SMEM);

    // 0. all weight splits in one launch
    split_all_kernel<<<(N_SPLIT_TOT/8 + 255)/256, 256>>>(
        W_in, W_out, x_proj, dt_w, wi_hi, wo_hi, xp_hi, dw_hi);

    // 1. LayerNorm -> xn hi
    ln_kernel<<<BL, 256>>>(x, ln_g, ln_b, xn_hi);

    // 2. xz = xn @ W_in^T -> fp16  (4096 x 4096 x 1024)
    gemm_1p<3,1><<<dim3(2*D_INNER/128, BL/128), 256, G1_SMEM>>>(
        xn_hi, D_MODEL, wi_hi, D_MODEL,
        xz_h, 2*D_INNER, BL, 2*D_INNER, D_MODEL, nullptr, nullptr);

    // 3. causal depthwise conv + SiLU -> u hi (time-tiled x4)
    conv_silu_kernel<<<(BL*D_INNER/16 + 255)/256, 256>>>(xz_h, conv_w, conv_b, u_hi);

    // 4. x_dbl = u @ x_proj^T  (4096 x 96 x 2048), split-K=8
    gemm_1p<0,XPROJ_SPLITK><<<dim3(1, BL/128, XPROJ_SPLITK), 256, G1_SMEM>>>(
        u_hi, D_INNER, xp_hi, D_INNER,
        part, XDBL_C, BL, XDBL_C, D_INNER, nullptr, nullptr);
    xproj_reduce<<<(BL*XDBL_C/4 + 255)/256, 256>>>(part, xdbl, xd_hi);

    // 5. delta = softplus(dt_r @ dt_w^T + dt_b) -> fp16  (4096 x 2048 x 64)
    gemm_1p<1,1><<<dim3(D_INNER/128, BL/128), 256, G1_SMEM>>>(
        xd_hi, XDBL_C, dw_hi, DT_RANK,
        dl, D_INNER, BL, D_INNER, DT_RANK, dt_b, nullptr);

    // 6. selective scan + fused gate -> y hi
    scan_kernel<<<dim3(D_INNER/SC_DC, BSZ), SC_DC*D_STATE>>>(
        u_hi, dl, xdbl, A_log, xz_h, D_prm, y_hi);

    // 7. out = y @ W_out^T + x  (4096 x 1024 x 2048)
    gemm_1p<2,1><<<dim3(D_MODEL/128, BL/128), 256, G1_SMEM>>>(
        y_hi, D_INNER, wo_hi, D_INNER,
        out, D_MODEL, BL, D_MODEL, D_INNER, nullptr, x);
}

// round 16
// speedup vs baseline: 2.0156x; 1.0158x over previous
#include <cuda_runtime.h>
#include <cuda_fp16.h>
#include <math.h>
#include <stdint.h>

#define D_MODEL 1024
#define D_INNER 2048
#define D_STATE 16
#define DT_RANK 64
#define CONV_K  4
#define BSZ     2
#define SEQ     2048
#define BL      (BSZ*SEQ)             // 4096
#define XDBL_C  (DT_RANK + 2*D_STATE) // 96
#define XPROJ_SPLITK 8

// ---------------- scratch (static device globals) ---------------------------
__device__ __align__(16) __half g_xn_hi[BL * D_MODEL];
__device__ __align__(16) __half g_xz_h [BL * 2 * D_INNER];
__device__ __align__(16) __half g_u_hi [BL * D_INNER];
__device__ __align__(16) float  g_xdbl [BL * XDBL_C];
__device__ __align__(16) __half g_xd_hi[BL * XDBL_C];
__device__ __align__(16) float  g_part [XPROJ_SPLITK * BL * XDBL_C];
__device__ __align__(16) __half g_dl   [BL * D_INNER];
__device__ __align__(16) __half g_y_hi [BL * D_INNER];
__device__ __align__(16) __half g_wi_hi[2 * D_INNER * D_MODEL];
__device__ __align__(16) __half g_xp_hi[XDBL_C * D_INNER];
__device__ __align__(16) __half g_dw_hi[D_INNER * DT_RANK];
__device__ __align__(16) __half g_wo_hi[D_MODEL * D_INNER];

// ---------------- helpers ----------------------------------------------------
__device__ __forceinline__ void cp16(void* dst_smem, const void* src, int sz) {
    uint32_t d = (uint32_t)__cvta_generic_to_shared(dst_smem);
    asm volatile("cp.async.cg.shared.global [%0], [%1], 16, %2;\n"
                 :: "r"(d), "l"(src), "r"(sz));
}
__device__ __forceinline__ void cp_commit() {
    asm volatile("cp.async.commit_group;\n");
}
template<int N_> __device__ __forceinline__ void cp_wait() {
    asm volatile("cp.async.wait_group %0;\n" :: "n"(N_));
}
__device__ __forceinline__ uint2 h_pack4(float4 v) {
    __half2 a = __halves2half2(__float2half_rn(v.x), __float2half_rn(v.y));
    __half2 b = __halves2half2(__float2half_rn(v.z), __float2half_rn(v.w));
    uint2 r; r.x = *(uint32_t*)&a; r.y = *(uint32_t*)&b;
    return r;
}
__device__ __forceinline__ float4 h_unpack4(uint2 h) {
    __half2 a = *(__half2*)&h.x, b = *(__half2*)&h.y;
    return make_float4(__low2float(a), __high2float(a),
                       __low2float(b), __high2float(b));
}
__device__ __forceinline__ void mma16(float* c, const uint32_t* a, const uint32_t* b) {
    asm volatile(
        "mma.sync.aligned.m16n8k16.row.col.f32.f16.f16.f32 "
        "{%0,%1,%2,%3}, {%4,%5,%6,%7}, {%8,%9}, {%0,%1,%2,%3};\n"
        : "+f"(c[0]), "+f"(c[1]), "+f"(c[2]), "+f"(c[3])
        : "r"(a[0]), "r"(a[1]), "r"(a[2]), "r"(a[3]), "r"(b[0]), "r"(b[1]));
}
#define LDSM_X4(r0, r1, r2, r3, addr)                                       \
    asm volatile("ldmatrix.sync.aligned.m8n8.x4.shared.b16 "                \
                 "{%0,%1,%2,%3}, [%4];"                                     \
                 : "=r"(r0), "=r"(r1), "=r"(r2), "=r"(r3) : "r"(addr))

// K-chunk 64: rows of 64 halfs padded to 72 (conflict-free ldmatrix)
#define RS_H    72
#define TILE_H  (128 * RS_H)              // 9216 halfs = 18432 B

// ================= single-pass fp16 GEMM, K-chunk 64, 3-stage ===============
// EPI: 0 fp32 out | 1 softplus(acc+bias[n]) -> half | 2 fp32 + res | 3 half out
#define S1_STAGE_H (2 * TILE_H)           // 36864 B
#define G1_SMEM    (3 * S1_STAGE_H * 2)   // 110592 B

template<int EPI, int SPLITK>
__global__ __launch_bounds__(256, 2) void gemm_1p(
    const __half* __restrict__ Ahi, int lda,
    const __half* __restrict__ Bhi, int ldb,
    void* __restrict__ Cout, int ldc, int M, int N, int K,
    const float* __restrict__ bias, const float* __restrict__ res)
{
    extern __shared__ __half sm[];
    int tid = threadIdx.x;
    int m0 = blockIdx.y * 128;
    int n0 = blockIdx.x * 128;

    float* Cf = (float*)Cout;
    __half* Ch = (__half*)Cout;

    if (SPLITK > 1) {
        int z = blockIdx.z;
        int Ks = K / SPLITK;
        Ahi += (size_t)z * Ks;
        Bhi += (size_t)z * Ks;
        Cf += (size_t)z * M * ldc;
        K = Ks;
    }
    int KT = K / 64;

    int lane = tid & 31, wid = tid >> 5;
    int p = lane >> 2, q = lane & 3;
    int wm = (wid & 1) * 64;
    int wn = (wid >> 1) * 32;

    float acc[4][4][4];
    #pragma unroll
    for (int i = 0; i < 4; i++)
        #pragma unroll
        for (int j = 0; j < 4; j++)
            #pragma unroll
            for (int r = 0; r < 4; r++) acc[i][j][r] = 0.f;

    auto load_stage = [&](int kt, int slot) {
        __half* base = sm + slot * S1_STAGE_H;
        int k0 = kt * 64;
        #pragma unroll
        for (int c = tid; c < 2048; c += 256) {
            int tile = c >> 10;           // 0:A 1:B
            int idx = c & 1023;
            int r = idx >> 3;
            int j = idx & 7;
            __half* dst = base + tile * TILE_H + r * RS_H + j * 8;
            if (tile == 0) {
                cp16(dst, Ahi + (size_t)(m0 + r) * lda + k0 + j * 8, 16);
            } else {
                int n = n0 + r;
                int sz = (n < N) ? 16 : 0;
                int rr = sz ? n : 0;
                cp16(dst, Bhi + (size_t)rr * ldb + k0 + j * 8, sz);
            }
        }
    };

    load_stage(0, 0); cp_commit();
    if (KT > 1) load_stage(1, 1);
    cp_commit();

    uint32_t smbase = (uint32_t)__cvta_generic_to_shared(sm);
    uint32_t a_off = ((wm + (lane & 15)) * RS_H + (lane >> 4) * 8) * 2;
    uint32_t b_off = ((wn + (lane >> 4) * 8 + (lane & 7)) * RS_H
                      + ((lane >> 3) & 1) * 8) * 2;

    for (int kt = 0; kt < KT; kt++) {
        cp_wait<1>();
        __syncthreads();
        if (kt + 2 < KT) load_stage(kt + 2, (kt + 2) % 3);
        cp_commit();

        uint32_t st = smbase + (kt % 3) * S1_STAGE_H * 2;
        uint32_t aHi = st + a_off;
        uint32_t bHi = st + TILE_H * 2 + b_off;

        #pragma unroll
        for (int s = 0; s < 4; s++) {
            uint32_t ko = s * 32;
            uint32_t bh[4][2];
            LDSM_X4(bh[0][0], bh[0][1], bh[1][0], bh[1][1], bHi + ko);
            LDSM_X4(bh[2][0], bh[2][1], bh[3][0], bh[3][1], bHi + 16 * RS_H * 2 + ko);
            #pragma unroll
            for (int mi = 0; mi < 4; mi++) {
                uint32_t ah[4];
                LDSM_X4(ah[0], ah[1], ah[2], ah[3], aHi + mi * 16 * RS_H * 2 + ko);
                #pragma unroll
                for (int ni = 0; ni < 4; ni++)
                    mma16(acc[mi][ni], ah, bh[ni]);
            }
        }
    }

    #pragma unroll
    for (int mi = 0; mi < 4; mi++) {
        int row = m0 + wm + mi * 16 + p;
        #pragma unroll
        for (int ni = 0; ni < 4; ni++) {
            int col = n0 + wn + ni * 8 + q * 2;
            if (col < N) {
                float v[4] = { acc[mi][ni][0], acc[mi][ni][1],
                               acc[mi][ni][2], acc[mi][ni][3] };
                if (EPI == 1) {
                    #pragma unroll
                    for (int r = 0; r < 4; r++) {
                        float t = v[r] + bias[col + (r & 1)];
                        float e = __expf(t);
                        v[r] = (t > 15.f) ? t : log1pf(e);
                    }
                }
                if (EPI == 1 || EPI == 3) {
                    __half2 v01 = __halves2half2(__float2half_rn(v[0]),
                                                 __float2half_rn(v[1]));
                    __half2 v23 = __halves2half2(__float2half_rn(v[2]),
                                                 __float2half_rn(v[3]));
                    *(__half2*)(Ch + (size_t)row * ldc + col) = v01;
                    *(__half2*)(Ch + (size_t)(row + 8) * ldc + col) = v23;
                } else {
                    if (EPI == 2) {
                        v[0] += res[(size_t)row * ldc + col];
                        v[1] += res[(size_t)row * ldc + col + 1];
                        v[2] += res[(size_t)(row + 8) * ldc + col];
                        v[3] += res[(size_t)(row + 8) * ldc + col + 1];
                    }
                    float* c0 = Cf + (size_t)row * ldc + col;
                    float* c1 = Cf + (size_t)(row + 8) * ldc + col;
                    c0[0] = v[0]; c0[1] = v[1];
                    c1[0] = v[2]; c1[1] = v[3];
                }
            }
        }
    }
}

// ---------------- fused weight splits (all 4 in one launch) -------------------
#define N_WI  (2 * D_INNER * D_MODEL)
#define N_WO  (D_MODEL * D_INNER)
#define N_XP  (XDBL_C * D_INNER)
#define N_DW  (D_INNER * DT_RANK)
#define N_SPLIT_TOT (N_WI + N_WO + N_XP + N_DW)

__global__ __launch_bounds__(256) void split_all_kernel(
    const float* __restrict__ wi, const float* __restrict__ wo,
    const float* __restrict__ xp, const float* __restrict__ dw,
    __half* __restrict__ wi_h, __half* __restrict__ wo_h,
    __half* __restrict__ xp_h, __half* __restrict__ dw_h)
{
    int i = (blockIdx.x * 256 + threadIdx.x) * 8;
    if (i >= N_SPLIT_TOT) return;
    const float* src; __half* dst; int off;
    if (i < N_WI)                    { src = wi; dst = wi_h; off = i; }
    else if (i < N_WI + N_WO)        { src = wo; dst = wo_h; off = i - N_WI; }
    else if (i < N_WI + N_WO + N_XP) { src = xp; dst = xp_h; off = i - N_WI - N_WO; }
    else                             { src = dw; dst = dw_h; off = i - N_WI - N_WO - N_XP; }
    float4 a = *(const float4*)(src + off);
    float4 b = *(const float4*)(src + off + 4);
    uint2 h0 = h_pack4(a), h1 = h_pack4(b);
    *(uint4*)(dst + off) = make_uint4(h0.x, h0.y, h1.x, h1.y);
}

// ---------------- LayerNorm (hi only) -----------------------------------------
__global__ __launch_bounds__(256) void ln_kernel(
    const float* __restrict__ x, const float* __restrict__ g,
    const float* __restrict__ b, __half* __restrict__ ohi)
{
    int row = blockIdx.x;
    const float4* xr = (const float4*)(x + (size_t)row * D_MODEL);
    float4 v = xr[threadIdx.x];
    float s  = v.x + v.y + v.z + v.w;
    float ss = v.x*v.x + v.y*v.y + v.z*v.z + v.w*v.w;
    #pragma unroll
    for (int o = 16; o; o >>= 1) {
        s  += __shfl_xor_sync(0xffffffffu, s, o);
        ss += __shfl_xor_sync(0xffffffffu, ss, o);
    }
    __shared__ float red[16];
    __shared__ float mu_s, rstd_s;
    int w = threadIdx.x >> 5, lane = threadIdx.x & 31;
    if (lane == 0) { red[w] = s; red[8 + w] = ss; }
    __syncthreads();
    if (threadIdx.x == 0) {
        float S = 0.f, SS = 0.f;
        #pragma unroll
        for (int i = 0; i < 8; i++) { S += red[i]; SS += red[8 + i]; }
        float mu = S * (1.f / D_MODEL);
        float var = SS * (1.f / D_MODEL) - mu * mu;
        mu_s = mu; rstd_s = rsqrtf(var + 1e-5f);
    }
    __syncthreads();
    float mu = mu_s, r = rstd_s;
    float4 gv = ((const float4*)g)[threadIdx.x];
    float4 bv = ((const float4*)b)[threadIdx.x];
    float4 o;
    o.x = (v.x - mu) * r * gv.x + bv.x;
    o.y = (v.y - mu) * r * gv.y + bv.y;
    o.z = (v.z - mu) * r * gv.z + bv.z;
    o.w = (v.w - mu) * r * gv.w + bv.w;
    ((uint2*)(ohi + (size_t)row * D_MODEL))[threadIdx.x] = h_pack4(o);
}

// ---------------- split-K reduce for x_proj (fp32 + hi) -----------------------
__global__ __launch_bounds__(256) void xproj_reduce(
    const float* __restrict__ part, float* __restrict__ out,
    __half* __restrict__ ohi)
{
    int i = (blockIdx.x * 256 + threadIdx.x) * 4;
    if (i >= BL * XDBL_C) return;
    const int stride = BL * XDBL_C;
    float4 s = *(const float4*)(part + i);
    #pragma unroll
    for (int z = 1; z < XPROJ_SPLITK; z++) {
        float4 p = *(const float4*)(part + z * stride + i);
        s.x += p.x; s.y += p.y; s.z += p.z; s.w += p.w;
    }
    *(float4*)(out + i) = s;
    *(uint2*)(ohi + i) = h_pack4(s);
}

// ---------------- causal depthwise conv (K=4) + SiLU, time-tiled x4 ----------
__global__ __launch_bounds__(256) void conv_silu_kernel(
    const __half* __restrict__ xz, const float* __restrict__ w,
    const float* __restrict__ bias, __half* __restrict__ uhi)
{
    const int ND4 = D_INNER / 4;
    const int NT4 = SEQ / 4;
    int idx = blockIdx.x * 256 + threadIdx.x;
    if (idx >= BSZ * NT4 * ND4) return;
    int d4 = (idx % ND4) * 4;
    int t0 = ((idx / ND4) % NT4) * 4;
    int b  = idx / (ND4 * NT4);

    float4 bi = *(const float4*)(bias + d4);
    float4 wr[4];
    #pragma unroll
    for (int c = 0; c < 4; c++) wr[c] = *(const float4*)(w + (d4 + c) * CONV_K);

    float4 xv[7];
    #pragma unroll
    for (int j = 0; j < 7; j++) {
        int ts = t0 - 3 + j;
        if (ts >= 0) {
            uint2 xh = *(const uint2*)(xz + (size_t)(b * SEQ + ts) * (2 * D_INNER) + d4);
            xv[j] = h_unpack4(xh);
        } else {
            xv[j] = make_float4(0.f, 0.f, 0.f, 0.f);
        }
    }

    #pragma unroll
    for (int o = 0; o < 4; o++) {
        float4 acc = bi;
        #pragma unroll
        for (int k = 0; k < CONV_K; k++) {
            float4 xk = xv[o + k];
            acc.x += ((const float*)&wr[0])[k] * xk.x;
            acc.y += ((const float*)&wr[1])[k] * xk.y;
            acc.z += ((const float*)&wr[2])[k] * xk.z;
            acc.w += ((const float*)&wr[3])[k] * xk.w;
        }
        float4 val;
        val.x = acc.x / (1.f + __expf(-acc.x));
        val.y = acc.y / (1.f + __expf(-acc.y));
        val.z = acc.z / (1.f + __expf(-acc.z));
        val.w = acc.w / (1.f + __expf(-acc.w));
        size_t oi = (size_t)(b * SEQ + t0 + o) * D_INNER + d4;
        *(uint2*)(uhi + oi) = h_pack4(val);
    }
}

// ---------------- selective scan: 8 lanes/channel, 2 states/lane --------------
// Warp covers 4 channels. Lane owns states n and n+8; 3-level shfl reduce.
#define SC_DC 16
#define SC_TC 64
__global__ __launch_bounds__(128) void scan_kernel(
    const __half* __restrict__ uhi, const __half* __restrict__ dl,
    const float* __restrict__ xdbl, const float* __restrict__ A_log,
    const __half* __restrict__ xz, const float* __restrict__ Dp,
    __half* __restrict__ yhi)
{
    __shared__ float u_s [SC_TC][SC_DC];
    __shared__ float du_s[SC_TC][SC_DC];
    __shared__ float dl_s[SC_TC][SC_DC];
    __shared__ float B_s [SC_TC][D_STATE];
    __shared__ float C_s [SC_TC][D_STATE];
    __shared__ float y_s [SC_TC][SC_DC];

    int b  = blockIdx.y;
    int d0 = blockIdx.x * SC_DC;
    int tid = threadIdx.x;               // 128 threads
    int g = tid >> 3;                    // channel 0..15
    int n = tid & 7;                     // state base 0..7 (owns n and n+8)
    int d = d0 + g;

    float a0 = -expf(A_log[d * D_STATE + n]);
    float a1 = -expf(A_log[d * D_STATE + n + 8]);
    float s0 = 0.f, s1 = 0.f;

    for (int t0 = 0; t0 < SEQ; t0 += SC_TC) {
        // stage u, dl, du: 64x16 halfs; 128 thr x 8 elems (uint4 loads)
        {
            int i = tid * 8;
            int tt = i >> 4, gg = i & 15;          // gg = 0 or 8
            size_t gi = (size_t)(b * SEQ + t0 + tt) * D_INNER + d0 + gg;
            uint4 uh = *(const uint4*)(uhi + gi);
            uint4 dh = *(const uint4*)(dl + gi);
            float4 u0 = h_unpack4(make_uint2(uh.x, uh.y));
            float4 u1 = h_unpack4(make_uint2(uh.z, uh.w));
            float4 d0f = h_unpack4(make_uint2(dh.x, dh.y));
            float4 d1f = h_unpack4(make_uint2(dh.z, dh.w));
            *(float4*)&u_s [tt][gg]     = u0;
            *(float4*)&u_s [tt][gg + 4] = u1;
            *(float4*)&dl_s[tt][gg]     = d0f;
            *(float4*)&dl_s[tt][gg + 4] = d1f;
            *(float4*)&du_s[tt][gg]     = make_float4(d0f.x*u0.x, d0f.y*u0.y, d0f.z*u0.z, d0f.w*u0.w);
            *(float4*)&du_s[tt][gg + 4] = make_float4(d1f.x*u1.x, d1f.y*u1.y, d1f.z*u1.z, d1f.w*u1.w);
        }
        // stage B,C: 64 rows x 32 floats = 2048 floats; 128 thr x 4 float4s
        for (int i = tid * 4; i < SC_TC * 32; i += 512) {
            int tt = i >> 5, pos = i & 31;
            const float* r = xdbl + (size_t)(b * SEQ + t0 + tt) * XDBL_C + DT_RANK;
            float4 v = *(const float4*)(r + pos);
            if (pos < 16) *(float4*)&B_s[tt][pos] = v;
            else          *(float4*)&C_s[tt][pos - 16] = v;
        }
        __syncthreads();
        #pragma unroll 4
        for (int t = 0; t < SC_TC; t++) {
            float dlt = dl_s[t][g];
            float du  = du_s[t][g];
            float dA0 = __expf(dlt * a0);
            float dA1 = __expf(dlt * a1);
            s0 = fmaf(dA0, s0, du * B_s[t][n]);
            s1 = fmaf(dA1, s1, du * B_s[t][n + 8]);
            float part = fmaf(s1, C_s[t][n + 8], s0 * C_s[t][n]);
            part += __shfl_xor_sync(0xffffffffu, part, 4);
            part += __shfl_xor_sync(0xffffffffu, part, 2);
            part += __shfl_xor_sync(0xffffffffu, part, 1);
            if (n == 0) y_s[t][g] = part;
        }
        __syncthreads();
        // fused gate: 128 thr x 8 elems
        {
            int i = tid * 8;
            int tt = i >> 4, gg = i & 15;
            int rowg = b * SEQ + t0 + tt;
            uint4 zh = *(const uint4*)(xz + (size_t)rowg * (2 * D_INNER) + D_INNER + d0 + gg);
            float4 z0 = h_unpack4(make_uint2(zh.x, zh.y));
            float4 z1 = h_unpack4(make_uint2(zh.z, zh.w));
            float4 u0 = *(const float4*)&u_s[tt][gg];
            float4 u1 = *(const float4*)&u_s[tt][gg + 4];
            float4 y0 = *(const float4*)&y_s[tt][gg];
            float4 y1 = *(const float4*)&y_s[tt][gg + 4];
            float4 p0 = *(const float4*)(Dp + d0 + gg);
            float4 p1 = *(const float4*)(Dp + d0 + gg + 4);
            float4 v0, v1;
            v0.x = (y0.x + u0.x * p0.x) * (z0.x / (1.f + __expf(-z0.x)));
            v0.y = (y0.y + u0.y * p0.y) * (z0.y / (1.f + __expf(-z0.y)));
            v0.z = (y0.z + u0.z * p0.z) * (z0.z / (1.f + __expf(-z0.z)));
            v0.w = (y0.w + u0.w * p0.w) * (z0.w / (1.f + __expf(-z0.w)));
            v1.x = (y1.x + u1.x * p1.x) * (z1.x / (1.f + __expf(-z1.x)));
            v1.y = (y1.y + u1.y * p1.y) * (z1.y / (1.f + __expf(-z1.y)));
            v1.z = (y1.z + u1.z * p1.z) * (z1.z / (1.f + __expf(-z1.z)));
            v1.w = (y1.w + u1.w * p1.w) * (z1.w / (1.f + __expf(-z1.w)));
            uint2 h0 = h_pack4(v0), h1 = h_pack4(v1);
            size_t oi = (size_t)rowg * D_INNER + d0 + gg;
            *(uint4*)(yhi + oi) = make_uint4(h0.x, h0.y, h1.x, h1.y);
        }
        __syncthreads();
    }
}

// ---------------- launch ------------------------------------------------------
extern "C" void kernel_launch(void* const* d_in, const int* in_sizes, int n_in,
                              void* d_out, int out_size)
{
    const float* x      = (const float*)d_in[0];
    const float* ln_g   = (const float*)d_in[1];
    const float* ln_b   = (const float*)d_in[2];
    const float* W_in   = (const float*)d_in[3];
    const float* conv_w = (const float*)d_in[4];
    const float* conv_b = (const float*)d_in[5];
    const float* A_log  = (const float*)d_in[6];
    const float* D_prm  = (const float*)d_in[7];
    const float* x_proj = (const float*)d_in[8];
    const float* dt_w   = (const float*)d_in[9];
    const float* dt_b   = (const float*)d_in[10];
    const float* W_out  = (const float*)d_in[11];
    float* out = (float*)d_out;

    __half *xn_hi, *xz_h, *u_hi, *xd_hi, *dl, *y_hi;
    __half *wi_hi, *xp_hi, *dw_hi, *wo_hi;
    float *xdbl, *part;
    cudaGetSymbolAddress((void**)&xn_hi, g_xn_hi);
    cudaGetSymbolAddress((void**)&xz_h,  g_xz_h);
    cudaGetSymbolAddress((void**)&u_hi,  g_u_hi);
    cudaGetSymbolAddress((void**)&xdbl,  g_xdbl);
    cudaGetSymbolAddress((void**)&xd_hi, g_xd_hi);
    cudaGetSymbolAddress((void**)&part,  g_part);
    cudaGetSymbolAddress((void**)&dl,    g_dl);
    cudaGetSymbolAddress((void**)&y_hi,  g_y_hi);
    cudaGetSymbolAddress((void**)&wi_hi, g_wi_hi);
    cudaGetSymbolAddress((void**)&xp_hi, g_xp_hi);
    cudaGetSymbolAddress((void**)&dw_hi, g_dw_hi);
    cudaGetSymbolAddress((void**)&wo_hi, g_wo_hi);

    cudaFuncSetAttribute(gemm_1p<3,1>, cudaFuncAttributeMaxDynamicSharedMemorySize, G1_SMEM);
    cudaFuncSetAttribute(gemm_1p<0,XPROJ_SPLITK>, cudaFuncAttributeMaxDynamicSharedMemorySize, G1_SMEM);
    cudaFuncSetAttribute(gemm_1p<1,1>, cudaFuncAttributeMaxDynamicSharedMemorySize, G1_SMEM);
    cudaFuncSetAttribute(gemm_1p<2,1>, cudaFuncAttributeMaxDynamicSharedMemorySize, G1_SMEM);

    // 0. all weight splits in one launch
    split_all_kernel<<<(N_SPLIT_TOT/8 + 255)/256, 256>>>(
        W_in, W_out, x_proj, dt_w, wi_hi, wo_hi, xp_hi, dw_hi);

    // 1. LayerNorm -> xn hi
    ln_kernel<<<BL, 256>>>(x, ln_g, ln_b, xn_hi);

    // 2. xz = xn @ W_in^T -> fp16  (4096 x 4096 x 1024)
    gemm_1p<3,1><<<dim3(2*D_INNER/128, BL/128), 256, G1_SMEM>>>(
        xn_hi, D_MODEL, wi_hi, D_MODEL,
        xz_h, 2*D_INNER, BL, 2*D_INNER, D_MODEL, nullptr, nullptr);

    // 3. causal depthwise conv + SiLU -> u hi (time-tiled x4)
    conv_silu_kernel<<<(BL*D_INNER/16 + 255)/256, 256>>>(xz_h, conv_w, conv_b, u_hi);

    // 4. x_dbl = u @ x_proj^T  (4096 x 96 x 2048), split-K=8
    gemm_1p<0,XPROJ_SPLITK><<<dim3(1, BL/128, XPROJ_SPLITK), 256, G1_SMEM>>>(
        u_hi, D_INNER, xp_hi, D_INNER,
        part, XDBL_C, BL, XDBL_C, D_INNER, nullptr, nullptr);
    xproj_reduce<<<(BL*XDBL_C/4 + 255)/256, 256>>>(part, xdbl, xd_hi);

    // 5. delta = softplus(dt_r @ dt_w^T + dt_b) -> fp16  (4096 x 2048 x 64)
    gemm_1p<1,1><<<dim3(D_INNER/128, BL/128), 256, G1_SMEM>>>(
        xd_hi, XDBL_C, dw_hi, DT_RANK,
        dl, D_INNER, BL, D_INNER, DT_RANK, dt_b, nullptr);

    // 6. selective scan + fused gate -> y hi
    scan_kernel<<<dim3(D_INNER/SC_DC, BSZ), 128>>>(
        u_hi, dl, xdbl, A_log, xz_h, D_prm, y_hi);

    // 7. out = y @ W_out^T + x  (4096 x 1024 x 2048)
    gemm_1p<2,1><<<dim3(D_MODEL/128, BL/128), 256, G1_SMEM>>>(
        y_hi, D_INNER, wo_hi, D_INNER,
        out, D_MODEL, BL, D_MODEL, D_INNER, nullptr, x);
}